// round 9
// baseline (speedup 1.0000x reference)
#include <cuda_runtime.h>
#include <stdint.h>
#include <math.h>

typedef unsigned long long ull;

// ---------------------------------------------------------------------------
// Problem constants
// ---------------------------------------------------------------------------
namespace {
constexpr int TT = 128, BB = 32;
constexpr int POS_E = 64, WORD_E = 512, POS_H = 256, WORD_H = 1024;
constexpr int POS_V = 45, WORD_V = 32000;
constexpr int NTOK = TT * BB;      // 4096
constexpr int NTOKP = NTOK + 32;   // history col 0 = zeros (t = -1 slot)

// ---------------------------------------------------------------------------
// Device scratch (static globals; no allocation allowed)
// ---------------------------------------------------------------------------
__device__ float g_p_embT[POS_E * NTOK];             // [E][tok]
__device__ float g_w_embT[WORD_E * NTOK];
__device__ float g_poutsT[POS_H * NTOKP];            // histories [H][NTOKP], slot t+1
__device__ float g_wh0T[WORD_H * NTOKP];
__device__ float g_woutsT[WORD_H * NTOKP];
__device__ float g_wmidT[WORD_E * NTOK];
__device__ float g_preT_p[4 * POS_H * NTOK];         // emb@Wih pos, [4H][tok]
__device__ float g_preT_w0[4 * WORD_H * NTOK];
// packed sequential weights, k-major per block: [blk][K][ROWS]
__device__ float g_Wpos[4 * POS_H * 1280];           // [128][1280][8]
__device__ float g_Ww0[4 * WORD_H * 1280];           // [128][1280][32]
__device__ float g_Ww1[4 * WORD_H * 2048];           // [128][2048][32]
__device__ float g_bpos[4 * POS_H], g_bw0[4 * WORD_H], g_bw1[4 * WORD_H];
// cell state ping-pong (each [H][32]; block-private rows)
__device__ float g_Cpos[2][POS_H * BB];
__device__ float g_Cw0[2][WORD_H * BB];
__device__ float g_Cw1[2][WORD_H * BB];
__device__ unsigned g_flags[128 * 8];                // per-block barrier flags (32B spaced)
}  // namespace

// ---------------------------------------------------------------------------
// f32x2 packed helpers
// ---------------------------------------------------------------------------
__device__ __forceinline__ ull pack2(float lo, float hi) {
    ull r; asm("mov.b64 %0, {%1,%2};" : "=l"(r) : "f"(lo), "f"(hi)); return r;
}
__device__ __forceinline__ ull dup2(float v) { return pack2(v, v); }
__device__ __forceinline__ void fma2(ull& d, ull a, ull b) {
    asm("fma.rn.f32x2 %0, %1, %2, %0;" : "+l"(d) : "l"(a), "l"(b));
}
__device__ __forceinline__ void unpack2(ull v, float& lo, float& hi) {
    asm("mov.b64 {%0,%1}, %2;" : "=f"(lo), "=f"(hi) : "l"(v));
}
__device__ __forceinline__ float sigm(float x) { return 1.f / (1.f + expf(-x)); }

__device__ __forceinline__ void cp_async16(unsigned smem_addr, const void* gptr) {
    asm volatile("cp.async.cg.shared.global [%0], [%1], 16;"
                 :: "r"(smem_addr), "l"(gptr));
}
__device__ __forceinline__ void cp_async_commit() {
    asm volatile("cp.async.commit_group;");
}
__device__ __forceinline__ void cp_async_wait0() {
    asm volatile("cp.async.wait_group 0;");
}
__device__ __forceinline__ unsigned smem_u32(const void* p) {
    return (unsigned)__cvta_generic_to_shared(p);
}

// ---------------------------------------------------------------------------
// Init / gather / weight repack
// ---------------------------------------------------------------------------
__global__ void zero_init_kernel() {
    int i = blockIdx.x * blockDim.x + threadIdx.x;
    if (i < POS_H * BB) {
        g_poutsT[(size_t)(i >> 5) * NTOKP + (i & 31)] = 0.f;
        g_Cpos[0][i] = 0.f;
    }
    if (i < WORD_H * BB) {
        int r = i >> 5, b = i & 31;
        g_wh0T[(size_t)r * NTOKP + b] = 0.f;
        g_woutsT[(size_t)r * NTOKP + b] = 0.f;
        g_Cw0[0][i] = 0.f;
        g_Cw1[0][i] = 0.f;
    }
    if (i < 128 * 8) g_flags[i] = 0u;
}

__global__ void gather_kernel(const int* __restrict__ pos, const int* __restrict__ word,
                              const float* __restrict__ posW, const float* __restrict__ wordW) {
    int j = blockIdx.x * blockDim.x + threadIdx.x;
    if (j < WORD_E * NTOK) {
        int d = j / NTOK, tok = j - d * NTOK;
        g_w_embT[j] = wordW[(size_t)word[tok] * WORD_E + d];
    }
    if (j < POS_E * NTOK) {
        int d = j / NTOK, tok = j - d * NTOK;
        g_p_embT[j] = posW[(size_t)pos[tok] * POS_E + d];
    }
}

// Repack into k-major per-block layout (source row strides: 1088 / 768 / 1024).
__global__ void repack_kernel(const float* __restrict__ pWih, const float* __restrict__ pWhh,
                              const float* __restrict__ w0Wih, const float* __restrict__ w0Whh,
                              const float* __restrict__ w1Wih, const float* __restrict__ w1Whh,
                              const float* __restrict__ pbih, const float* __restrict__ pbhh,
                              const float* __restrict__ w0bih, const float* __restrict__ w0bhh,
                              const float* __restrict__ w1bih, const float* __restrict__ w1bhh) {
    int i = blockIdx.x * blockDim.x + threadIdx.x;
    const int A = 4 * POS_H * 1280;
    const int Bq = 4 * WORD_H * 1280;
    const int Cq = 4 * WORD_H * 2048;
    if (i < A) {
        int blk = i / (1280 * 8), rem = i - blk * (1280 * 8);
        int k = rem >> 3, rowl = rem & 7;
        int g = rowl >> 1, hh = rowl & 1;
        int R = g * POS_H + blk * 2 + hh;
        g_Wpos[i] = (k < 1024) ? pWih[(size_t)R * 1088 + 64 + k]
                               : pWhh[(size_t)R * 256 + (k - 1024)];
        return;
    }
    i -= A;
    if (i < Bq) {
        int blk = i / (1280 * 32), rem = i - blk * (1280 * 32);
        int k = rem >> 5, rowl = rem & 31;
        int g = rowl >> 3, hh = rowl & 7;
        int R = g * WORD_H + blk * 8 + hh;
        g_Ww0[i] = (k < 256) ? w0Wih[(size_t)R * 768 + 512 + k]
                             : w0Whh[(size_t)R * 1024 + (k - 256)];
        return;
    }
    i -= Bq;
    if (i < Cq) {
        int blk = i / (2048 * 32), rem = i - blk * (2048 * 32);
        int k = rem >> 5, rowl = rem & 31;
        int g = rowl >> 3, hh = rowl & 7;
        int R = g * WORD_H + blk * 8 + hh;
        g_Ww1[i] = (k < 1024) ? w1Wih[(size_t)R * 1024 + k]
                              : w1Whh[(size_t)R * 1024 + (k - 1024)];
        return;
    }
    i -= Cq;
    if (i < 4 * POS_H) { g_bpos[i] = pbih[i] + pbhh[i]; return; }
    i -= 4 * POS_H;
    if (i < 4 * WORD_H) { g_bw0[i] = w0bih[i] + w0bhh[i]; return; }
    i -= 4 * WORD_H;
    if (i < 4 * WORD_H) { g_bw1[i] = w1bih[i] + w1bhh[i]; }
}

// ---------------------------------------------------------------------------
// Persistent recurrence kernel: 128 blocks x 512 threads, 192KB dynamic smem.
// ---------------------------------------------------------------------------
constexpr int REC_THREADS = 512;
constexpr int REC_SMEM = (2 * 256 * 32 + 2 * 256 * 32 + 16 * 32 * 32) * 4;  // 196608

// Flag-based grid barrier: each block releases its own flag (no atomic
// serialization); 128 threads poll the 128 flags with acquire loads.
__device__ __forceinline__ void grid_barrier(unsigned ep) {
    __syncthreads();
    if (threadIdx.x == 0) {
        asm volatile("st.global.release.gpu.u32 [%0], %1;"
                     :: "l"(&g_flags[blockIdx.x * 8]), "r"(ep) : "memory");
    }
    if (threadIdx.x < 128) {
        unsigned v;
        do {
            asm volatile("ld.global.acquire.gpu.u32 %0, [%1];"
                         : "=r"(v) : "l"(&g_flags[threadIdx.x * 8]) : "memory");
        } while (v < ep);
    }
    __syncthreads();
}

// Word-size LSTM cell (H=1024). 256-k chunks; 16 warps = 16 k-slices (16 k each).
template <int K>
__device__ __forceinline__ void cell_word(
    float (*xs)[256][32], float (*ws)[256][32], float (*red)[32][32],
    const float* __restrict__ Wblk, const float* __restrict__ bcomb,
    const float* __restrict__ preT, int tok0,
    const float* __restrict__ x1, int K1, const float* __restrict__ x2,
    const float* __restrict__ cin, float* __restrict__ cout,
    float* __restrict__ hcol) {
    constexpr int NC = K / 256;
    const int tid = threadIdx.x;
    const int w = tid >> 5, lane = tid & 31;
    const int rowg = lane >> 2;   // rows rowg*4..+3
    const int bg = lane & 3;      // batch bg*8..+7

    // gate-operand prefetch
    const int hh = tid >> 5, gb = tid & 31;
    const int habs_g = blockIdx.x * 8 + hh;
    float cin_v = 0.f, bb[4], pre_g[4];
    if (tid < 256) {
        cin_v = cin[habs_g * 32 + gb];
#pragma unroll
        for (int g = 0; g < 4; g++) {
            bb[g] = bcomb[g * WORD_H + habs_g];
            pre_g[g] = preT ? preT[(size_t)(g * WORD_H + habs_g) * NTOK + tok0 + gb] : 0.f;
        }
    }

    ull acc[4][4];
#pragma unroll
    for (int r = 0; r < 4; r++)
#pragma unroll
        for (int j = 0; j < 4; j++) acc[r][j] = 0ull;

    float4 px[4], pw[4];
#pragma unroll
    for (int it = 0; it < 4; it++) {   // chunk 0 (always inside x1)
        int f = tid + it * REC_THREADS;
        px[it] = *(const float4*)(x1 + (size_t)(f >> 3) * NTOKP + (f & 7) * 4);
        pw[it] = *(const float4*)(Wblk + (size_t)(f >> 3) * 32 + (f & 7) * 4);
    }
#pragma unroll
    for (int it = 0; it < 4; it++) {
        int f = tid + it * REC_THREADS;
        *(float4*)&xs[0][f >> 3][(f & 7) * 4] = px[it];
        *(float4*)&ws[0][f >> 3][(f & 7) * 4] = pw[it];
    }
    __syncthreads();

    for (int c = 0; c < NC; c++) {
        const int cur = c & 1, nxt = cur ^ 1;
        if (c + 1 < NC) {
            int kb = (c + 1) * 256;
            const float* xsrc = (kb < K1) ? x1 + (size_t)kb * NTOKP
                                          : x2 + (size_t)(kb - K1) * NTOKP;
            const float* wsrc = Wblk + (size_t)kb * 32;
#pragma unroll
            for (int it = 0; it < 4; it++) {
                int f = tid + it * REC_THREADS;
                px[it] = *(const float4*)(xsrc + (size_t)(f >> 3) * NTOKP + (f & 7) * 4);
                pw[it] = *(const float4*)(wsrc + (size_t)(f >> 3) * 32 + (f & 7) * 4);
            }
        }
#pragma unroll
        for (int kk = 0; kk < 16; kk++) {
            int k = w * 16 + kk;
            const ulonglong2* xp = (const ulonglong2*)&xs[cur][k][bg * 8];
            ulonglong2 xv0 = xp[0], xv1 = xp[1];
            float4 wv = *(const float4*)&ws[cur][k][rowg * 4];
            ull wd0 = dup2(wv.x), wd1 = dup2(wv.y), wd2 = dup2(wv.z), wd3 = dup2(wv.w);
            fma2(acc[0][0], wd0, xv0.x); fma2(acc[0][1], wd0, xv0.y);
            fma2(acc[0][2], wd0, xv1.x); fma2(acc[0][3], wd0, xv1.y);
            fma2(acc[1][0], wd1, xv0.x); fma2(acc[1][1], wd1, xv0.y);
            fma2(acc[1][2], wd1, xv1.x); fma2(acc[1][3], wd1, xv1.y);
            fma2(acc[2][0], wd2, xv0.x); fma2(acc[2][1], wd2, xv0.y);
            fma2(acc[2][2], wd2, xv1.x); fma2(acc[2][3], wd2, xv1.y);
            fma2(acc[3][0], wd3, xv0.x); fma2(acc[3][1], wd3, xv0.y);
            fma2(acc[3][2], wd3, xv1.x); fma2(acc[3][3], wd3, xv1.y);
        }
        if (c + 1 < NC) {
#pragma unroll
            for (int it = 0; it < 4; it++) {
                int f = tid + it * REC_THREADS;
                *(float4*)&xs[nxt][f >> 3][(f & 7) * 4] = px[it];
                *(float4*)&ws[nxt][f >> 3][(f & 7) * 4] = pw[it];
            }
        }
        __syncthreads();
    }
#pragma unroll
    for (int r = 0; r < 4; r++) {
        int row = rowg * 4 + r;
#pragma unroll
        for (int j = 0; j < 4; j += 2) {
            float a0, a1, a2, a3;
            unpack2(acc[r][j], a0, a1);
            unpack2(acc[r][j + 1], a2, a3);
            *(float4*)&red[w][row][bg * 8 + j * 2] = make_float4(a0, a1, a2, a3);
        }
    }
    __syncthreads();
    if (tid < 256) {
        float gs[4];
#pragma unroll
        for (int g = 0; g < 4; g++) {
            float s = bb[g] + pre_g[g];
#pragma unroll
            for (int ww = 0; ww < 16; ww++) s += red[ww][g * 8 + hh][gb];
            gs[g] = s;
        }
        float i = sigm(gs[0]), f = sigm(gs[1]), g = tanhf(gs[2]), o = sigm(gs[3]);
        float c2 = f * cin_v + i * g;
        float h2 = o * tanhf(c2);
        cout[habs_g * 32 + gb] = c2;
        hcol[(size_t)habs_g * NTOKP + gb] = h2;
    }
}

// Pos cell (H=256, ROWS=8, K=1280, K1=1024). 256-k chunks; 8 k-slices of 64.
__device__ __forceinline__ void cell_pos(
    float (*xs)[256][32], float (*ws)[256][32], float (*red)[32][32],
    const float* __restrict__ Wblk, const float* __restrict__ bcomb,
    const float* __restrict__ preT, int tok0,
    const float* __restrict__ x1 /*1024 rows*/, const float* __restrict__ x2 /*256*/,
    const float* __restrict__ cin, float* __restrict__ cout,
    float* __restrict__ hcol) {
    constexpr int K = 1280, NC = K / 256, K1 = 1024;
    const int tid = threadIdx.x;
    const int ksl = tid >> 6;     // 0..7
    const int sub = tid & 63;
    const int rowl = sub >> 3;    // 0..7
    const int bg = sub & 7;       // batch bg*4..+3

    const int hh = tid >> 5, gb = tid & 31;
    const int habs_g = blockIdx.x * 2 + hh;
    float cin_v = 0.f, bb[4], pre_g[4];
    if (tid < 64) {
        cin_v = cin[habs_g * 32 + gb];
#pragma unroll
        for (int g = 0; g < 4; g++) {
            bb[g] = bcomb[g * POS_H + habs_g];
            pre_g[g] = preT[(size_t)(g * POS_H + habs_g) * NTOK + tok0 + gb];
        }
    }

    ull acc0 = 0ull, acc1 = 0ull;
    float4 px[4], pw;
#pragma unroll
    for (int it = 0; it < 4; it++) {
        int f = tid + it * REC_THREADS;
        px[it] = *(const float4*)(x1 + (size_t)(f >> 3) * NTOKP + (f & 7) * 4);
    }
    pw = *(const float4*)(Wblk + (size_t)(tid >> 1) * 8 + (tid & 1) * 4);
#pragma unroll
    for (int it = 0; it < 4; it++) {
        int f = tid + it * REC_THREADS;
        *(float4*)&xs[0][f >> 3][(f & 7) * 4] = px[it];
    }
    *(float4*)&ws[0][tid >> 1][(tid & 1) * 4] = pw;
    __syncthreads();

    for (int c = 0; c < NC; c++) {
        const int cur = c & 1, nxt = cur ^ 1;
        if (c + 1 < NC) {
            int kb = (c + 1) * 256;
            const float* xsrc = (kb < K1) ? x1 + (size_t)kb * NTOKP
                                          : x2 + (size_t)(kb - K1) * NTOKP;
#pragma unroll
            for (int it = 0; it < 4; it++) {
                int f = tid + it * REC_THREADS;
                px[it] = *(const float4*)(xsrc + (size_t)(f >> 3) * NTOKP + (f & 7) * 4);
            }
            pw = *(const float4*)(Wblk + (size_t)(kb + (tid >> 1)) * 8 + (tid & 1) * 4);
        }
#pragma unroll
        for (int kk = 0; kk < 32; kk++) {
            int k = ksl * 32 + kk;
            ulonglong2 xv = *(const ulonglong2*)&xs[cur][k][bg * 4];
            ull wd = dup2(ws[cur][k][rowl]);
            fma2(acc0, wd, xv.x);
            fma2(acc1, wd, xv.y);
        }
        if (c + 1 < NC) {
#pragma unroll
            for (int it = 0; it < 4; it++) {
                int f = tid + it * REC_THREADS;
                *(float4*)&xs[nxt][f >> 3][(f & 7) * 4] = px[it];
            }
            *(float4*)&ws[nxt][tid >> 1][(tid & 1) * 4] = pw;
        }
        __syncthreads();
    }
    {
        float a0, a1, a2, a3;
        unpack2(acc0, a0, a1);
        unpack2(acc1, a2, a3);
        *(float4*)&red[ksl][rowl][bg * 4] = make_float4(a0, a1, a2, a3);
    }
    __syncthreads();
    if (tid < 64) {
        float gs[4];
#pragma unroll
        for (int g = 0; g < 4; g++) {
            float s = bb[g] + pre_g[g];
#pragma unroll
            for (int s8 = 0; s8 < 8; s8++) s += red[s8][g * 2 + hh][gb];
            gs[g] = s;
        }
        float i = sigm(gs[0]), f = sigm(gs[1]), g = tanhf(gs[2]), o = sigm(gs[3]);
        float c2 = f * cin_v + i * g;
        float h2 = o * tanhf(c2);
        cout[habs_g * 32 + gb] = c2;
        hcol[(size_t)habs_g * NTOKP + gb] = h2;
    }
}

__global__ __launch_bounds__(REC_THREADS, 1) void recurrence_kernel() {
    extern __shared__ float smem[];
    float (*xs)[256][32] = (float(*)[256][32])smem;
    float (*ws)[256][32] = (float(*)[256][32])(smem + 2 * 256 * 32);
    float (*red)[32][32] = (float(*)[32][32])(smem + 4 * 256 * 32);
    unsigned ep = 0;
    const int blk = blockIdx.x;
    const float* WposB = g_Wpos + (size_t)blk * 1280 * 8;
    const float* Ww0B  = g_Ww0 + (size_t)blk * 1280 * 32;
    const float* Ww1B  = g_Ww1 + (size_t)blk * 2048 * 32;
    for (int t = 0; t < TT; t++) {
        const int p = t & 1, q = p ^ 1;
        const int tok0 = t * BB;
        cell_pos(xs, ws, red, WposB, g_bpos, g_preT_p, tok0,
                 g_woutsT + (size_t)t * 32, g_poutsT + (size_t)t * 32,
                 g_Cpos[p], g_Cpos[q], g_poutsT + (size_t)(t + 1) * 32);
        grid_barrier(++ep);
        cell_word<1280>(xs, ws, red, Ww0B, g_bw0, g_preT_w0, tok0,
                        g_poutsT + (size_t)(t + 1) * 32, 256,
                        g_wh0T + (size_t)t * 32,
                        g_Cw0[p], g_Cw0[q], g_wh0T + (size_t)(t + 1) * 32);
        grid_barrier(++ep);
        cell_word<2048>(xs, ws, red, Ww1B, g_bw1, nullptr, tok0,
                        g_wh0T + (size_t)(t + 1) * 32, 1024,
                        g_woutsT + (size_t)t * 32,
                        g_Cw1[p], g_Cw1[q], g_woutsT + (size_t)(t + 1) * 32);
        grid_barrier(++ep);
    }
}

// ---------------------------------------------------------------------------
// Pipelined f32x2 GEMM: C[m,n] = sum_k AT[k,m]*W[n,k] + bias[n].
// Double-buffered smem; cp.async for A tiles, register prefetch for W tiles.
// Dynamic smem: As[2][32][128] | Ws[2][32][132]
// ---------------------------------------------------------------------------
constexpr int GEMM_SMEM = (2 * 32 * 128 + 2 * 32 * 132) * 4;  // 66560

__global__ __launch_bounds__(256, 2) void gemm_t_kernel(
    const float* __restrict__ AT, int M, int lda,
    const float* __restrict__ W, int ldw, const float* __restrict__ bias,
    float* __restrict__ C, float* __restrict__ CT, int N, int K) {
    extern __shared__ float gsm[];
    float (*As)[32][128] = (float(*)[32][128])gsm;
    float (*Ws)[32][132] = (float(*)[32][132])(gsm + 2 * 32 * 128);
    const int tid = threadIdx.x;
    const int rt = tid & 15;
    const int ct = tid >> 4;
    const int rBase = blockIdx.y * 128, cBase = blockIdx.x * 128;
    const int NC = K / 32;

    ull acc[8][4];
#pragma unroll
    for (int jj = 0; jj < 8; jj++)
#pragma unroll
        for (int p = 0; p < 4; p++) acc[jj][p] = 0ull;

    // --- prologue: stage tile 0 ---
    float4 pww[4];
    {
#pragma unroll
        for (int it = 0; it < 4; it++) {   // A tile via cp.async
            int flat = tid + it * 256;
            int k = flat >> 5, m4 = flat & 31;
            cp_async16(smem_u32(&As[0][k][m4 * 4]),
                       &AT[(size_t)k * lda + rBase + m4 * 4]);
        }
        cp_async_commit();
#pragma unroll
        for (int it = 0; it < 4; it++) {   // W tile via registers
            int flat = tid + it * 256;
            int n = flat >> 3, k4 = flat & 7;
            pww[it] = *(const float4*)&W[(size_t)(cBase + n) * ldw + k4 * 4];
        }
#pragma unroll
        for (int it = 0; it < 4; it++) {
            int flat = tid + it * 256;
            int n = flat >> 3, k4 = flat & 7;
            Ws[0][k4 * 4 + 0][n] = pww[it].x;
            Ws[0][k4 * 4 + 1][n] = pww[it].y;
            Ws[0][k4 * 4 + 2][n] = pww[it].z;
            Ws[0][k4 * 4 + 3][n] = pww[it].w;
        }
        cp_async_wait0();
        __syncthreads();
    }

    for (int c = 0; c < NC; c++) {
        const int cur = c & 1, nxt = cur ^ 1;
        if (c + 1 < NC) {
            int kb = (c + 1) * 32;
#pragma unroll
            for (int it = 0; it < 4; it++) {
                int flat = tid + it * 256;
                int k = flat >> 5, m4 = flat & 31;
                cp_async16(smem_u32(&As[nxt][k][m4 * 4]),
                           &AT[(size_t)(kb + k) * lda + rBase + m4 * 4]);
            }
            cp_async_commit();
#pragma unroll
            for (int it = 0; it < 4; it++) {
                int flat = tid + it * 256;
                int n = flat >> 3, k4 = flat & 7;
                pww[it] = *(const float4*)&W[(size_t)(cBase + n) * ldw + kb + k4 * 4];
            }
        }
#pragma unroll
        for (int k = 0; k < 32; k++) {
            ull xd[8];
#pragma unroll
            for (int jj = 0; jj < 8; jj++) xd[jj] = dup2(As[cur][k][rt + 16 * jj]);
            const ulonglong2* wpp = (const ulonglong2*)&Ws[cur][k][ct * 8];
            ulonglong2 wa = wpp[0];
            ulonglong2 wb = wpp[1];
#pragma unroll
            for (int jj = 0; jj < 8; jj++) {
                fma2(acc[jj][0], xd[jj], wa.x);
                fma2(acc[jj][1], xd[jj], wa.y);
                fma2(acc[jj][2], xd[jj], wb.x);
                fma2(acc[jj][3], xd[jj], wb.y);
            }
        }
        if (c + 1 < NC) {
#pragma unroll
            for (int it = 0; it < 4; it++) {
                int flat = tid + it * 256;
                int n = flat >> 3, k4 = flat & 7;
                Ws[nxt][k4 * 4 + 0][n] = pww[it].x;
                Ws[nxt][k4 * 4 + 1][n] = pww[it].y;
                Ws[nxt][k4 * 4 + 2][n] = pww[it].z;
                Ws[nxt][k4 * 4 + 3][n] = pww[it].w;
            }
        }
        cp_async_wait0();
        __syncthreads();
    }

    float bcol[8];
#pragma unroll
    for (int qq = 0; qq < 8; qq++) bcol[qq] = bias ? bias[cBase + ct * 8 + qq] : 0.f;
#pragma unroll
    for (int jj = 0; jj < 8; jj++) {
        int m = rBase + rt + 16 * jj;
        float v[8];
#pragma unroll
        for (int p = 0; p < 4; p++) unpack2(acc[jj][p], v[2 * p], v[2 * p + 1]);
#pragma unroll
        for (int qq = 0; qq < 8; qq++) v[qq] += bcol[qq];
        if (C) {
            float4* dst = (float4*)&C[(size_t)m * N + cBase + ct * 8];
            dst[0] = make_float4(v[0], v[1], v[2], v[3]);
            dst[1] = make_float4(v[4], v[5], v[6], v[7]);
        }
        if (CT) {
#pragma unroll
            for (int qq = 0; qq < 8; qq++)
                CT[(size_t)(cBase + ct * 8 + qq) * M + m] = v[qq];
        }
    }
}

// ---------------------------------------------------------------------------
// pos projection + log-softmax (one block per timestep)
// ---------------------------------------------------------------------------
__global__ void pos_projT_kernel(const float* __restrict__ Wp, const float* __restrict__ bp,
                                 float* __restrict__ out) {
    __shared__ float xs[POS_H][32];
    __shared__ float lg[POS_V][33];
    __shared__ float lsb[32];
    const int t = blockIdx.x;
    const int tok0 = t * 32;
    const int tid = threadIdx.x;
    const int b = tid & 31, vg = tid >> 5;
    for (int i = tid; i < POS_H * 32; i += 256) {
        int k = i >> 5, bb = i & 31;
        xs[k][bb] = g_poutsT[(size_t)k * NTOKP + 32 + tok0 + bb];
    }
    __syncthreads();
    for (int v = vg; v < POS_V; v += 8) {
        float s = bp[v];
        const float* wv = Wp + (size_t)v * POS_H;
        for (int k = 0; k < POS_H; k++) s = fmaf(xs[k][b], wv[k], s);
        lg[v][b] = s;
    }
    __syncthreads();
    if (tid < 32) {
        float m = -INFINITY;
        for (int v = 0; v < POS_V; v++) m = fmaxf(m, lg[v][tid]);
        float e = 0.f;
        for (int v = 0; v < POS_V; v++) e += expf(lg[v][tid] - m);
        lsb[tid] = m + logf(e);
    }
    __syncthreads();
    float ls = lsb[b];
    for (int v = vg; v < POS_V; v += 8)
        out[(size_t)(tok0 + b) * POS_V + v] = lg[v][b] - ls;
}

// ---------------------------------------------------------------------------
// word log-softmax in place over 32000 (one block per row, float4)
// ---------------------------------------------------------------------------
__global__ void word_softmax_kernel(float* __restrict__ logits) {
    __shared__ float red[8];
    const int row = blockIdx.x;
    float4* p4 = (float4*)(logits + (size_t)row * WORD_V);
    const int NV4 = WORD_V / 4;  // 8000
    const int tid = threadIdx.x;  // 256
    float m = -INFINITY;
    for (int i = tid; i < NV4; i += 256) {
        float4 v = p4[i];
        m = fmaxf(m, fmaxf(fmaxf(v.x, v.y), fmaxf(v.z, v.w)));
    }
#pragma unroll
    for (int o = 16; o; o >>= 1) m = fmaxf(m, __shfl_xor_sync(0xffffffffu, m, o));
    if ((tid & 31) == 0) red[tid >> 5] = m;
    __syncthreads();
    float M = red[0];
#pragma unroll
    for (int w = 1; w < 8; w++) M = fmaxf(M, red[w]);
    __syncthreads();
    float s = 0.f;
    for (int i = tid; i < NV4; i += 256) {
        float4 v = p4[i];
        s += expf(v.x - M) + expf(v.y - M) + expf(v.z - M) + expf(v.w - M);
    }
#pragma unroll
    for (int o = 16; o; o >>= 1) s += __shfl_xor_sync(0xffffffffu, s, o);
    if ((tid & 31) == 0) red[tid >> 5] = s;
    __syncthreads();
    float S = 0.f;
#pragma unroll
    for (int w = 0; w < 8; w++) S += red[w];
    float ls = M + logf(S);
    for (int i = tid; i < NV4; i += 256) {
        float4 v = p4[i];
        v.x -= ls; v.y -= ls; v.z -= ls; v.w -= ls;
        p4[i] = v;
    }
}

// ---------------------------------------------------------------------------
// Host side
// ---------------------------------------------------------------------------
extern "C" void kernel_launch(void* const* d_in, const int* in_sizes, int n_in,
                              void* d_out, int out_size) {
    (void)in_sizes; (void)n_in; (void)out_size;
    const int*   pos        = (const int*)d_in[0];
    const int*   word       = (const int*)d_in[1];
    const float* pos_emb_W  = (const float*)d_in[2];
    const float* word_emb_W = (const float*)d_in[3];
    const float* pos_Wih    = (const float*)d_in[4];
    const float* pos_Whh    = (const float*)d_in[5];
    const float* pos_bih    = (const float*)d_in[6];
    const float* pos_bhh    = (const float*)d_in[7];
    const float* w0_Wih     = (const float*)d_in[8];
    const float* w0_Whh     = (const float*)d_in[9];
    const float* w0_bih     = (const float*)d_in[10];
    const float* w0_bhh     = (const float*)d_in[11];
    const float* w1_Wih     = (const float*)d_in[12];
    const float* w1_Whh     = (const float*)d_in[13];
    const float* w1_bih     = (const float*)d_in[14];
    const float* w1_bhh     = (const float*)d_in[15];
    const float* pos_proj_W = (const float*)d_in[16];
    const float* pos_proj_b = (const float*)d_in[17];
    const float* wp1_W      = (const float*)d_in[18];
    const float* wp1_b      = (const float*)d_in[19];
    const float* wp2_b      = (const float*)d_in[20];
    float* out = (float*)d_out;

    float *p_embT, *w_embT, *woutsT, *wmidT, *preT_p, *preT_w0;
    cudaGetSymbolAddress((void**)&p_embT, g_p_embT);
    cudaGetSymbolAddress((void**)&w_embT, g_w_embT);
    cudaGetSymbolAddress((void**)&woutsT, g_woutsT);
    cudaGetSymbolAddress((void**)&wmidT, g_wmidT);
    cudaGetSymbolAddress((void**)&preT_p, g_preT_p);
    cudaGetSymbolAddress((void**)&preT_w0, g_preT_w0);

    static bool attr_done = false;
    if (!attr_done) {
        cudaFuncSetAttribute(recurrence_kernel,
                             cudaFuncAttributeMaxDynamicSharedMemorySize, REC_SMEM);
        cudaFuncSetAttribute(gemm_t_kernel,
                             cudaFuncAttributeMaxDynamicSharedMemorySize, GEMM_SMEM);
        attr_done = true;
    }

    zero_init_kernel<<<(WORD_H * BB + 255) / 256, 256>>>();
    gather_kernel<<<(WORD_E * NTOK + 255) / 256, 256>>>(pos, word, pos_emb_W, word_emb_W);

    {
        const int total = 4 * POS_H * 1280 + 4 * WORD_H * 1280 + 4 * WORD_H * 2048 +
                          4 * POS_H + 2 * (4 * WORD_H);
        repack_kernel<<<(total + 255) / 256, 256>>>(
            pos_Wih, pos_Whh, w0_Wih, w0_Whh, w1_Wih, w1_Whh,
            pos_bih, pos_bhh, w0_bih, w0_bhh, w1_bih, w1_bhh);
    }

    // precompute emb @ Wih_emb-part for all timesteps (transposed outputs)
    gemm_t_kernel<<<dim3(4 * POS_H / 128, NTOK / 128), 256, GEMM_SMEM>>>(
        p_embT, NTOK, NTOK, pos_Wih, POS_E + WORD_H, nullptr,
        nullptr, preT_p, 4 * POS_H, POS_E);
    gemm_t_kernel<<<dim3(4 * WORD_H / 128, NTOK / 128), 256, GEMM_SMEM>>>(
        w_embT, NTOK, NTOK, w0_Wih, WORD_E + POS_H, nullptr,
        nullptr, preT_w0, 4 * WORD_H, WORD_E);

    // the whole 128-step recurrence in ONE persistent kernel
    recurrence_kernel<<<128, REC_THREADS, REC_SMEM>>>();

    // pos projection + log-softmax
    pos_projT_kernel<<<TT, 256>>>(pos_proj_W, pos_proj_b, out);

    // word head
    gemm_t_kernel<<<dim3(WORD_E / 128, NTOK / 128), 256, GEMM_SMEM>>>(
        woutsT + 32, NTOK, NTOKP, wp1_W, WORD_H, wp1_b,
        nullptr, wmidT, WORD_E, WORD_H);
    float* wlp = out + (size_t)NTOK * POS_V;
    gemm_t_kernel<<<dim3(WORD_V / 128, NTOK / 128), 256, GEMM_SMEM>>>(
        wmidT, NTOK, NTOK, word_emb_W, WORD_E, wp2_b,
        wlp, nullptr, WORD_V, WORD_E);
    word_softmax_kernel<<<NTOK, 256>>>(wlp);
}

// round 10
// speedup vs baseline: 1.6222x; 1.6222x over previous
#include <cuda_runtime.h>
#include <stdint.h>
#include <math.h>

typedef unsigned long long ull;

// ---------------------------------------------------------------------------
// Problem constants
// ---------------------------------------------------------------------------
namespace {
constexpr int TT = 128, BB = 32;
constexpr int POS_E = 64, WORD_E = 512, POS_H = 256, WORD_H = 1024;
constexpr int POS_V = 45, WORD_V = 32000;
constexpr int NTOK = TT * BB;      // 4096
constexpr int NTOKP = NTOK + 32;   // history col 0 = zeros (t = -1 slot)

// ---------------------------------------------------------------------------
// Device scratch (static globals; no allocation allowed)
// ---------------------------------------------------------------------------
__device__ float g_p_embT[POS_E * NTOK];             // [E][tok]
__device__ float g_w_embT[WORD_E * NTOK];
__device__ float g_poutsT[POS_H * NTOKP];            // histories [H][NTOKP], slot t+1
__device__ float g_wh0T[WORD_H * NTOKP];
__device__ float g_woutsT[WORD_H * NTOKP];
__device__ float g_wmidT[WORD_E * NTOK];
__device__ float g_preT_p[4 * POS_H * NTOK];         // emb@Wih pos, [4H][tok]
__device__ float g_preT_w0[4 * WORD_H * NTOK];
// packed sequential weights, k-major per block: [blk][K][ROWS]
__device__ float g_Wpos[4 * POS_H * 1280];           // [128][1280][8]
__device__ float g_Ww0[4 * WORD_H * 1280];           // [128][1280][32]
__device__ float g_Ww1[4 * WORD_H * 2048];           // [128][2048][32]
__device__ float g_bpos[4 * POS_H], g_bw0[4 * WORD_H], g_bw1[4 * WORD_H];
// cell state ping-pong (each [H][32]; block-private rows)
__device__ float g_Cpos[2][POS_H * BB];
__device__ float g_Cw0[2][WORD_H * BB];
__device__ float g_Cw1[2][WORD_H * BB];
__device__ unsigned g_bar_ctr;
}  // namespace

// ---------------------------------------------------------------------------
// f32x2 packed helpers
// ---------------------------------------------------------------------------
__device__ __forceinline__ ull pack2(float lo, float hi) {
    ull r; asm("mov.b64 %0, {%1,%2};" : "=l"(r) : "f"(lo), "f"(hi)); return r;
}
__device__ __forceinline__ ull dup2(float v) { return pack2(v, v); }
__device__ __forceinline__ void fma2(ull& d, ull a, ull b) {
    asm("fma.rn.f32x2 %0, %1, %2, %0;" : "+l"(d) : "l"(a), "l"(b));
}
__device__ __forceinline__ void unpack2(ull v, float& lo, float& hi) {
    asm("mov.b64 {%0,%1}, %2;" : "=f"(lo), "=f"(hi) : "l"(v));
}
__device__ __forceinline__ float sigm(float x) { return 1.f / (1.f + expf(-x)); }

// ---------------------------------------------------------------------------
// Init / gather / weight repack
// ---------------------------------------------------------------------------
__global__ void zero_init_kernel() {
    int i = blockIdx.x * blockDim.x + threadIdx.x;
    if (i < POS_H * BB) {
        g_poutsT[(size_t)(i >> 5) * NTOKP + (i & 31)] = 0.f;
        g_Cpos[0][i] = 0.f;
    }
    if (i < WORD_H * BB) {
        int r = i >> 5, b = i & 31;
        g_wh0T[(size_t)r * NTOKP + b] = 0.f;
        g_woutsT[(size_t)r * NTOKP + b] = 0.f;
        g_Cw0[0][i] = 0.f;
        g_Cw1[0][i] = 0.f;
    }
    if (i == 0) g_bar_ctr = 0u;
}

__global__ void gather_kernel(const int* __restrict__ pos, const int* __restrict__ word,
                              const float* __restrict__ posW, const float* __restrict__ wordW) {
    int j = blockIdx.x * blockDim.x + threadIdx.x;
    if (j < WORD_E * NTOK) {
        int d = j / NTOK, tok = j - d * NTOK;
        g_w_embT[j] = wordW[(size_t)word[tok] * WORD_E + d];
    }
    if (j < POS_E * NTOK) {
        int d = j / NTOK, tok = j - d * NTOK;
        g_p_embT[j] = posW[(size_t)pos[tok] * POS_E + d];
    }
}

// Repack into k-major per-block layout (source row strides: 1088 / 768 / 1024).
__global__ void repack_kernel(const float* __restrict__ pWih, const float* __restrict__ pWhh,
                              const float* __restrict__ w0Wih, const float* __restrict__ w0Whh,
                              const float* __restrict__ w1Wih, const float* __restrict__ w1Whh,
                              const float* __restrict__ pbih, const float* __restrict__ pbhh,
                              const float* __restrict__ w0bih, const float* __restrict__ w0bhh,
                              const float* __restrict__ w1bih, const float* __restrict__ w1bhh) {
    int i = blockIdx.x * blockDim.x + threadIdx.x;
    const int A = 4 * POS_H * 1280;
    const int Bq = 4 * WORD_H * 1280;
    const int Cq = 4 * WORD_H * 2048;
    if (i < A) {
        int blk = i / (1280 * 8), rem = i - blk * (1280 * 8);
        int k = rem >> 3, rowl = rem & 7;
        int g = rowl >> 1, hh = rowl & 1;
        int R = g * POS_H + blk * 2 + hh;
        g_Wpos[i] = (k < 1024) ? pWih[(size_t)R * 1088 + 64 + k]
                               : pWhh[(size_t)R * 256 + (k - 1024)];
        return;
    }
    i -= A;
    if (i < Bq) {
        int blk = i / (1280 * 32), rem = i - blk * (1280 * 32);
        int k = rem >> 5, rowl = rem & 31;
        int g = rowl >> 3, hh = rowl & 7;
        int R = g * WORD_H + blk * 8 + hh;
        g_Ww0[i] = (k < 256) ? w0Wih[(size_t)R * 768 + 512 + k]
                             : w0Whh[(size_t)R * 1024 + (k - 256)];
        return;
    }
    i -= Bq;
    if (i < Cq) {
        int blk = i / (2048 * 32), rem = i - blk * (2048 * 32);
        int k = rem >> 5, rowl = rem & 31;
        int g = rowl >> 3, hh = rowl & 7;
        int R = g * WORD_H + blk * 8 + hh;
        g_Ww1[i] = (k < 1024) ? w1Wih[(size_t)R * 1024 + k]
                              : w1Whh[(size_t)R * 1024 + (k - 1024)];
        return;
    }
    i -= Cq;
    if (i < 4 * POS_H) { g_bpos[i] = pbih[i] + pbhh[i]; return; }
    i -= 4 * POS_H;
    if (i < 4 * WORD_H) { g_bw0[i] = w0bih[i] + w0bhh[i]; return; }
    i -= 4 * WORD_H;
    if (i < 4 * WORD_H) { g_bw1[i] = w1bih[i] + w1bhh[i]; }
}

// ---------------------------------------------------------------------------
// Persistent recurrence kernel: 128 blocks x 512 threads, 192KB dynamic smem.
// (byte-identical to Round 7 — proven 8,980us baseline)
// ---------------------------------------------------------------------------
constexpr int REC_THREADS = 512;
constexpr int REC_SMEM = (2 * 256 * 32 + 2 * 256 * 32 + 16 * 32 * 32) * 4;  // 196608

__device__ __forceinline__ void grid_barrier(unsigned target) {
    __syncthreads();
    if (threadIdx.x == 0) {
        __threadfence();
        atomicAdd(&g_bar_ctr, 1u);
        while (*(volatile unsigned*)&g_bar_ctr < target) __nanosleep(64);
        __threadfence();
    }
    __syncthreads();
}

// Word-size LSTM cell (H=1024). 256-k chunks; 16 warps = 16 k-slices (16 k each).
template <int K>
__device__ __forceinline__ void cell_word(
    float (*xs)[256][32], float (*ws)[256][32], float (*red)[32][32],
    const float* __restrict__ Wblk, const float* __restrict__ bcomb,
    const float* __restrict__ preT, int tok0,
    const float* __restrict__ x1, int K1, const float* __restrict__ x2,
    const float* __restrict__ cin, float* __restrict__ cout,
    float* __restrict__ hcol) {
    constexpr int NC = K / 256;
    const int tid = threadIdx.x;
    const int w = tid >> 5, lane = tid & 31;
    const int rowg = lane >> 2;   // rows rowg*4..+3
    const int bg = lane & 3;      // batch bg*8..+7

    // gate-operand prefetch
    const int hh = tid >> 5, gb = tid & 31;
    const int habs_g = blockIdx.x * 8 + hh;
    float cin_v = 0.f, bb[4], pre_g[4];
    if (tid < 256) {
        cin_v = cin[habs_g * 32 + gb];
#pragma unroll
        for (int g = 0; g < 4; g++) {
            bb[g] = bcomb[g * WORD_H + habs_g];
            pre_g[g] = preT ? preT[(size_t)(g * WORD_H + habs_g) * NTOK + tok0 + gb] : 0.f;
        }
    }

    ull acc[4][4];
#pragma unroll
    for (int r = 0; r < 4; r++)
#pragma unroll
        for (int j = 0; j < 4; j++) acc[r][j] = 0ull;

    float4 px[4], pw[4];
#pragma unroll
    for (int it = 0; it < 4; it++) {   // chunk 0 (always inside x1)
        int f = tid + it * REC_THREADS;
        px[it] = *(const float4*)(x1 + (size_t)(f >> 3) * NTOKP + (f & 7) * 4);
        pw[it] = *(const float4*)(Wblk + (size_t)(f >> 3) * 32 + (f & 7) * 4);
    }
#pragma unroll
    for (int it = 0; it < 4; it++) {
        int f = tid + it * REC_THREADS;
        *(float4*)&xs[0][f >> 3][(f & 7) * 4] = px[it];
        *(float4*)&ws[0][f >> 3][(f & 7) * 4] = pw[it];
    }
    __syncthreads();

    for (int c = 0; c < NC; c++) {
        const int cur = c & 1, nxt = cur ^ 1;
        if (c + 1 < NC) {
            int kb = (c + 1) * 256;
            const float* xsrc = (kb < K1) ? x1 + (size_t)kb * NTOKP
                                          : x2 + (size_t)(kb - K1) * NTOKP;
            const float* wsrc = Wblk + (size_t)kb * 32;
#pragma unroll
            for (int it = 0; it < 4; it++) {
                int f = tid + it * REC_THREADS;
                px[it] = *(const float4*)(xsrc + (size_t)(f >> 3) * NTOKP + (f & 7) * 4);
                pw[it] = *(const float4*)(wsrc + (size_t)(f >> 3) * 32 + (f & 7) * 4);
            }
        }
#pragma unroll
        for (int kk = 0; kk < 16; kk++) {
            int k = w * 16 + kk;
            const ulonglong2* xp = (const ulonglong2*)&xs[cur][k][bg * 8];
            ulonglong2 xv0 = xp[0], xv1 = xp[1];
            float4 wv = *(const float4*)&ws[cur][k][rowg * 4];
            ull wd0 = dup2(wv.x), wd1 = dup2(wv.y), wd2 = dup2(wv.z), wd3 = dup2(wv.w);
            fma2(acc[0][0], wd0, xv0.x); fma2(acc[0][1], wd0, xv0.y);
            fma2(acc[0][2], wd0, xv1.x); fma2(acc[0][3], wd0, xv1.y);
            fma2(acc[1][0], wd1, xv0.x); fma2(acc[1][1], wd1, xv0.y);
            fma2(acc[1][2], wd1, xv1.x); fma2(acc[1][3], wd1, xv1.y);
            fma2(acc[2][0], wd2, xv0.x); fma2(acc[2][1], wd2, xv0.y);
            fma2(acc[2][2], wd2, xv1.x); fma2(acc[2][3], wd2, xv1.y);
            fma2(acc[3][0], wd3, xv0.x); fma2(acc[3][1], wd3, xv0.y);
            fma2(acc[3][2], wd3, xv1.x); fma2(acc[3][3], wd3, xv1.y);
        }
        if (c + 1 < NC) {
#pragma unroll
            for (int it = 0; it < 4; it++) {
                int f = tid + it * REC_THREADS;
                *(float4*)&xs[nxt][f >> 3][(f & 7) * 4] = px[it];
                *(float4*)&ws[nxt][f >> 3][(f & 7) * 4] = pw[it];
            }
        }
        __syncthreads();
    }
#pragma unroll
    for (int r = 0; r < 4; r++) {
        int row = rowg * 4 + r;
#pragma unroll
        for (int j = 0; j < 4; j += 2) {
            float a0, a1, a2, a3;
            unpack2(acc[r][j], a0, a1);
            unpack2(acc[r][j + 1], a2, a3);
            *(float4*)&red[w][row][bg * 8 + j * 2] = make_float4(a0, a1, a2, a3);
        }
    }
    __syncthreads();
    if (tid < 256) {
        float gs[4];
#pragma unroll
        for (int g = 0; g < 4; g++) {
            float s = bb[g] + pre_g[g];
#pragma unroll
            for (int ww = 0; ww < 16; ww++) s += red[ww][g * 8 + hh][gb];
            gs[g] = s;
        }
        float i = sigm(gs[0]), f = sigm(gs[1]), g = tanhf(gs[2]), o = sigm(gs[3]);
        float c2 = f * cin_v + i * g;
        float h2 = o * tanhf(c2);
        cout[habs_g * 32 + gb] = c2;
        hcol[(size_t)habs_g * NTOKP + gb] = h2;
    }
}

// Pos cell (H=256, ROWS=8, K=1280, K1=1024). 256-k chunks; 8 k-slices of 64.
__device__ __forceinline__ void cell_pos(
    float (*xs)[256][32], float (*ws)[256][32], float (*red)[32][32],
    const float* __restrict__ Wblk, const float* __restrict__ bcomb,
    const float* __restrict__ preT, int tok0,
    const float* __restrict__ x1 /*1024 rows*/, const float* __restrict__ x2 /*256*/,
    const float* __restrict__ cin, float* __restrict__ cout,
    float* __restrict__ hcol) {
    constexpr int K = 1280, NC = K / 256, K1 = 1024;
    const int tid = threadIdx.x;
    const int ksl = tid >> 6;     // 0..7
    const int sub = tid & 63;
    const int rowl = sub >> 3;    // 0..7
    const int bg = sub & 7;       // batch bg*4..+3

    const int hh = tid >> 5, gb = tid & 31;
    const int habs_g = blockIdx.x * 2 + hh;
    float cin_v = 0.f, bb[4], pre_g[4];
    if (tid < 64) {
        cin_v = cin[habs_g * 32 + gb];
#pragma unroll
        for (int g = 0; g < 4; g++) {
            bb[g] = bcomb[g * POS_H + habs_g];
            pre_g[g] = preT[(size_t)(g * POS_H + habs_g) * NTOK + tok0 + gb];
        }
    }

    ull acc0 = 0ull, acc1 = 0ull;
    float4 px[4], pw;
#pragma unroll
    for (int it = 0; it < 4; it++) {
        int f = tid + it * REC_THREADS;
        px[it] = *(const float4*)(x1 + (size_t)(f >> 3) * NTOKP + (f & 7) * 4);
    }
    pw = *(const float4*)(Wblk + (size_t)(tid >> 1) * 8 + (tid & 1) * 4);
#pragma unroll
    for (int it = 0; it < 4; it++) {
        int f = tid + it * REC_THREADS;
        *(float4*)&xs[0][f >> 3][(f & 7) * 4] = px[it];
    }
    *(float4*)&ws[0][tid >> 1][(tid & 1) * 4] = pw;
    __syncthreads();

    for (int c = 0; c < NC; c++) {
        const int cur = c & 1, nxt = cur ^ 1;
        if (c + 1 < NC) {
            int kb = (c + 1) * 256;
            const float* xsrc = (kb < K1) ? x1 + (size_t)kb * NTOKP
                                          : x2 + (size_t)(kb - K1) * NTOKP;
#pragma unroll
            for (int it = 0; it < 4; it++) {
                int f = tid + it * REC_THREADS;
                px[it] = *(const float4*)(xsrc + (size_t)(f >> 3) * NTOKP + (f & 7) * 4);
            }
            pw = *(const float4*)(Wblk + (size_t)(kb + (tid >> 1)) * 8 + (tid & 1) * 4);
        }
#pragma unroll
        for (int kk = 0; kk < 32; kk++) {
            int k = ksl * 32 + kk;
            ulonglong2 xv = *(const ulonglong2*)&xs[cur][k][bg * 4];
            ull wd = dup2(ws[cur][k][rowl]);
            fma2(acc0, wd, xv.x);
            fma2(acc1, wd, xv.y);
        }
        if (c + 1 < NC) {
#pragma unroll
            for (int it = 0; it < 4; it++) {
                int f = tid + it * REC_THREADS;
                *(float4*)&xs[nxt][f >> 3][(f & 7) * 4] = px[it];
            }
            *(float4*)&ws[nxt][tid >> 1][(tid & 1) * 4] = pw;
        }
        __syncthreads();
    }
    {
        float a0, a1, a2, a3;
        unpack2(acc0, a0, a1);
        unpack2(acc1, a2, a3);
        *(float4*)&red[ksl][rowl][bg * 4] = make_float4(a0, a1, a2, a3);
    }
    __syncthreads();
    if (tid < 64) {
        float gs[4];
#pragma unroll
        for (int g = 0; g < 4; g++) {
            float s = bb[g] + pre_g[g];
#pragma unroll
            for (int s8 = 0; s8 < 8; s8++) s += red[s8][g * 2 + hh][gb];
            gs[g] = s;
        }
        float i = sigm(gs[0]), f = sigm(gs[1]), g = tanhf(gs[2]), o = sigm(gs[3]);
        float c2 = f * cin_v + i * g;
        float h2 = o * tanhf(c2);
        cout[habs_g * 32 + gb] = c2;
        hcol[(size_t)habs_g * NTOKP + gb] = h2;
    }
}

__global__ __launch_bounds__(REC_THREADS, 1) void recurrence_kernel() {
    extern __shared__ float smem[];
    float (*xs)[256][32] = (float(*)[256][32])smem;
    float (*ws)[256][32] = (float(*)[256][32])(smem + 2 * 256 * 32);
    float (*red)[32][32] = (float(*)[32][32])(smem + 4 * 256 * 32);
    unsigned ep = 0;
    const unsigned NB = gridDim.x;
    const int blk = blockIdx.x;
    const float* WposB = g_Wpos + (size_t)blk * 1280 * 8;
    const float* Ww0B  = g_Ww0 + (size_t)blk * 1280 * 32;
    const float* Ww1B  = g_Ww1 + (size_t)blk * 2048 * 32;
    for (int t = 0; t < TT; t++) {
        const int p = t & 1, q = p ^ 1;
        const int tok0 = t * BB;
        cell_pos(xs, ws, red, WposB, g_bpos, g_preT_p, tok0,
                 g_woutsT + (size_t)t * 32, g_poutsT + (size_t)t * 32,
                 g_Cpos[p], g_Cpos[q], g_poutsT + (size_t)(t + 1) * 32);
        grid_barrier(++ep * NB);
        cell_word<1280>(xs, ws, red, Ww0B, g_bw0, g_preT_w0, tok0,
                        g_poutsT + (size_t)(t + 1) * 32, 256,
                        g_wh0T + (size_t)t * 32,
                        g_Cw0[p], g_Cw0[q], g_wh0T + (size_t)(t + 1) * 32);
        grid_barrier(++ep * NB);
        cell_word<2048>(xs, ws, red, Ww1B, g_bw1, nullptr, tok0,
                        g_wh0T + (size_t)(t + 1) * 32, 1024,
                        g_woutsT + (size_t)t * 32,
                        g_Cw1[p], g_Cw1[q], g_woutsT + (size_t)(t + 1) * 32);
        grid_barrier(++ep * NB);
    }
}

// ---------------------------------------------------------------------------
// Pipelined f32x2 GEMM: C[m,n] = sum_k AT[k,m]*W[n,k] + bias[n].
// Register double buffer (LDG->reg while computing, STS into other smem buf) —
// the exact pattern proven in the recurrence cells. No cp.async.
// Dynamic smem: As[2][32][128] | Ws[2][32][132]
// ---------------------------------------------------------------------------
constexpr int GEMM_SMEM = (2 * 32 * 128 + 2 * 32 * 132) * 4;  // 66560

__global__ __launch_bounds__(256, 2) void gemm_t_kernel(
    const float* __restrict__ AT, int M, int lda,
    const float* __restrict__ W, int ldw, const float* __restrict__ bias,
    float* __restrict__ C, float* __restrict__ CT, int N, int K) {
    extern __shared__ float gsm[];
    float (*As)[32][128] = (float(*)[32][128])gsm;
    float (*Ws)[32][132] = (float(*)[32][132])(gsm + 2 * 32 * 128);
    const int tid = threadIdx.x;
    const int rt = tid & 15;
    const int ct = tid >> 4;
    const int rBase = blockIdx.y * 128, cBase = blockIdx.x * 128;
    const int NC = K / 32;

    // per-thread load coordinates
    const int ak = tid >> 5, am4 = tid & 31;          // A: [k][m4*4], k=ak, +8 per it
    const int wn = tid >> 3, wk4 = tid & 7;           // W: row n=wn (+32 per it), k4

    ull acc[8][4];
#pragma unroll
    for (int jj = 0; jj < 8; jj++)
#pragma unroll
        for (int p = 0; p < 4; p++) acc[jj][p] = 0ull;

    float4 pa[4], pww[4];
    // prologue: tile 0
#pragma unroll
    for (int it = 0; it < 4; it++) {
        pa[it] = *(const float4*)&AT[(size_t)(ak + it * 8) * lda + rBase + am4 * 4];
        pww[it] = *(const float4*)&W[(size_t)(cBase + wn + it * 32) * ldw + wk4 * 4];
    }
#pragma unroll
    for (int it = 0; it < 4; it++) {
        *(float4*)&As[0][ak + it * 8][am4 * 4] = pa[it];
        int n = wn + it * 32;
        Ws[0][wk4 * 4 + 0][n] = pww[it].x;
        Ws[0][wk4 * 4 + 1][n] = pww[it].y;
        Ws[0][wk4 * 4 + 2][n] = pww[it].z;
        Ws[0][wk4 * 4 + 3][n] = pww[it].w;
    }
    __syncthreads();

    for (int c = 0; c < NC; c++) {
        const int cur = c & 1, nxt = cur ^ 1;
        if (c + 1 < NC) {
            int kb = (c + 1) * 32;
#pragma unroll
            for (int it = 0; it < 4; it++) {
                pa[it] = *(const float4*)&AT[(size_t)(kb + ak + it * 8) * lda + rBase + am4 * 4];
                pww[it] = *(const float4*)&W[(size_t)(cBase + wn + it * 32) * ldw + kb + wk4 * 4];
            }
        }
#pragma unroll
        for (int k = 0; k < 32; k++) {
            ull xd[8];
#pragma unroll
            for (int jj = 0; jj < 8; jj++) xd[jj] = dup2(As[cur][k][rt + 16 * jj]);
            const ulonglong2* wpp = (const ulonglong2*)&Ws[cur][k][ct * 8];
            ulonglong2 wa = wpp[0];
            ulonglong2 wb = wpp[1];
#pragma unroll
            for (int jj = 0; jj < 8; jj++) {
                fma2(acc[jj][0], xd[jj], wa.x);
                fma2(acc[jj][1], xd[jj], wa.y);
                fma2(acc[jj][2], xd[jj], wb.x);
                fma2(acc[jj][3], xd[jj], wb.y);
            }
        }
        if (c + 1 < NC) {
#pragma unroll
            for (int it = 0; it < 4; it++) {
                *(float4*)&As[nxt][ak + it * 8][am4 * 4] = pa[it];
                int n = wn + it * 32;
                Ws[nxt][wk4 * 4 + 0][n] = pww[it].x;
                Ws[nxt][wk4 * 4 + 1][n] = pww[it].y;
                Ws[nxt][wk4 * 4 + 2][n] = pww[it].z;
                Ws[nxt][wk4 * 4 + 3][n] = pww[it].w;
            }
        }
        __syncthreads();
    }

    float bcol[8];
#pragma unroll
    for (int qq = 0; qq < 8; qq++) bcol[qq] = bias ? bias[cBase + ct * 8 + qq] : 0.f;
#pragma unroll
    for (int jj = 0; jj < 8; jj++) {
        int m = rBase + rt + 16 * jj;
        float v[8];
#pragma unroll
        for (int p = 0; p < 4; p++) unpack2(acc[jj][p], v[2 * p], v[2 * p + 1]);
#pragma unroll
        for (int qq = 0; qq < 8; qq++) v[qq] += bcol[qq];
        if (C) {
            float4* dst = (float4*)&C[(size_t)m * N + cBase + ct * 8];
            dst[0] = make_float4(v[0], v[1], v[2], v[3]);
            dst[1] = make_float4(v[4], v[5], v[6], v[7]);
        }
        if (CT) {
#pragma unroll
            for (int qq = 0; qq < 8; qq++)
                CT[(size_t)(cBase + ct * 8 + qq) * M + m] = v[qq];
        }
    }
}

// ---------------------------------------------------------------------------
// pos projection + log-softmax (one block per timestep)
// ---------------------------------------------------------------------------
__global__ void pos_projT_kernel(const float* __restrict__ Wp, const float* __restrict__ bp,
                                 float* __restrict__ out) {
    __shared__ float xs[POS_H][32];
    __shared__ float lg[POS_V][33];
    __shared__ float lsb[32];
    const int t = blockIdx.x;
    const int tok0 = t * 32;
    const int tid = threadIdx.x;
    const int b = tid & 31, vg = tid >> 5;
    for (int i = tid; i < POS_H * 32; i += 256) {
        int k = i >> 5, bb = i & 31;
        xs[k][bb] = g_poutsT[(size_t)k * NTOKP + 32 + tok0 + bb];
    }
    __syncthreads();
    for (int v = vg; v < POS_V; v += 8) {
        float s = bp[v];
        const float* wv = Wp + (size_t)v * POS_H;
        for (int k = 0; k < POS_H; k++) s = fmaf(xs[k][b], wv[k], s);
        lg[v][b] = s;
    }
    __syncthreads();
    if (tid < 32) {
        float m = -INFINITY;
        for (int v = 0; v < POS_V; v++) m = fmaxf(m, lg[v][tid]);
        float e = 0.f;
        for (int v = 0; v < POS_V; v++) e += expf(lg[v][tid] - m);
        lsb[tid] = m + logf(e);
    }
    __syncthreads();
    float ls = lsb[b];
    for (int v = vg; v < POS_V; v += 8)
        out[(size_t)(tok0 + b) * POS_V + v] = lg[v][b] - ls;
}

// ---------------------------------------------------------------------------
// word log-softmax in place over 32000 (one block per row, float4)
// ---------------------------------------------------------------------------
__global__ void word_softmax_kernel(float* __restrict__ logits) {
    __shared__ float red[8];
    const int row = blockIdx.x;
    float4* p4 = (float4*)(logits + (size_t)row * WORD_V);
    const int NV4 = WORD_V / 4;  // 8000
    const int tid = threadIdx.x;  // 256
    float m = -INFINITY;
    for (int i = tid; i < NV4; i += 256) {
        float4 v = p4[i];
        m = fmaxf(m, fmaxf(fmaxf(v.x, v.y), fmaxf(v.z, v.w)));
    }
#pragma unroll
    for (int o = 16; o; o >>= 1) m = fmaxf(m, __shfl_xor_sync(0xffffffffu, m, o));
    if ((tid & 31) == 0) red[tid >> 5] = m;
    __syncthreads();
    float M = red[0];
#pragma unroll
    for (int w = 1; w < 8; w++) M = fmaxf(M, red[w]);
    __syncthreads();
    float s = 0.f;
    for (int i = tid; i < NV4; i += 256) {
        float4 v = p4[i];
        s += expf(v.x - M) + expf(v.y - M) + expf(v.z - M) + expf(v.w - M);
    }
#pragma unroll
    for (int o = 16; o; o >>= 1) s += __shfl_xor_sync(0xffffffffu, s, o);
    if ((tid & 31) == 0) red[tid >> 5] = s;
    __syncthreads();
    float S = 0.f;
#pragma unroll
    for (int w = 0; w < 8; w++) S += red[w];
    float ls = M + logf(S);
    for (int i = tid; i < NV4; i += 256) {
        float4 v = p4[i];
        v.x -= ls; v.y -= ls; v.z -= ls; v.w -= ls;
        p4[i] = v;
    }
}

// ---------------------------------------------------------------------------
// Host side
// ---------------------------------------------------------------------------
extern "C" void kernel_launch(void* const* d_in, const int* in_sizes, int n_in,
                              void* d_out, int out_size) {
    (void)in_sizes; (void)n_in; (void)out_size;
    const int*   pos        = (const int*)d_in[0];
    const int*   word       = (const int*)d_in[1];
    const float* pos_emb_W  = (const float*)d_in[2];
    const float* word_emb_W = (const float*)d_in[3];
    const float* pos_Wih    = (const float*)d_in[4];
    const float* pos_Whh    = (const float*)d_in[5];
    const float* pos_bih    = (const float*)d_in[6];
    const float* pos_bhh    = (const float*)d_in[7];
    const float* w0_Wih     = (const float*)d_in[8];
    const float* w0_Whh     = (const float*)d_in[9];
    const float* w0_bih     = (const float*)d_in[10];
    const float* w0_bhh     = (const float*)d_in[11];
    const float* w1_Wih     = (const float*)d_in[12];
    const float* w1_Whh     = (const float*)d_in[13];
    const float* w1_bih     = (const float*)d_in[14];
    const float* w1_bhh     = (const float*)d_in[15];
    const float* pos_proj_W = (const float*)d_in[16];
    const float* pos_proj_b = (const float*)d_in[17];
    const float* wp1_W      = (const float*)d_in[18];
    const float* wp1_b      = (const float*)d_in[19];
    const float* wp2_b      = (const float*)d_in[20];
    float* out = (float*)d_out;

    float *p_embT, *w_embT, *woutsT, *wmidT, *preT_p, *preT_w0;
    cudaGetSymbolAddress((void**)&p_embT, g_p_embT);
    cudaGetSymbolAddress((void**)&w_embT, g_w_embT);
    cudaGetSymbolAddress((void**)&woutsT, g_woutsT);
    cudaGetSymbolAddress((void**)&wmidT, g_wmidT);
    cudaGetSymbolAddress((void**)&preT_p, g_preT_p);
    cudaGetSymbolAddress((void**)&preT_w0, g_preT_w0);

    static bool attr_done = false;
    if (!attr_done) {
        cudaFuncSetAttribute(recurrence_kernel,
                             cudaFuncAttributeMaxDynamicSharedMemorySize, REC_SMEM);
        cudaFuncSetAttribute(gemm_t_kernel,
                             cudaFuncAttributeMaxDynamicSharedMemorySize, GEMM_SMEM);
        attr_done = true;
    }

    zero_init_kernel<<<(WORD_H * BB + 255) / 256, 256>>>();
    gather_kernel<<<(WORD_E * NTOK + 255) / 256, 256>>>(pos, word, pos_emb_W, word_emb_W);

    {
        const int total = 4 * POS_H * 1280 + 4 * WORD_H * 1280 + 4 * WORD_H * 2048 +
                          4 * POS_H + 2 * (4 * WORD_H);
        repack_kernel<<<(total + 255) / 256, 256>>>(
            pos_Wih, pos_Whh, w0_Wih, w0_Whh, w1_Wih, w1_Whh,
            pos_bih, pos_bhh, w0_bih, w0_bhh, w1_bih, w1_bhh);
    }

    // precompute emb @ Wih_emb-part for all timesteps (transposed outputs)
    gemm_t_kernel<<<dim3(4 * POS_H / 128, NTOK / 128), 256, GEMM_SMEM>>>(
        p_embT, NTOK, NTOK, pos_Wih, POS_E + WORD_H, nullptr,
        nullptr, preT_p, 4 * POS_H, POS_E);
    gemm_t_kernel<<<dim3(4 * WORD_H / 128, NTOK / 128), 256, GEMM_SMEM>>>(
        w_embT, NTOK, NTOK, w0_Wih, WORD_E + POS_H, nullptr,
        nullptr, preT_w0, 4 * WORD_H, WORD_E);

    // the whole 128-step recurrence in ONE persistent kernel
    recurrence_kernel<<<128, REC_THREADS, REC_SMEM>>>();

    // pos projection + log-softmax
    pos_projT_kernel<<<TT, 256>>>(pos_proj_W, pos_proj_b, out);

    // word head
    gemm_t_kernel<<<dim3(WORD_E / 128, NTOK / 128), 256, GEMM_SMEM>>>(
        woutsT + 32, NTOK, NTOKP, wp1_W, WORD_H, wp1_b,
        nullptr, wmidT, WORD_E, WORD_H);
    float* wlp = out + (size_t)NTOK * POS_V;
    gemm_t_kernel<<<dim3(WORD_V / 128, NTOK / 128), 256, GEMM_SMEM>>>(
        wmidT, NTOK, NTOK, word_emb_W, WORD_E, wp2_b,
        wlp, nullptr, WORD_V, WORD_E);
    word_softmax_kernel<<<NTOK, 256>>>(wlp);
}

// round 12
// speedup vs baseline: 2.0716x; 1.2770x over previous
#include <cuda_runtime.h>
#include <cuda_bf16.h>
#include <stdint.h>
#include <math.h>

typedef unsigned long long ull;

// ---------------------------------------------------------------------------
// Problem constants
// ---------------------------------------------------------------------------
namespace {
constexpr int TT = 128, BB = 32;
constexpr int POS_E = 64, WORD_E = 512, POS_H = 256, WORD_H = 1024;
constexpr int POS_V = 45, WORD_V = 32000;
constexpr int NTOK = TT * BB;      // 4096
constexpr int NTOKP = NTOK + 32;   // history col 0 = zeros (t = -1 slot)

// ---------------------------------------------------------------------------
// Device scratch (static globals; no allocation allowed)
// ---------------------------------------------------------------------------
__device__ float g_p_embT[POS_E * NTOK];             // [E][tok]
__device__ float g_w_embT[WORD_E * NTOK];
__device__ float g_poutsT[POS_H * NTOKP];            // histories [H][NTOKP], slot t+1
__device__ float g_wh0T[WORD_H * NTOKP];
__device__ float g_woutsT[WORD_H * NTOKP];
__device__ float g_wmid[NTOK * WORD_E];              // wp1 output, row-major
__device__ __nv_bfloat16 g_wmid_bf[NTOK * WORD_E];   // bf16 copy (4 MB)
__device__ __nv_bfloat16 g_emb_bf[WORD_V * WORD_E];  // bf16 word emb (32 MB)
__device__ float g_preT_p[4 * POS_H * NTOK];         // emb@Wih pos, [4H][tok]
__device__ float g_preT_w0[4 * WORD_H * NTOK];
// packed sequential weights, k-major per block: [blk][K][ROWS]
__device__ float g_Wpos[4 * POS_H * 1280];           // [128][1280][8]
__device__ float g_Ww0[4 * WORD_H * 1280];           // [128][1280][32]
__device__ float g_Ww1[4 * WORD_H * 2048];           // [128][2048][32]
__device__ float g_bpos[4 * POS_H], g_bw0[4 * WORD_H], g_bw1[4 * WORD_H];
// cell state ping-pong (each [H][32]; block-private rows)
__device__ float g_Cpos[2][POS_H * BB];
__device__ float g_Cw0[2][WORD_H * BB];
__device__ float g_Cw1[2][WORD_H * BB];
__device__ unsigned g_bar_ctr;
}  // namespace

// ---------------------------------------------------------------------------
// f32x2 packed helpers
// ---------------------------------------------------------------------------
__device__ __forceinline__ ull pack2(float lo, float hi) {
    ull r; asm("mov.b64 %0, {%1,%2};" : "=l"(r) : "f"(lo), "f"(hi)); return r;
}
__device__ __forceinline__ ull dup2(float v) { return pack2(v, v); }
__device__ __forceinline__ void fma2(ull& d, ull a, ull b) {
    asm("fma.rn.f32x2 %0, %1, %2, %0;" : "+l"(d) : "l"(a), "l"(b));
}
__device__ __forceinline__ void unpack2(ull v, float& lo, float& hi) {
    asm("mov.b64 {%0,%1}, %2;" : "=f"(lo), "=f"(hi) : "l"(v));
}
__device__ __forceinline__ float sigm(float x) { return 1.f / (1.f + expf(-x)); }

// ---------------------------------------------------------------------------
// Init / gather / conversions / weight repack
// ---------------------------------------------------------------------------
__global__ void zero_init_kernel() {
    int i = blockIdx.x * blockDim.x + threadIdx.x;
    if (i < POS_H * BB) {
        g_poutsT[(size_t)(i >> 5) * NTOKP + (i & 31)] = 0.f;
        g_Cpos[0][i] = 0.f;
    }
    if (i < WORD_H * BB) {
        int r = i >> 5, b = i & 31;
        g_wh0T[(size_t)r * NTOKP + b] = 0.f;
        g_woutsT[(size_t)r * NTOKP + b] = 0.f;
        g_Cw0[0][i] = 0.f;
        g_Cw1[0][i] = 0.f;
    }
    if (i == 0) g_bar_ctr = 0u;
}

__global__ void gather_kernel(const int* __restrict__ pos, const int* __restrict__ word,
                              const float* __restrict__ posW, const float* __restrict__ wordW) {
    int j = blockIdx.x * blockDim.x + threadIdx.x;
    if (j < WORD_E * NTOK) {
        int d = j / NTOK, tok = j - d * NTOK;
        g_w_embT[j] = wordW[(size_t)word[tok] * WORD_E + d];
    }
    if (j < POS_E * NTOK) {
        int d = j / NTOK, tok = j - d * NTOK;
        g_p_embT[j] = posW[(size_t)pos[tok] * POS_E + d];
    }
}

__global__ void cvt_emb_kernel(const float* __restrict__ src) {
    size_t i = ((size_t)blockIdx.x * blockDim.x + threadIdx.x) * 4;
    if (i < (size_t)WORD_V * WORD_E) {
        float4 v = *(const float4*)(src + i);
        *(__nv_bfloat162*)&g_emb_bf[i] = __floats2bfloat162_rn(v.x, v.y);
        *(__nv_bfloat162*)&g_emb_bf[i + 2] = __floats2bfloat162_rn(v.z, v.w);
    }
}

__global__ void cvt_wmid_kernel() {
    size_t i = ((size_t)blockIdx.x * blockDim.x + threadIdx.x) * 4;
    if (i < (size_t)NTOK * WORD_E) {
        float4 v = *(const float4*)(g_wmid + i);
        *(__nv_bfloat162*)&g_wmid_bf[i] = __floats2bfloat162_rn(v.x, v.y);
        *(__nv_bfloat162*)&g_wmid_bf[i + 2] = __floats2bfloat162_rn(v.z, v.w);
    }
}

// Repack into k-major per-block layout (source row strides: 1088 / 768 / 1024).
__global__ void repack_kernel(const float* __restrict__ pWih, const float* __restrict__ pWhh,
                              const float* __restrict__ w0Wih, const float* __restrict__ w0Whh,
                              const float* __restrict__ w1Wih, const float* __restrict__ w1Whh,
                              const float* __restrict__ pbih, const float* __restrict__ pbhh,
                              const float* __restrict__ w0bih, const float* __restrict__ w0bhh,
                              const float* __restrict__ w1bih, const float* __restrict__ w1bhh) {
    int i = blockIdx.x * blockDim.x + threadIdx.x;
    const int A = 4 * POS_H * 1280;
    const int Bq = 4 * WORD_H * 1280;
    const int Cq = 4 * WORD_H * 2048;
    if (i < A) {
        int blk = i / (1280 * 8), rem = i - blk * (1280 * 8);
        int k = rem >> 3, rowl = rem & 7;
        int g = rowl >> 1, hh = rowl & 1;
        int R = g * POS_H + blk * 2 + hh;
        g_Wpos[i] = (k < 1024) ? pWih[(size_t)R * 1088 + 64 + k]
                               : pWhh[(size_t)R * 256 + (k - 1024)];
        return;
    }
    i -= A;
    if (i < Bq) {
        int blk = i / (1280 * 32), rem = i - blk * (1280 * 32);
        int k = rem >> 5, rowl = rem & 31;
        int g = rowl >> 3, hh = rowl & 7;
        int R = g * WORD_H + blk * 8 + hh;
        g_Ww0[i] = (k < 256) ? w0Wih[(size_t)R * 768 + 512 + k]
                             : w0Whh[(size_t)R * 1024 + (k - 256)];
        return;
    }
    i -= Bq;
    if (i < Cq) {
        int blk = i / (2048 * 32), rem = i - blk * (2048 * 32);
        int k = rem >> 5, rowl = rem & 31;
        int g = rowl >> 3, hh = rowl & 7;
        int R = g * WORD_H + blk * 8 + hh;
        g_Ww1[i] = (k < 1024) ? w1Wih[(size_t)R * 1024 + k]
                              : w1Whh[(size_t)R * 1024 + (k - 1024)];
        return;
    }
    i -= Cq;
    if (i < 4 * POS_H) { g_bpos[i] = pbih[i] + pbhh[i]; return; }
    i -= 4 * POS_H;
    if (i < 4 * WORD_H) { g_bw0[i] = w0bih[i] + w0bhh[i]; return; }
    i -= 4 * WORD_H;
    if (i < 4 * WORD_H) { g_bw1[i] = w1bih[i] + w1bhh[i]; }
}

// ---------------------------------------------------------------------------
// Persistent recurrence kernel (byte-identical to the proven 8,980us version)
// ---------------------------------------------------------------------------
constexpr int REC_THREADS = 512;
constexpr int REC_SMEM = (2 * 256 * 32 + 2 * 256 * 32 + 16 * 32 * 32) * 4;  // 196608

__device__ __forceinline__ void grid_barrier(unsigned target) {
    __syncthreads();
    if (threadIdx.x == 0) {
        __threadfence();
        atomicAdd(&g_bar_ctr, 1u);
        while (*(volatile unsigned*)&g_bar_ctr < target) __nanosleep(64);
        __threadfence();
    }
    __syncthreads();
}

template <int K>
__device__ __forceinline__ void cell_word(
    float (*xs)[256][32], float (*ws)[256][32], float (*red)[32][32],
    const float* __restrict__ Wblk, const float* __restrict__ bcomb,
    const float* __restrict__ preT, int tok0,
    const float* __restrict__ x1, int K1, const float* __restrict__ x2,
    const float* __restrict__ cin, float* __restrict__ cout,
    float* __restrict__ hcol) {
    constexpr int NC = K / 256;
    const int tid = threadIdx.x;
    const int w = tid >> 5, lane = tid & 31;
    const int rowg = lane >> 2;
    const int bg = lane & 3;

    const int hh = tid >> 5, gb = tid & 31;
    const int habs_g = blockIdx.x * 8 + hh;
    float cin_v = 0.f, bb[4], pre_g[4];
    if (tid < 256) {
        cin_v = cin[habs_g * 32 + gb];
#pragma unroll
        for (int g = 0; g < 4; g++) {
            bb[g] = bcomb[g * WORD_H + habs_g];
            pre_g[g] = preT ? preT[(size_t)(g * WORD_H + habs_g) * NTOK + tok0 + gb] : 0.f;
        }
    }

    ull acc[4][4];
#pragma unroll
    for (int r = 0; r < 4; r++)
#pragma unroll
        for (int j = 0; j < 4; j++) acc[r][j] = 0ull;

    float4 px[4], pw[4];
#pragma unroll
    for (int it = 0; it < 4; it++) {
        int f = tid + it * REC_THREADS;
        px[it] = *(const float4*)(x1 + (size_t)(f >> 3) * NTOKP + (f & 7) * 4);
        pw[it] = *(const float4*)(Wblk + (size_t)(f >> 3) * 32 + (f & 7) * 4);
    }
#pragma unroll
    for (int it = 0; it < 4; it++) {
        int f = tid + it * REC_THREADS;
        *(float4*)&xs[0][f >> 3][(f & 7) * 4] = px[it];
        *(float4*)&ws[0][f >> 3][(f & 7) * 4] = pw[it];
    }
    __syncthreads();

    for (int c = 0; c < NC; c++) {
        const int cur = c & 1, nxt = cur ^ 1;
        if (c + 1 < NC) {
            int kb = (c + 1) * 256;
            const float* xsrc = (kb < K1) ? x1 + (size_t)kb * NTOKP
                                          : x2 + (size_t)(kb - K1) * NTOKP;
            const float* wsrc = Wblk + (size_t)kb * 32;
#pragma unroll
            for (int it = 0; it < 4; it++) {
                int f = tid + it * REC_THREADS;
                px[it] = *(const float4*)(xsrc + (size_t)(f >> 3) * NTOKP + (f & 7) * 4);
                pw[it] = *(const float4*)(wsrc + (size_t)(f >> 3) * 32 + (f & 7) * 4);
            }
        }
#pragma unroll
        for (int kk = 0; kk < 16; kk++) {
            int k = w * 16 + kk;
            const ulonglong2* xp = (const ulonglong2*)&xs[cur][k][bg * 8];
            ulonglong2 xv0 = xp[0], xv1 = xp[1];
            float4 wv = *(const float4*)&ws[cur][k][rowg * 4];
            ull wd0 = dup2(wv.x), wd1 = dup2(wv.y), wd2 = dup2(wv.z), wd3 = dup2(wv.w);
            fma2(acc[0][0], wd0, xv0.x); fma2(acc[0][1], wd0, xv0.y);
            fma2(acc[0][2], wd0, xv1.x); fma2(acc[0][3], wd0, xv1.y);
            fma2(acc[1][0], wd1, xv0.x); fma2(acc[1][1], wd1, xv0.y);
            fma2(acc[1][2], wd1, xv1.x); fma2(acc[1][3], wd1, xv1.y);
            fma2(acc[2][0], wd2, xv0.x); fma2(acc[2][1], wd2, xv0.y);
            fma2(acc[2][2], wd2, xv1.x); fma2(acc[2][3], wd2, xv1.y);
            fma2(acc[3][0], wd3, xv0.x); fma2(acc[3][1], wd3, xv0.y);
            fma2(acc[3][2], wd3, xv1.x); fma2(acc[3][3], wd3, xv1.y);
        }
        if (c + 1 < NC) {
#pragma unroll
            for (int it = 0; it < 4; it++) {
                int f = tid + it * REC_THREADS;
                *(float4*)&xs[nxt][f >> 3][(f & 7) * 4] = px[it];
                *(float4*)&ws[nxt][f >> 3][(f & 7) * 4] = pw[it];
            }
        }
        __syncthreads();
    }
#pragma unroll
    for (int r = 0; r < 4; r++) {
        int row = rowg * 4 + r;
#pragma unroll
        for (int j = 0; j < 4; j += 2) {
            float a0, a1, a2, a3;
            unpack2(acc[r][j], a0, a1);
            unpack2(acc[r][j + 1], a2, a3);
            *(float4*)&red[w][row][bg * 8 + j * 2] = make_float4(a0, a1, a2, a3);
        }
    }
    __syncthreads();
    if (tid < 256) {
        float gs[4];
#pragma unroll
        for (int g = 0; g < 4; g++) {
            float s = bb[g] + pre_g[g];
#pragma unroll
            for (int ww = 0; ww < 16; ww++) s += red[ww][g * 8 + hh][gb];
            gs[g] = s;
        }
        float i = sigm(gs[0]), f = sigm(gs[1]), g = tanhf(gs[2]), o = sigm(gs[3]);
        float c2 = f * cin_v + i * g;
        float h2 = o * tanhf(c2);
        cout[habs_g * 32 + gb] = c2;
        hcol[(size_t)habs_g * NTOKP + gb] = h2;
    }
}

__device__ __forceinline__ void cell_pos(
    float (*xs)[256][32], float (*ws)[256][32], float (*red)[32][32],
    const float* __restrict__ Wblk, const float* __restrict__ bcomb,
    const float* __restrict__ preT, int tok0,
    const float* __restrict__ x1, const float* __restrict__ x2,
    const float* __restrict__ cin, float* __restrict__ cout,
    float* __restrict__ hcol) {
    constexpr int K = 1280, NC = K / 256, K1 = 1024;
    const int tid = threadIdx.x;
    const int ksl = tid >> 6;
    const int sub = tid & 63;
    const int rowl = sub >> 3;
    const int bg = sub & 7;

    const int hh = tid >> 5, gb = tid & 31;
    const int habs_g = blockIdx.x * 2 + hh;
    float cin_v = 0.f, bb[4], pre_g[4];
    if (tid < 64) {
        cin_v = cin[habs_g * 32 + gb];
#pragma unroll
        for (int g = 0; g < 4; g++) {
            bb[g] = bcomb[g * POS_H + habs_g];
            pre_g[g] = preT[(size_t)(g * POS_H + habs_g) * NTOK + tok0 + gb];
        }
    }

    ull acc0 = 0ull, acc1 = 0ull;
    float4 px[4], pw;
#pragma unroll
    for (int it = 0; it < 4; it++) {
        int f = tid + it * REC_THREADS;
        px[it] = *(const float4*)(x1 + (size_t)(f >> 3) * NTOKP + (f & 7) * 4);
    }
    pw = *(const float4*)(Wblk + (size_t)(tid >> 1) * 8 + (tid & 1) * 4);
#pragma unroll
    for (int it = 0; it < 4; it++) {
        int f = tid + it * REC_THREADS;
        *(float4*)&xs[0][f >> 3][(f & 7) * 4] = px[it];
    }
    *(float4*)&ws[0][tid >> 1][(tid & 1) * 4] = pw;
    __syncthreads();

    for (int c = 0; c < NC; c++) {
        const int cur = c & 1, nxt = cur ^ 1;
        if (c + 1 < NC) {
            int kb = (c + 1) * 256;
            const float* xsrc = (kb < K1) ? x1 + (size_t)kb * NTOKP
                                          : x2 + (size_t)(kb - K1) * NTOKP;
#pragma unroll
            for (int it = 0; it < 4; it++) {
                int f = tid + it * REC_THREADS;
                px[it] = *(const float4*)(xsrc + (size_t)(f >> 3) * NTOKP + (f & 7) * 4);
            }
            pw = *(const float4*)(Wblk + (size_t)(kb + (tid >> 1)) * 8 + (tid & 1) * 4);
        }
#pragma unroll
        for (int kk = 0; kk < 32; kk++) {
            int k = ksl * 32 + kk;
            ulonglong2 xv = *(const ulonglong2*)&xs[cur][k][bg * 4];
            ull wd = dup2(ws[cur][k][rowl]);
            fma2(acc0, wd, xv.x);
            fma2(acc1, wd, xv.y);
        }
        if (c + 1 < NC) {
#pragma unroll
            for (int it = 0; it < 4; it++) {
                int f = tid + it * REC_THREADS;
                *(float4*)&xs[nxt][f >> 3][(f & 7) * 4] = px[it];
            }
            *(float4*)&ws[nxt][tid >> 1][(tid & 1) * 4] = pw;
        }
        __syncthreads();
    }
    {
        float a0, a1, a2, a3;
        unpack2(acc0, a0, a1);
        unpack2(acc1, a2, a3);
        *(float4*)&red[ksl][rowl][bg * 4] = make_float4(a0, a1, a2, a3);
    }
    __syncthreads();
    if (tid < 64) {
        float gs[4];
#pragma unroll
        for (int g = 0; g < 4; g++) {
            float s = bb[g] + pre_g[g];
#pragma unroll
            for (int s8 = 0; s8 < 8; s8++) s += red[s8][g * 2 + hh][gb];
            gs[g] = s;
        }
        float i = sigm(gs[0]), f = sigm(gs[1]), g = tanhf(gs[2]), o = sigm(gs[3]);
        float c2 = f * cin_v + i * g;
        float h2 = o * tanhf(c2);
        cout[habs_g * 32 + gb] = c2;
        hcol[(size_t)habs_g * NTOKP + gb] = h2;
    }
}

__global__ __launch_bounds__(REC_THREADS, 1) void recurrence_kernel() {
    extern __shared__ float smem[];
    float (*xs)[256][32] = (float(*)[256][32])smem;
    float (*ws)[256][32] = (float(*)[256][32])(smem + 2 * 256 * 32);
    float (*red)[32][32] = (float(*)[32][32])(smem + 4 * 256 * 32);
    unsigned ep = 0;
    const unsigned NB = gridDim.x;
    const int blk = blockIdx.x;
    const float* WposB = g_Wpos + (size_t)blk * 1280 * 8;
    const float* Ww0B  = g_Ww0 + (size_t)blk * 1280 * 32;
    const float* Ww1B  = g_Ww1 + (size_t)blk * 2048 * 32;
    for (int t = 0; t < TT; t++) {
        const int p = t & 1, q = p ^ 1;
        const int tok0 = t * BB;
        cell_pos(xs, ws, red, WposB, g_bpos, g_preT_p, tok0,
                 g_woutsT + (size_t)t * 32, g_poutsT + (size_t)t * 32,
                 g_Cpos[p], g_Cpos[q], g_poutsT + (size_t)(t + 1) * 32);
        grid_barrier(++ep * NB);
        cell_word<1280>(xs, ws, red, Ww0B, g_bw0, g_preT_w0, tok0,
                        g_poutsT + (size_t)(t + 1) * 32, 256,
                        g_wh0T + (size_t)t * 32,
                        g_Cw0[p], g_Cw0[q], g_wh0T + (size_t)(t + 1) * 32);
        grid_barrier(++ep * NB);
        cell_word<2048>(xs, ws, red, Ww1B, g_bw1, nullptr, tok0,
                        g_wh0T + (size_t)(t + 1) * 32, 1024,
                        g_woutsT + (size_t)t * 32,
                        g_Cw1[p], g_Cw1[q], g_woutsT + (size_t)(t + 1) * 32);
        grid_barrier(++ep * NB);
    }
}

// ---------------------------------------------------------------------------
// f32x2 GEMM (R7 static-smem version): C[m,n] = sum_k AT[k,m]*W[n,k] + bias[n]
// ---------------------------------------------------------------------------
__global__ __launch_bounds__(256, 2) void gemm_t_kernel(
    const float* __restrict__ AT, int M, int lda,
    const float* __restrict__ W, int ldw, const float* __restrict__ bias,
    float* __restrict__ C, float* __restrict__ CT, int N, int K) {
    __shared__ float As[32][128];
    __shared__ float Ws[32][132];
    const int tid = threadIdx.x;
    const int rt = tid & 15;
    const int ct = tid >> 4;
    const int rBase = blockIdx.y * 128, cBase = blockIdx.x * 128;

    ull acc[8][4];
#pragma unroll
    for (int jj = 0; jj < 8; jj++)
#pragma unroll
        for (int p = 0; p < 4; p++) acc[jj][p] = 0ull;

    for (int kb = 0; kb < K; kb += 32) {
#pragma unroll
        for (int it = 0; it < 4; it++) {
            int flat = tid + it * 256;
            int k = flat >> 5, m4 = flat & 31;
            float4 v = *(const float4*)&AT[(size_t)(kb + k) * lda + rBase + m4 * 4];
            *(float4*)&As[k][m4 * 4] = v;
        }
#pragma unroll
        for (int it = 0; it < 4; it++) {
            int flat = tid + it * 256;
            int n = flat >> 3, k4 = flat & 7;
            float4 v = *(const float4*)&W[(size_t)(cBase + n) * ldw + kb + k4 * 4];
            Ws[k4 * 4 + 0][n] = v.x;
            Ws[k4 * 4 + 1][n] = v.y;
            Ws[k4 * 4 + 2][n] = v.z;
            Ws[k4 * 4 + 3][n] = v.w;
        }
        __syncthreads();
#pragma unroll
        for (int k = 0; k < 32; k++) {
            ull xd[8];
#pragma unroll
            for (int jj = 0; jj < 8; jj++) xd[jj] = dup2(As[k][rt + 16 * jj]);
            const ulonglong2* wpp = (const ulonglong2*)&Ws[k][ct * 8];
            ulonglong2 wa = wpp[0];
            ulonglong2 wb = wpp[1];
#pragma unroll
            for (int jj = 0; jj < 8; jj++) {
                fma2(acc[jj][0], xd[jj], wa.x);
                fma2(acc[jj][1], xd[jj], wa.y);
                fma2(acc[jj][2], xd[jj], wb.x);
                fma2(acc[jj][3], xd[jj], wb.y);
            }
        }
        __syncthreads();
    }
    float bcol[8];
#pragma unroll
    for (int qq = 0; qq < 8; qq++) bcol[qq] = bias ? bias[cBase + ct * 8 + qq] : 0.f;
#pragma unroll
    for (int jj = 0; jj < 8; jj++) {
        int m = rBase + rt + 16 * jj;
        float v[8];
#pragma unroll
        for (int p = 0; p < 4; p++) unpack2(acc[jj][p], v[2 * p], v[2 * p + 1]);
#pragma unroll
        for (int qq = 0; qq < 8; qq++) v[qq] += bcol[qq];
        if (C) {
            float4* dst = (float4*)&C[(size_t)m * N + cBase + ct * 8];
            dst[0] = make_float4(v[0], v[1], v[2], v[3]);
            dst[1] = make_float4(v[4], v[5], v[6], v[7]);
        }
        if (CT) {
#pragma unroll
            for (int qq = 0; qq < 8; qq++)
                CT[(size_t)(cBase + ct * 8 + qq) * M + m] = v[qq];
        }
    }
}

// ---------------------------------------------------------------------------
// Warp-MMA bf16 head GEMM: logits[m,n] = sum_k wmid_bf[m,k]*emb_bf[n,k] + b[n]
//   mma.sync.m16n8k16.row.col.f32.bf16.bf16.f32 (baseline ISA, no tcgen05).
//   Block 256 thr = 8 warps (4M x 2N), tile 128x128, warp tile 32x64,
//   K=512 in 16 chunks of 32, double-buffered smem, reg-prefetch staging.
//   smem rows stride 40 bf16 -> conflict-free fragment LDS.
// ---------------------------------------------------------------------------
__device__ __forceinline__ void mma_bf16(float& c0, float& c1, float& c2, float& c3,
                                         unsigned a0, unsigned a1, unsigned a2, unsigned a3,
                                         unsigned b0, unsigned b1) {
    asm volatile("mma.sync.aligned.m16n8k16.row.col.f32.bf16.bf16.f32 "
                 "{%0,%1,%2,%3}, {%4,%5,%6,%7}, {%8,%9}, {%0,%1,%2,%3};"
                 : "+f"(c0), "+f"(c1), "+f"(c2), "+f"(c3)
                 : "r"(a0), "r"(a1), "r"(a2), "r"(a3), "r"(b0), "r"(b1));
}

__global__ __launch_bounds__(256, 1) void head_mma_kernel(
    const float* __restrict__ wp2b, float* __restrict__ outp) {
    __shared__ __nv_bfloat16 As[2][128][40];
    __shared__ __nv_bfloat16 Bs[2][128][40];
    const int tid = threadIdx.x;
    const int wid = tid >> 5, lane = tid & 31;
    const int wm = wid & 3;   // M warp: rows wm*32..+31
    const int wn = wid >> 2;  // N warp: cols wn*64..+63
    const int rBase = blockIdx.y * 128, cBase = blockIdx.x * 128;
    const int gid = lane >> 2, tig = lane & 3;

    float acc[2][8][4];
#pragma unroll
    for (int mt = 0; mt < 2; mt++)
#pragma unroll
        for (int nt = 0; nt < 8; nt++)
#pragma unroll
            for (int q = 0; q < 4; q++) acc[mt][nt][q] = 0.f;

    // staging coords: flat = tid + it*256 -> row = flat>>2, group g = flat&3
    const int sr0 = tid >> 2, sg = tid & 3;

    uint4 pa[2], pb[2];
#pragma unroll
    for (int it = 0; it < 2; it++) {
        int r = sr0 + it * 64;
        pa[it] = *(const uint4*)(g_wmid_bf + (size_t)(rBase + r) * WORD_E + sg * 8);
        pb[it] = *(const uint4*)(g_emb_bf + (size_t)(cBase + r) * WORD_E + sg * 8);
    }
#pragma unroll
    for (int it = 0; it < 2; it++) {
        int r = sr0 + it * 64;
        *(uint4*)&As[0][r][sg * 8] = pa[it];
        *(uint4*)&Bs[0][r][sg * 8] = pb[it];
    }
    __syncthreads();

    const int NCHUNK = WORD_E / 32;  // 16
    for (int c = 0; c < NCHUNK; c++) {
        const int cur = c & 1, nxt = cur ^ 1;
        if (c + 1 < NCHUNK) {
            int kb = (c + 1) * 32;
#pragma unroll
            for (int it = 0; it < 2; it++) {
                int r = sr0 + it * 64;
                pa[it] = *(const uint4*)(g_wmid_bf + (size_t)(rBase + r) * WORD_E + kb + sg * 8);
                pb[it] = *(const uint4*)(g_emb_bf + (size_t)(cBase + r) * WORD_E + kb + sg * 8);
            }
        }
#pragma unroll
        for (int ks = 0; ks < 32; ks += 16) {
            const int k0 = ks + tig * 2;
            unsigned b[8][2];
#pragma unroll
            for (int nt = 0; nt < 8; nt++) {
                int n0 = wn * 64 + nt * 8 + gid;
                b[nt][0] = *(const unsigned*)&Bs[cur][n0][k0];
                b[nt][1] = *(const unsigned*)&Bs[cur][n0][k0 + 8];
            }
#pragma unroll
            for (int mt = 0; mt < 2; mt++) {
                int r0 = wm * 32 + mt * 16 + gid;
                unsigned a0 = *(const unsigned*)&As[cur][r0][k0];
                unsigned a1 = *(const unsigned*)&As[cur][r0 + 8][k0];
                unsigned a2 = *(const unsigned*)&As[cur][r0][k0 + 8];
                unsigned a3 = *(const unsigned*)&As[cur][r0 + 8][k0 + 8];
#pragma unroll
                for (int nt = 0; nt < 8; nt++)
                    mma_bf16(acc[mt][nt][0], acc[mt][nt][1], acc[mt][nt][2], acc[mt][nt][3],
                             a0, a1, a2, a3, b[nt][0], b[nt][1]);
            }
        }
        if (c + 1 < NCHUNK) {
#pragma unroll
            for (int it = 0; it < 2; it++) {
                int r = sr0 + it * 64;
                *(uint4*)&As[nxt][r][sg * 8] = pa[it];
                *(uint4*)&Bs[nxt][r][sg * 8] = pb[it];
            }
        }
        __syncthreads();
    }

    // epilogue: add bias, write logits
#pragma unroll
    for (int nt = 0; nt < 8; nt++) {
        int col = cBase + wn * 64 + nt * 8 + tig * 2;
        float2 bv = *(const float2*)(wp2b + col);
#pragma unroll
        for (int mt = 0; mt < 2; mt++) {
            int row = rBase + wm * 32 + mt * 16 + gid;
            float2 v0 = make_float2(acc[mt][nt][0] + bv.x, acc[mt][nt][1] + bv.y);
            float2 v1 = make_float2(acc[mt][nt][2] + bv.x, acc[mt][nt][3] + bv.y);
            *(float2*)(outp + (size_t)row * WORD_V + col) = v0;
            *(float2*)(outp + (size_t)(row + 8) * WORD_V + col) = v1;
        }
    }
}

// ---------------------------------------------------------------------------
// pos projection + log-softmax (one block per timestep)
// ---------------------------------------------------------------------------
__global__ void pos_projT_kernel(const float* __restrict__ Wp, const float* __restrict__ bp,
                                 float* __restrict__ out) {
    __shared__ float xs[POS_H][32];
    __shared__ float lg[POS_V][33];
    __shared__ float lsb[32];
    const int t = blockIdx.x;
    const int tok0 = t * 32;
    const int tid = threadIdx.x;
    const int b = tid & 31, vg = tid >> 5;
    for (int i = tid; i < POS_H * 32; i += 256) {
        int k = i >> 5, bb = i & 31;
        xs[k][bb] = g_poutsT[(size_t)k * NTOKP + 32 + tok0 + bb];
    }
    __syncthreads();
    for (int v = vg; v < POS_V; v += 8) {
        float s = bp[v];
        const float* wv = Wp + (size_t)v * POS_H;
        for (int k = 0; k < POS_H; k++) s = fmaf(xs[k][b], wv[k], s);
        lg[v][b] = s;
    }
    __syncthreads();
    if (tid < 32) {
        float m = -INFINITY;
        for (int v = 0; v < POS_V; v++) m = fmaxf(m, lg[v][tid]);
        float e = 0.f;
        for (int v = 0; v < POS_V; v++) e += expf(lg[v][tid] - m);
        lsb[tid] = m + logf(e);
    }
    __syncthreads();
    float ls = lsb[b];
    for (int v = vg; v < POS_V; v += 8)
        out[(size_t)(tok0 + b) * POS_V + v] = lg[v][b] - ls;
}

// ---------------------------------------------------------------------------
// word log-softmax in place over 32000 (one block per row, float4)
// ---------------------------------------------------------------------------
__global__ void word_softmax_kernel(float* __restrict__ logits) {
    __shared__ float red[8];
    const int row = blockIdx.x;
    float4* p4 = (float4*)(logits + (size_t)row * WORD_V);
    const int NV4 = WORD_V / 4;
    const int tid = threadIdx.x;
    float m = -INFINITY;
    for (int i = tid; i < NV4; i += 256) {
        float4 v = p4[i];
        m = fmaxf(m, fmaxf(fmaxf(v.x, v.y), fmaxf(v.z, v.w)));
    }
#pragma unroll
    for (int o = 16; o; o >>= 1) m = fmaxf(m, __shfl_xor_sync(0xffffffffu, m, o));
    if ((tid & 31) == 0) red[tid >> 5] = m;
    __syncthreads();
    float M = red[0];
#pragma unroll
    for (int w = 1; w < 8; w++) M = fmaxf(M, red[w]);
    __syncthreads();
    float s = 0.f;
    for (int i = tid; i < NV4; i += 256) {
        float4 v = p4[i];
        s += expf(v.x - M) + expf(v.y - M) + expf(v.z - M) + expf(v.w - M);
    }
#pragma unroll
    for (int o = 16; o; o >>= 1) s += __shfl_xor_sync(0xffffffffu, s, o);
    if ((tid & 31) == 0) red[tid >> 5] = s;
    __syncthreads();
    float S = 0.f;
#pragma unroll
    for (int w = 0; w < 8; w++) S += red[w];
    float ls = M + logf(S);
    for (int i = tid; i < NV4; i += 256) {
        float4 v = p4[i];
        v.x -= ls; v.y -= ls; v.z -= ls; v.w -= ls;
        p4[i] = v;
    }
}

// ---------------------------------------------------------------------------
// Host side
// ---------------------------------------------------------------------------
extern "C" void kernel_launch(void* const* d_in, const int* in_sizes, int n_in,
                              void* d_out, int out_size) {
    (void)in_sizes; (void)n_in; (void)out_size;
    const int*   pos        = (const int*)d_in[0];
    const int*   word       = (const int*)d_in[1];
    const float* pos_emb_W  = (const float*)d_in[2];
    const float* word_emb_W = (const float*)d_in[3];
    const float* pos_Wih    = (const float*)d_in[4];
    const float* pos_Whh    = (const float*)d_in[5];
    const float* pos_bih    = (const float*)d_in[6];
    const float* pos_bhh    = (const float*)d_in[7];
    const float* w0_Wih     = (const float*)d_in[8];
    const float* w0_Whh     = (const float*)d_in[9];
    const float* w0_bih     = (const float*)d_in[10];
    const float* w0_bhh     = (const float*)d_in[11];
    const float* w1_Wih     = (const float*)d_in[12];
    const float* w1_Whh     = (const float*)d_in[13];
    const float* w1_bih     = (const float*)d_in[14];
    const float* w1_bhh     = (const float*)d_in[15];
    const float* pos_proj_W = (const float*)d_in[16];
    const float* pos_proj_b = (const float*)d_in[17];
    const float* wp1_W      = (const float*)d_in[18];
    const float* wp1_b      = (const float*)d_in[19];
    const float* wp2_b      = (const float*)d_in[20];
    float* out = (float*)d_out;

    float *p_embT, *w_embT, *woutsT, *wmid, *preT_p, *preT_w0;
    cudaGetSymbolAddress((void**)&p_embT, g_p_embT);
    cudaGetSymbolAddress((void**)&w_embT, g_w_embT);
    cudaGetSymbolAddress((void**)&woutsT, g_woutsT);
    cudaGetSymbolAddress((void**)&wmid, g_wmid);
    cudaGetSymbolAddress((void**)&preT_p, g_preT_p);
    cudaGetSymbolAddress((void**)&preT_w0, g_preT_w0);

    static bool attr_done = false;
    if (!attr_done) {
        cudaFuncSetAttribute(recurrence_kernel,
                             cudaFuncAttributeMaxDynamicSharedMemorySize, REC_SMEM);
        attr_done = true;
    }

    zero_init_kernel<<<(WORD_H * BB + 255) / 256, 256>>>();
    gather_kernel<<<(WORD_E * NTOK + 255) / 256, 256>>>(pos, word, pos_emb_W, word_emb_W);
    cvt_emb_kernel<<<(WORD_V * WORD_E / 4 + 255) / 256, 256>>>(word_emb_W);

    {
        const int total = 4 * POS_H * 1280 + 4 * WORD_H * 1280 + 4 * WORD_H * 2048 +
                          4 * POS_H + 2 * (4 * WORD_H);
        repack_kernel<<<(total + 255) / 256, 256>>>(
            pos_Wih, pos_Whh, w0_Wih, w0_Whh, w1_Wih, w1_Whh,
            pos_bih, pos_bhh, w0_bih, w0_bhh, w1_bih, w1_bhh);
    }

    // precompute emb @ Wih_emb-part for all timesteps (transposed outputs)
    gemm_t_kernel<<<dim3(4 * POS_H / 128, NTOK / 128), 256>>>(
        p_embT, NTOK, NTOK, pos_Wih, POS_E + WORD_H, nullptr,
        nullptr, preT_p, 4 * POS_H, POS_E);
    gemm_t_kernel<<<dim3(4 * WORD_H / 128, NTOK / 128), 256>>>(
        w_embT, NTOK, NTOK, w0_Wih, WORD_E + POS_H, nullptr,
        nullptr, preT_w0, 4 * WORD_H, WORD_E);

    // the whole 128-step recurrence in ONE persistent kernel
    recurrence_kernel<<<128, REC_THREADS, REC_SMEM>>>();

    // pos projection + log-softmax
    pos_projT_kernel<<<TT, 256>>>(pos_proj_W, pos_proj_b, out);

    // word head: wp1 (fp32) -> wmid row-major -> bf16 -> warp-MMA big GEMM
    gemm_t_kernel<<<dim3(WORD_E / 128, NTOK / 128), 256>>>(
        woutsT + 32, NTOK, NTOKP, wp1_W, WORD_H, wp1_b,
        wmid, nullptr, WORD_E, WORD_H);
    cvt_wmid_kernel<<<(NTOK * WORD_E / 4 + 255) / 256, 256>>>();

    float* wlp = out + (size_t)NTOK * POS_V;
    head_mma_kernel<<<dim3(WORD_V / 128, NTOK / 128), 256>>>(wp2_b, wlp);
    word_softmax_kernel<<<NTOK, 256>>>(wlp);
}

// round 13
// speedup vs baseline: 3.0523x; 1.4734x over previous
#include <cuda_runtime.h>
#include <cuda_bf16.h>
#include <stdint.h>
#include <math.h>

typedef unsigned long long ull;

// ---------------------------------------------------------------------------
// Problem constants
// ---------------------------------------------------------------------------
namespace {
constexpr int TT = 128, BB = 32;
constexpr int POS_E = 64, WORD_E = 512, POS_H = 256, WORD_H = 1024;
constexpr int POS_V = 45, WORD_V = 32000;
constexpr int NTOK = TT * BB;      // 4096
constexpr int NTOKP = NTOK + 32;
constexpr int NROWS = (TT + 1) * 32;  // 4128 token rows (slot 0 = zeros)

// ---------------------------------------------------------------------------
// Device scratch
// ---------------------------------------------------------------------------
__device__ float g_p_embT[POS_E * NTOK];
__device__ float g_w_embT[WORD_E * NTOK];
__device__ float g_poutsT[POS_H * NTOKP];            // fp32 [H][NTOKP] (pos proj)
__device__ float g_woutsT[WORD_H * NTOKP];           // fp32 (wp1 GEMM)
__device__ float g_wmid[NTOK * WORD_E];
__device__ __align__(16) __nv_bfloat16 g_wmid_bf[NTOK * WORD_E];
__device__ __align__(16) __nv_bfloat16 g_emb_bf[WORD_V * WORD_E];
__device__ float g_preT_p[4 * POS_H * NTOK];
__device__ float g_preT_w0[4 * WORD_H * NTOK];
// bf16 hi/lo h histories, row-major [token_row][dim], slot t+1 rows (t+1)*32..
__device__ __align__(16) __nv_bfloat16 g_pob_h[NROWS * POS_H];
__device__ __align__(16) __nv_bfloat16 g_pob_l[NROWS * POS_H];
__device__ __align__(16) __nv_bfloat16 g_w0b_h[NROWS * WORD_H];
__device__ __align__(16) __nv_bfloat16 g_w0b_l[NROWS * WORD_H];
__device__ __align__(16) __nv_bfloat16 g_w1b_h[NROWS * WORD_H];
__device__ __align__(16) __nv_bfloat16 g_w1b_l[NROWS * WORD_H];
// fragment-linear packed bf16 hi/lo weights (uint32 = 2 bf16 along k)
constexpr int POS_U32_BLK = 5 * 16 * 2 * 32 * 4;     // 20480
constexpr int W0_U32_BLK  = 5 * 16 * 4 * 32 * 4;     // 40960
constexpr int W1_U32_BLK  = 8 * 16 * 4 * 32 * 4;     // 65536
__device__ __align__(16) unsigned g_WposP[128 * POS_U32_BLK];
__device__ __align__(16) unsigned g_Ww0P[128 * W0_U32_BLK];
__device__ __align__(16) unsigned g_Ww1P[128 * W1_U32_BLK];
__device__ float g_bpos[4 * POS_H], g_bw0[4 * WORD_H], g_bw1[4 * WORD_H];
__device__ float g_Cpos[2][POS_H * BB];
__device__ float g_Cw0[2][WORD_H * BB];
__device__ float g_Cw1[2][WORD_H * BB];
__device__ unsigned g_bar_ctr;
}  // namespace

// ---------------------------------------------------------------------------
// helpers
// ---------------------------------------------------------------------------
__device__ __forceinline__ ull pack2(float lo, float hi) {
    ull r; asm("mov.b64 %0, {%1,%2};" : "=l"(r) : "f"(lo), "f"(hi)); return r;
}
__device__ __forceinline__ ull dup2(float v) { return pack2(v, v); }
__device__ __forceinline__ void fma2(ull& d, ull a, ull b) {
    asm("fma.rn.f32x2 %0, %1, %2, %0;" : "+l"(d) : "l"(a), "l"(b));
}
__device__ __forceinline__ void unpack2(ull v, float& lo, float& hi) {
    asm("mov.b64 {%0,%1}, %2;" : "=f"(lo), "=f"(hi) : "l"(v));
}
__device__ __forceinline__ float sigm(float x) { return 1.f / (1.f + expf(-x)); }

__device__ __forceinline__ void mma_bf16(float& c0, float& c1, float& c2, float& c3,
                                         unsigned a0, unsigned a1, unsigned a2, unsigned a3,
                                         unsigned b0, unsigned b1) {
    asm volatile("mma.sync.aligned.m16n8k16.row.col.f32.bf16.bf16.f32 "
                 "{%0,%1,%2,%3}, {%4,%5,%6,%7}, {%8,%9}, {%0,%1,%2,%3};"
                 : "+f"(c0), "+f"(c1), "+f"(c2), "+f"(c3)
                 : "r"(a0), "r"(a1), "r"(a2), "r"(a3), "r"(b0), "r"(b1));
}

// ---------------------------------------------------------------------------
// Init / gather / conversions
// ---------------------------------------------------------------------------
__global__ void zero_init_kernel() {
    int i = blockIdx.x * blockDim.x + threadIdx.x;
    if (i < 32 * POS_H) {
        ((unsigned short*)g_pob_h)[i] = 0;
        ((unsigned short*)g_pob_l)[i] = 0;
        g_Cpos[0][i] = 0.f;
    }
    if (i < 32 * WORD_H) {
        ((unsigned short*)g_w0b_h)[i] = 0;
        ((unsigned short*)g_w0b_l)[i] = 0;
        ((unsigned short*)g_w1b_h)[i] = 0;
        ((unsigned short*)g_w1b_l)[i] = 0;
        g_Cw0[0][i] = 0.f;
        g_Cw1[0][i] = 0.f;
    }
    if (i == 0) g_bar_ctr = 0u;
}

__global__ void gather_kernel(const int* __restrict__ pos, const int* __restrict__ word,
                              const float* __restrict__ posW, const float* __restrict__ wordW) {
    int j = blockIdx.x * blockDim.x + threadIdx.x;
    if (j < WORD_E * NTOK) {
        int d = j / NTOK, tok = j - d * NTOK;
        g_w_embT[j] = wordW[(size_t)word[tok] * WORD_E + d];
    }
    if (j < POS_E * NTOK) {
        int d = j / NTOK, tok = j - d * NTOK;
        g_p_embT[j] = posW[(size_t)pos[tok] * POS_E + d];
    }
}

__global__ void cvt_emb_kernel(const float* __restrict__ src) {
    size_t i = ((size_t)blockIdx.x * blockDim.x + threadIdx.x) * 4;
    if (i < (size_t)WORD_V * WORD_E) {
        float4 v = *(const float4*)(src + i);
        *(__nv_bfloat162*)&g_emb_bf[i] = __floats2bfloat162_rn(v.x, v.y);
        *(__nv_bfloat162*)&g_emb_bf[i + 2] = __floats2bfloat162_rn(v.z, v.w);
    }
}

__global__ void cvt_wmid_kernel() {
    size_t i = ((size_t)blockIdx.x * blockDim.x + threadIdx.x) * 4;
    if (i < (size_t)NTOK * WORD_E) {
        float4 v = *(const float4*)(g_wmid + i);
        *(__nv_bfloat162*)&g_wmid_bf[i] = __floats2bfloat162_rn(v.x, v.y);
        *(__nv_bfloat162*)&g_wmid_bf[i + 2] = __floats2bfloat162_rn(v.z, v.w);
    }
}

// ---------------------------------------------------------------------------
// Repack weights into fragment-linear bf16 hi/lo (+ combined biases).
// A-fragment (m16n8k16): reg r, lane l -> row = rt*16 + (l>>2) + (r&1)*8,
//                        k = (l&3)*2 + (r>>1)*8 (uint32 = bf16 pair k,k+1).
// ---------------------------------------------------------------------------
__device__ __forceinline__ unsigned pack_hl(float v0, float v1, int part) {
    __nv_bfloat16 h0 = __float2bfloat16(v0);
    __nv_bfloat16 h1 = __float2bfloat16(v1);
    unsigned short u0, u1;
    if (part == 0) {
        u0 = *(unsigned short*)&h0;
        u1 = *(unsigned short*)&h1;
    } else {
        __nv_bfloat16 l0 = __float2bfloat16(v0 - __bfloat162float(h0));
        __nv_bfloat16 l1 = __float2bfloat16(v1 - __bfloat162float(h1));
        u0 = *(unsigned short*)&l0;
        u1 = *(unsigned short*)&l1;
    }
    return (unsigned)u0 | ((unsigned)u1 << 16);
}

__global__ void repack_bf16_kernel(
    const float* __restrict__ pWih, const float* __restrict__ pWhh,
    const float* __restrict__ w0Wih, const float* __restrict__ w0Whh,
    const float* __restrict__ w1Wih, const float* __restrict__ w1Whh,
    const float* __restrict__ pbih, const float* __restrict__ pbhh,
    const float* __restrict__ w0bih, const float* __restrict__ w0bhh,
    const float* __restrict__ w1bih, const float* __restrict__ w1bhh) {
    long long i = (long long)blockIdx.x * blockDim.x + threadIdx.x;
    const long long P_TOT = 128LL * POS_U32_BLK;
    const long long W0_TOT = 128LL * W0_U32_BLK;
    const long long W1_TOT = 128LL * W1_U32_BLK;
    if (i < P_TOT) {  // pos: NC=5, F=2 (NRT=1), H=256, HPB=2
        int blk = (int)(i / POS_U32_BLK), e = (int)(i % POS_U32_BLK);
        int r = e & 3, lane = (e >> 2) & 31;
        int t1 = e >> 7;
        int part = t1 & 1;
        int t2 = t1 >> 1;
        int w = t2 & 15, c = t2 >> 4;
        int row_l = (lane >> 2) + (r & 1) * 8;
        int k_l = (lane & 3) * 2 + (r >> 1) * 8;
        int kg = c * 256 + w * 16 + k_l;
        float v0 = 0.f, v1 = 0.f;
        if (row_l < 8) {
            int g = row_l >> 1, hh = row_l & 1;
            int R = g * POS_H + blk * 2 + hh;
            v0 = (kg < 1024) ? pWih[(size_t)R * 1088 + 64 + kg] : pWhh[(size_t)R * 256 + kg - 1024];
            v1 = (kg + 1 < 1024) ? pWih[(size_t)R * 1088 + 64 + kg + 1]
                                 : pWhh[(size_t)R * 256 + kg + 1 - 1024];
        }
        g_WposP[i] = pack_hl(v0, v1, part);
        return;
    }
    i -= P_TOT;
    if (i < W0_TOT) {  // w0: NC=5, F=4, H=1024, HPB=8, K1=256
        int blk = (int)(i / W0_U32_BLK), e = (int)(i % W0_U32_BLK);
        int r = e & 3, lane = (e >> 2) & 31;
        int t1 = e >> 7;
        int f = t1 & 3;
        int t2 = t1 >> 2;
        int w = t2 & 15, c = t2 >> 4;
        int part = f & 1, rt = f >> 1;
        int row_l = rt * 16 + (lane >> 2) + (r & 1) * 8;
        int k_l = (lane & 3) * 2 + (r >> 1) * 8;
        int kg = c * 256 + w * 16 + k_l;
        int g = row_l >> 3, hh = row_l & 7;
        int R = g * WORD_H + blk * 8 + hh;
        float v0 = (kg < 256) ? w0Wih[(size_t)R * 768 + 512 + kg]
                              : w0Whh[(size_t)R * 1024 + kg - 256];
        float v1 = (kg + 1 < 256) ? w0Wih[(size_t)R * 768 + 512 + kg + 1]
                                  : w0Whh[(size_t)R * 1024 + kg + 1 - 256];
        g_Ww0P[i] = pack_hl(v0, v1, part);
        return;
    }
    i -= W0_TOT;
    if (i < W1_TOT) {  // w1: NC=8, F=4, K1=1024
        int blk = (int)(i / W1_U32_BLK), e = (int)(i % W1_U32_BLK);
        int r = e & 3, lane = (e >> 2) & 31;
        int t1 = e >> 7;
        int f = t1 & 3;
        int t2 = t1 >> 2;
        int w = t2 & 15, c = t2 >> 4;
        int part = f & 1, rt = f >> 1;
        int row_l = rt * 16 + (lane >> 2) + (r & 1) * 8;
        int k_l = (lane & 3) * 2 + (r >> 1) * 8;
        int kg = c * 256 + w * 16 + k_l;
        int g = row_l >> 3, hh = row_l & 7;
        int R = g * WORD_H + blk * 8 + hh;
        float v0 = (kg < 1024) ? w1Wih[(size_t)R * 1024 + kg]
                               : w1Whh[(size_t)R * 1024 + kg - 1024];
        float v1 = (kg + 1 < 1024) ? w1Wih[(size_t)R * 1024 + kg + 1]
                                   : w1Whh[(size_t)R * 1024 + kg + 1 - 1024];
        g_Ww1P[i] = pack_hl(v0, v1, part);
        return;
    }
    i -= W1_TOT;
    if (i < 4 * POS_H) { g_bpos[i] = pbih[i] + pbhh[i]; return; }
    i -= 4 * POS_H;
    if (i < 4 * WORD_H) { g_bw0[i] = w0bih[i] + w0bhh[i]; return; }
    i -= 4 * WORD_H;
    if (i < 4 * WORD_H) { g_bw1[i] = w1bih[i] + w1bhh[i]; }
}

// ---------------------------------------------------------------------------
// Persistent HMMA recurrence: 128 blocks x 512 threads.
// smem: xhi[2][32][264] bf16 | xlo[2][32][264] | red[16][32][34] f32
// ---------------------------------------------------------------------------
constexpr int REC_THREADS = 512;
constexpr int XROW = 264;             // padded row (stride 132 words == 4 mod 32)
constexpr int XBUF = 32 * XROW;       // elems per buffer
constexpr int REDW = 34;              // even stride -> aligned STS.64
constexpr int REC_SMEM = 2 * (2 * XBUF * 2) + 16 * 32 * REDW * 4;  // 137216

__device__ __forceinline__ void grid_barrier(unsigned target) {
    __syncthreads();
    if (threadIdx.x == 0) {
        __threadfence();
        atomicAdd(&g_bar_ctr, 1u);
        while (*(volatile unsigned*)&g_bar_ctr < target) __nanosleep(64);
        __threadfence();
    }
    __syncthreads();
}

// Generic split-bf16 HMMA LSTM cell. Block owns 32 (word) / 8 (pos) gate rows.
template <int NC, int NRT, int H, int HPB>
__device__ __forceinline__ void cell_mma(
    __nv_bfloat16* xhi, __nv_bfloat16* xlo, float* red,
    const uint4* __restrict__ W4, const float* __restrict__ bcomb,
    const float* __restrict__ preT, int tok0,
    const __nv_bfloat16* __restrict__ s1h, const __nv_bfloat16* __restrict__ s1l,
    int str1, int K1,
    const __nv_bfloat16* __restrict__ s2h, const __nv_bfloat16* __restrict__ s2l,
    int str2,
    const float* __restrict__ cin, float* __restrict__ cout,
    float* __restrict__ hcol32,
    __nv_bfloat16* __restrict__ hbh, __nv_bfloat16* __restrict__ hbl, int DIM) {
    constexpr int F = NRT * 2;
    const int tid = threadIdx.x;
    const int w = tid >> 5, lane = tid & 31;
    const int gid = lane >> 2, tig = lane & 3;

    // gate operand prefetch
    const int hh = tid >> 5, gb = tid & 31;
    const int habs = blockIdx.x * HPB + hh;
    float cin_v = 0.f, bbv[4], prg[4];
    if (tid < HPB * 32) {
        cin_v = cin[habs * 32 + gb];
#pragma unroll
        for (int g = 0; g < 4; g++) {
            bbv[g] = bcomb[g * H + habs];
            prg[g] = preT ? preT[(size_t)(g * H + habs) * NTOK + tok0 + gb] : 0.f;
        }
    }

    float acc[NRT][4][4];
#pragma unroll
    for (int rt = 0; rt < NRT; rt++)
#pragma unroll
        for (int nt = 0; nt < 4; nt++)
#pragma unroll
            for (int q = 0; q < 4; q++) acc[rt][nt][q] = 0.f;

    uint4 ph[2], pl[2];
    uint4 wreg[2][NRT][2];

    // prologue: x chunk 0 + weight frags chunk 0
    {
        const __nv_bfloat16* sh = s1h;  // kb=0 always < K1
        const __nv_bfloat16* sl = s1l;
#pragma unroll
        for (int it = 0; it < 2; it++) {
            int f = tid + it * REC_THREADS;
            int row = f >> 5, q = f & 31;
            ph[it] = *(const uint4*)(sh + (size_t)row * str1 + q * 8);
            pl[it] = *(const uint4*)(sl + (size_t)row * str1 + q * 8);
        }
#pragma unroll
        for (int it = 0; it < 2; it++) {
            int f = tid + it * REC_THREADS;
            int row = f >> 5, q = f & 31;
            *(uint4*)(xhi + row * XROW + q * 8) = ph[it];
            *(uint4*)(xlo + row * XROW + q * 8) = pl[it];
        }
#pragma unroll
        for (int rt = 0; rt < NRT; rt++)
#pragma unroll
            for (int p = 0; p < 2; p++)
                wreg[0][rt][p] = W4[((size_t)(0 * 16 + w) * F + rt * 2 + p) * 32 + lane];
    }
    __syncthreads();

    for (int c = 0; c < NC; c++) {
        const int cur = c & 1, nxt = cur ^ 1;
        if (c + 1 < NC) {
            int kb = (c + 1) * 256;
            const __nv_bfloat16* sh;
            const __nv_bfloat16* sl;
            int str;
            if (kb < K1) { sh = s1h + kb; sl = s1l + kb; str = str1; }
            else { sh = s2h + (kb - K1); sl = s2l + (kb - K1); str = str2; }
#pragma unroll
            for (int it = 0; it < 2; it++) {
                int f = tid + it * REC_THREADS;
                int row = f >> 5, q = f & 31;
                ph[it] = *(const uint4*)(sh + (size_t)row * str + q * 8);
                pl[it] = *(const uint4*)(sl + (size_t)row * str + q * 8);
            }
#pragma unroll
            for (int rt = 0; rt < NRT; rt++)
#pragma unroll
                for (int p = 0; p < 2; p++)
                    wreg[nxt][rt][p] =
                        W4[((size_t)((c + 1) * 16 + w) * F + rt * 2 + p) * 32 + lane];
        }
        // compute chunk c
        {
            const __nv_bfloat16* xh = xhi + cur * XBUF;
            const __nv_bfloat16* xl = xlo + cur * XBUF;
            const int kloc = w * 16 + tig * 2;
#pragma unroll
            for (int nt = 0; nt < 4; nt++) {
                int n = nt * 8 + gid;
                unsigned bh0 = *(const unsigned*)(xh + n * XROW + kloc);
                unsigned bh1 = *(const unsigned*)(xh + n * XROW + kloc + 8);
                unsigned bl0 = *(const unsigned*)(xl + n * XROW + kloc);
                unsigned bl1 = *(const unsigned*)(xl + n * XROW + kloc + 8);
#pragma unroll
                for (int rt = 0; rt < NRT; rt++) {
                    uint4 Ah = wreg[cur][rt][0];
                    uint4 Al = wreg[cur][rt][1];
                    mma_bf16(acc[rt][nt][0], acc[rt][nt][1], acc[rt][nt][2], acc[rt][nt][3],
                             Ah.x, Ah.y, Ah.z, Ah.w, bh0, bh1);
                    mma_bf16(acc[rt][nt][0], acc[rt][nt][1], acc[rt][nt][2], acc[rt][nt][3],
                             Ah.x, Ah.y, Ah.z, Ah.w, bl0, bl1);
                    mma_bf16(acc[rt][nt][0], acc[rt][nt][1], acc[rt][nt][2], acc[rt][nt][3],
                             Al.x, Al.y, Al.z, Al.w, bh0, bh1);
                }
            }
        }
        if (c + 1 < NC) {
#pragma unroll
            for (int it = 0; it < 2; it++) {
                int f = tid + it * REC_THREADS;
                int row = f >> 5, q = f & 31;
                *(uint4*)(xhi + nxt * XBUF + row * XROW + q * 8) = ph[it];
                *(uint4*)(xlo + nxt * XBUF + row * XROW + q * 8) = pl[it];
            }
        }
        __syncthreads();
    }
    // dump k-slice partials
#pragma unroll
    for (int rt = 0; rt < NRT; rt++)
#pragma unroll
        for (int nt = 0; nt < 4; nt++) {
            int row = rt * 16 + gid, col = nt * 8 + tig * 2;
            float* rp = red + (size_t)w * 32 * REDW + row * REDW + col;
            *(float2*)rp = make_float2(acc[rt][nt][0], acc[rt][nt][1]);
            *(float2*)(rp + 8 * REDW) = make_float2(acc[rt][nt][2], acc[rt][nt][3]);
        }
    __syncthreads();
    // gate stage
    if (tid < HPB * 32) {
        float gs[4];
#pragma unroll
        for (int g = 0; g < 4; g++) {
            float s = bbv[g] + prg[g];
#pragma unroll
            for (int ww = 0; ww < 16; ww++)
                s += red[(size_t)ww * 32 * REDW + (g * HPB + hh) * REDW + gb];
            gs[g] = s;
        }
        float i = sigm(gs[0]), f = sigm(gs[1]), g = tanhf(gs[2]), o = sigm(gs[3]);
        float c2 = f * cin_v + i * g;
        float h2 = o * tanhf(c2);
        cout[habs * 32 + gb] = c2;
        if (hcol32) hcol32[(size_t)habs * NTOKP + gb] = h2;
        __nv_bfloat16 hi = __float2bfloat16(h2);
        hbh[(size_t)gb * DIM + habs] = hi;
        hbl[(size_t)gb * DIM + habs] = __float2bfloat16(h2 - __bfloat162float(hi));
    }
}

__global__ __launch_bounds__(REC_THREADS, 1) void recurrence_kernel() {
    extern __shared__ char smc[];
    __nv_bfloat16* xhi = (__nv_bfloat16*)smc;
    __nv_bfloat16* xlo = xhi + 2 * XBUF;
    float* red = (float*)(smc + 2 * (2 * XBUF * 2));
    unsigned ep = 0;
    const unsigned NB = gridDim.x;
    const int blk = blockIdx.x;
    const uint4* WposP = (const uint4*)g_WposP + (size_t)blk * (POS_U32_BLK / 4);
    const uint4* Ww0P = (const uint4*)g_Ww0P + (size_t)blk * (W0_U32_BLK / 4);
    const uint4* Ww1P = (const uint4*)g_Ww1P + (size_t)blk * (W1_U32_BLK / 4);
    for (int t = 0; t < TT; t++) {
        const int p = t & 1, q = p ^ 1;
        const int tok0 = t * BB;
        const size_t rp = (size_t)t * 32;        // prev slot row base
        const size_t rc = (size_t)(t + 1) * 32;  // cur slot row base
        // pos: x = [w1_h(t-1) (1024); p_h(t-1) (256)]
        cell_mma<5, 1, POS_H, 2>(
            xhi, xlo, red, WposP, g_bpos, g_preT_p, tok0,
            g_w1b_h + rp * WORD_H, g_w1b_l + rp * WORD_H, WORD_H, 1024,
            g_pob_h + rp * POS_H, g_pob_l + rp * POS_H, POS_H,
            g_Cpos[p], g_Cpos[q],
            g_poutsT + rc,
            g_pob_h + rc * POS_H, g_pob_l + rc * POS_H, POS_H);
        grid_barrier(++ep * NB);
        // w0: x = [p_h(t) (256); wh0(t-1) (1024)]
        cell_mma<5, 2, WORD_H, 8>(
            xhi, xlo, red, Ww0P, g_bw0, g_preT_w0, tok0,
            g_pob_h + rc * POS_H, g_pob_l + rc * POS_H, POS_H, 256,
            g_w0b_h + rp * WORD_H, g_w0b_l + rp * WORD_H, WORD_H,
            g_Cw0[p], g_Cw0[q],
            nullptr,
            g_w0b_h + rc * WORD_H, g_w0b_l + rc * WORD_H, WORD_H);
        grid_barrier(++ep * NB);
        // w1: x = [wh0(t) (1024); w1_h(t-1) (1024)]
        cell_mma<8, 2, WORD_H, 8>(
            xhi, xlo, red, Ww1P, g_bw1, nullptr, tok0,
            g_w0b_h + rc * WORD_H, g_w0b_l + rc * WORD_H, WORD_H, 1024,
            g_w1b_h + rp * WORD_H, g_w1b_l + rp * WORD_H, WORD_H,
            g_Cw1[p], g_Cw1[q],
            g_woutsT + rc,
            g_w1b_h + rc * WORD_H, g_w1b_l + rc * WORD_H, WORD_H);
        grid_barrier(++ep * NB);
    }
}

// ---------------------------------------------------------------------------
// f32x2 GEMM (R7 static-smem, proven): C[m,n] = sum_k AT[k,m]*W[n,k] + bias
// ---------------------------------------------------------------------------
__global__ __launch_bounds__(256, 2) void gemm_t_kernel(
    const float* __restrict__ AT, int M, int lda,
    const float* __restrict__ W, int ldw, const float* __restrict__ bias,
    float* __restrict__ C, float* __restrict__ CT, int N, int K) {
    __shared__ float As[32][128];
    __shared__ float Ws[32][132];
    const int tid = threadIdx.x;
    const int rt = tid & 15;
    const int ct = tid >> 4;
    const int rBase = blockIdx.y * 128, cBase = blockIdx.x * 128;

    ull acc[8][4];
#pragma unroll
    for (int jj = 0; jj < 8; jj++)
#pragma unroll
        for (int p = 0; p < 4; p++) acc[jj][p] = 0ull;

    for (int kb = 0; kb < K; kb += 32) {
#pragma unroll
        for (int it = 0; it < 4; it++) {
            int flat = tid + it * 256;
            int k = flat >> 5, m4 = flat & 31;
            float4 v = *(const float4*)&AT[(size_t)(kb + k) * lda + rBase + m4 * 4];
            *(float4*)&As[k][m4 * 4] = v;
        }
#pragma unroll
        for (int it = 0; it < 4; it++) {
            int flat = tid + it * 256;
            int n = flat >> 3, k4 = flat & 7;
            float4 v = *(const float4*)&W[(size_t)(cBase + n) * ldw + kb + k4 * 4];
            Ws[k4 * 4 + 0][n] = v.x;
            Ws[k4 * 4 + 1][n] = v.y;
            Ws[k4 * 4 + 2][n] = v.z;
            Ws[k4 * 4 + 3][n] = v.w;
        }
        __syncthreads();
#pragma unroll
        for (int k = 0; k < 32; k++) {
            ull xd[8];
#pragma unroll
            for (int jj = 0; jj < 8; jj++) xd[jj] = dup2(As[k][rt + 16 * jj]);
            const ulonglong2* wpp = (const ulonglong2*)&Ws[k][ct * 8];
            ulonglong2 wa = wpp[0];
            ulonglong2 wb = wpp[1];
#pragma unroll
            for (int jj = 0; jj < 8; jj++) {
                fma2(acc[jj][0], xd[jj], wa.x);
                fma2(acc[jj][1], xd[jj], wa.y);
                fma2(acc[jj][2], xd[jj], wb.x);
                fma2(acc[jj][3], xd[jj], wb.y);
            }
        }
        __syncthreads();
    }
    float bcol[8];
#pragma unroll
    for (int qq = 0; qq < 8; qq++) bcol[qq] = bias ? bias[cBase + ct * 8 + qq] : 0.f;
#pragma unroll
    for (int jj = 0; jj < 8; jj++) {
        int m = rBase + rt + 16 * jj;
        float v[8];
#pragma unroll
        for (int p = 0; p < 4; p++) unpack2(acc[jj][p], v[2 * p], v[2 * p + 1]);
#pragma unroll
        for (int qq = 0; qq < 8; qq++) v[qq] += bcol[qq];
        if (C) {
            float4* dst = (float4*)&C[(size_t)m * N + cBase + ct * 8];
            dst[0] = make_float4(v[0], v[1], v[2], v[3]);
            dst[1] = make_float4(v[4], v[5], v[6], v[7]);
        }
        if (CT) {
#pragma unroll
            for (int qq = 0; qq < 8; qq++)
                CT[(size_t)(cBase + ct * 8 + qq) * M + m] = v[qq];
        }
    }
}

// ---------------------------------------------------------------------------
// Warp-MMA bf16 head GEMM (R12, proven)
// ---------------------------------------------------------------------------
__global__ __launch_bounds__(256, 1) void head_mma_kernel(
    const float* __restrict__ wp2b, float* __restrict__ outp) {
    __shared__ __nv_bfloat16 As[2][128][40];
    __shared__ __nv_bfloat16 Bs[2][128][40];
    const int tid = threadIdx.x;
    const int wid = tid >> 5, lane = tid & 31;
    const int wm = wid & 3;
    const int wn = wid >> 2;
    const int rBase = blockIdx.y * 128, cBase = blockIdx.x * 128;
    const int gid = lane >> 2, tig = lane & 3;

    float acc[2][8][4];
#pragma unroll
    for (int mt = 0; mt < 2; mt++)
#pragma unroll
        for (int nt = 0; nt < 8; nt++)
#pragma unroll
            for (int q = 0; q < 4; q++) acc[mt][nt][q] = 0.f;

    const int sr0 = tid >> 2, sg = tid & 3;

    uint4 pa[2], pb[2];
#pragma unroll
    for (int it = 0; it < 2; it++) {
        int r = sr0 + it * 64;
        pa[it] = *(const uint4*)(g_wmid_bf + (size_t)(rBase + r) * WORD_E + sg * 8);
        pb[it] = *(const uint4*)(g_emb_bf + (size_t)(cBase + r) * WORD_E + sg * 8);
    }
#pragma unroll
    for (int it = 0; it < 2; it++) {
        int r = sr0 + it * 64;
        *(uint4*)&As[0][r][sg * 8] = pa[it];
        *(uint4*)&Bs[0][r][sg * 8] = pb[it];
    }
    __syncthreads();

    const int NCHUNK = WORD_E / 32;
    for (int c = 0; c < NCHUNK; c++) {
        const int cur = c & 1, nxt = cur ^ 1;
        if (c + 1 < NCHUNK) {
            int kb = (c + 1) * 32;
#pragma unroll
            for (int it = 0; it < 2; it++) {
                int r = sr0 + it * 64;
                pa[it] = *(const uint4*)(g_wmid_bf + (size_t)(rBase + r) * WORD_E + kb + sg * 8);
                pb[it] = *(const uint4*)(g_emb_bf + (size_t)(cBase + r) * WORD_E + kb + sg * 8);
            }
        }
#pragma unroll
        for (int ks = 0; ks < 32; ks += 16) {
            const int k0 = ks + tig * 2;
            unsigned b[8][2];
#pragma unroll
            for (int nt = 0; nt < 8; nt++) {
                int n0 = wn * 64 + nt * 8 + gid;
                b[nt][0] = *(const unsigned*)&Bs[cur][n0][k0];
                b[nt][1] = *(const unsigned*)&Bs[cur][n0][k0 + 8];
            }
#pragma unroll
            for (int mt = 0; mt < 2; mt++) {
                int r0 = wm * 32 + mt * 16 + gid;
                unsigned a0 = *(const unsigned*)&As[cur][r0][k0];
                unsigned a1 = *(const unsigned*)&As[cur][r0 + 8][k0];
                unsigned a2 = *(const unsigned*)&As[cur][r0][k0 + 8];
                unsigned a3 = *(const unsigned*)&As[cur][r0 + 8][k0 + 8];
#pragma unroll
                for (int nt = 0; nt < 8; nt++)
                    mma_bf16(acc[mt][nt][0], acc[mt][nt][1], acc[mt][nt][2], acc[mt][nt][3],
                             a0, a1, a2, a3, b[nt][0], b[nt][1]);
            }
        }
        if (c + 1 < NCHUNK) {
#pragma unroll
            for (int it = 0; it < 2; it++) {
                int r = sr0 + it * 64;
                *(uint4*)&As[nxt][r][sg * 8] = pa[it];
                *(uint4*)&Bs[nxt][r][sg * 8] = pb[it];
            }
        }
        __syncthreads();
    }

#pragma unroll
    for (int nt = 0; nt < 8; nt++) {
        int col = cBase + wn * 64 + nt * 8 + tig * 2;
        float2 bv = *(const float2*)(wp2b + col);
#pragma unroll
        for (int mt = 0; mt < 2; mt++) {
            int row = rBase + wm * 32 + mt * 16 + gid;
            float2 v0 = make_float2(acc[mt][nt][0] + bv.x, acc[mt][nt][1] + bv.y);
            float2 v1 = make_float2(acc[mt][nt][2] + bv.x, acc[mt][nt][3] + bv.y);
            *(float2*)(outp + (size_t)row * WORD_V + col) = v0;
            *(float2*)(outp + (size_t)(row + 8) * WORD_V + col) = v1;
        }
    }
}

// ---------------------------------------------------------------------------
// pos projection + log-softmax (one block per timestep)
// ---------------------------------------------------------------------------
__global__ void pos_projT_kernel(const float* __restrict__ Wp, const float* __restrict__ bp,
                                 float* __restrict__ out) {
    __shared__ float xs[POS_H][32];
    __shared__ float lg[POS_V][33];
    __shared__ float lsb[32];
    const int t = blockIdx.x;
    const int tok0 = t * 32;
    const int tid = threadIdx.x;
    const int b = tid & 31, vg = tid >> 5;
    for (int i = tid; i < POS_H * 32; i += 256) {
        int k = i >> 5, bb = i & 31;
        xs[k][bb] = g_poutsT[(size_t)k * NTOKP + 32 + tok0 + bb];
    }
    __syncthreads();
    for (int v = vg; v < POS_V; v += 8) {
        float s = bp[v];
        const float* wv = Wp + (size_t)v * POS_H;
        for (int k = 0; k < POS_H; k++) s = fmaf(xs[k][b], wv[k], s);
        lg[v][b] = s;
    }
    __syncthreads();
    if (tid < 32) {
        float m = -INFINITY;
        for (int v = 0; v < POS_V; v++) m = fmaxf(m, lg[v][tid]);
        float e = 0.f;
        for (int v = 0; v < POS_V; v++) e += expf(lg[v][tid] - m);
        lsb[tid] = m + logf(e);
    }
    __syncthreads();
    float ls = lsb[b];
    for (int v = vg; v < POS_V; v += 8)
        out[(size_t)(tok0 + b) * POS_V + v] = lg[v][b] - ls;
}

// ---------------------------------------------------------------------------
// word log-softmax in place (one block per row, float4)
// ---------------------------------------------------------------------------
__global__ void word_softmax_kernel(float* __restrict__ logits) {
    __shared__ float red[8];
    const int row = blockIdx.x;
    float4* p4 = (float4*)(logits + (size_t)row * WORD_V);
    const int NV4 = WORD_V / 4;
    const int tid = threadIdx.x;
    float m = -INFINITY;
    for (int i = tid; i < NV4; i += 256) {
        float4 v = p4[i];
        m = fmaxf(m, fmaxf(fmaxf(v.x, v.y), fmaxf(v.z, v.w)));
    }
#pragma unroll
    for (int o = 16; o; o >>= 1) m = fmaxf(m, __shfl_xor_sync(0xffffffffu, m, o));
    if ((tid & 31) == 0) red[tid >> 5] = m;
    __syncthreads();
    float M = red[0];
#pragma unroll
    for (int w = 1; w < 8; w++) M = fmaxf(M, red[w]);
    __syncthreads();
    float s = 0.f;
    for (int i = tid; i < NV4; i += 256) {
        float4 v = p4[i];
        s += expf(v.x - M) + expf(v.y - M) + expf(v.z - M) + expf(v.w - M);
    }
#pragma unroll
    for (int o = 16; o; o >>= 1) s += __shfl_xor_sync(0xffffffffu, s, o);
    if ((tid & 31) == 0) red[tid >> 5] = s;
    __syncthreads();
    float S = 0.f;
#pragma unroll
    for (int w = 0; w < 8; w++) S += red[w];
    float ls = M + logf(S);
    for (int i = tid; i < NV4; i += 256) {
        float4 v = p4[i];
        v.x -= ls; v.y -= ls; v.z -= ls; v.w -= ls;
        p4[i] = v;
    }
}

// ---------------------------------------------------------------------------
// Host side
// ---------------------------------------------------------------------------
extern "C" void kernel_launch(void* const* d_in, const int* in_sizes, int n_in,
                              void* d_out, int out_size) {
    (void)in_sizes; (void)n_in; (void)out_size;
    const int*   pos        = (const int*)d_in[0];
    const int*   word       = (const int*)d_in[1];
    const float* pos_emb_W  = (const float*)d_in[2];
    const float* word_emb_W = (const float*)d_in[3];
    const float* pos_Wih    = (const float*)d_in[4];
    const float* pos_Whh    = (const float*)d_in[5];
    const float* pos_bih    = (const float*)d_in[6];
    const float* pos_bhh    = (const float*)d_in[7];
    const float* w0_Wih     = (const float*)d_in[8];
    const float* w0_Whh     = (const float*)d_in[9];
    const float* w0_bih     = (const float*)d_in[10];
    const float* w0_bhh     = (const float*)d_in[11];
    const float* w1_Wih     = (const float*)d_in[12];
    const float* w1_Whh     = (const float*)d_in[13];
    const float* w1_bih     = (const float*)d_in[14];
    const float* w1_bhh     = (const float*)d_in[15];
    const float* pos_proj_W = (const float*)d_in[16];
    const float* pos_proj_b = (const float*)d_in[17];
    const float* wp1_W      = (const float*)d_in[18];
    const float* wp1_b      = (const float*)d_in[19];
    const float* wp2_b      = (const float*)d_in[20];
    float* out = (float*)d_out;

    float *p_embT, *w_embT, *woutsT, *wmid, *preT_p, *preT_w0;
    cudaGetSymbolAddress((void**)&p_embT, g_p_embT);
    cudaGetSymbolAddress((void**)&w_embT, g_w_embT);
    cudaGetSymbolAddress((void**)&woutsT, g_woutsT);
    cudaGetSymbolAddress((void**)&wmid, g_wmid);
    cudaGetSymbolAddress((void**)&preT_p, g_preT_p);
    cudaGetSymbolAddress((void**)&preT_w0, g_preT_w0);

    static bool attr_done = false;
    if (!attr_done) {
        cudaFuncSetAttribute(recurrence_kernel,
                             cudaFuncAttributeMaxDynamicSharedMemorySize, REC_SMEM);
        attr_done = true;
    }

    zero_init_kernel<<<(32 * WORD_H + 255) / 256, 256>>>();
    gather_kernel<<<(WORD_E * NTOK + 255) / 256, 256>>>(pos, word, pos_emb_W, word_emb_W);
    cvt_emb_kernel<<<(WORD_V * WORD_E / 4 + 255) / 256, 256>>>(word_emb_W);

    {
        const long long total = 128LL * POS_U32_BLK + 128LL * W0_U32_BLK +
                                128LL * W1_U32_BLK + 4 * POS_H + 2 * (4 * WORD_H);
        repack_bf16_kernel<<<(unsigned)((total + 255) / 256), 256>>>(
            pos_Wih, pos_Whh, w0_Wih, w0_Whh, w1_Wih, w1_Whh,
            pos_bih, pos_bhh, w0_bih, w0_bhh, w1_bih, w1_bhh);
    }

    // precompute emb @ Wih_emb-part for all timesteps (transposed outputs)
    gemm_t_kernel<<<dim3(4 * POS_H / 128, NTOK / 128), 256>>>(
        p_embT, NTOK, NTOK, pos_Wih, POS_E + WORD_H, nullptr,
        nullptr, preT_p, 4 * POS_H, POS_E);
    gemm_t_kernel<<<dim3(4 * WORD_H / 128, NTOK / 128), 256>>>(
        w_embT, NTOK, NTOK, w0_Wih, WORD_E + POS_H, nullptr,
        nullptr, preT_w0, 4 * WORD_H, WORD_E);

    // the whole 128-step recurrence: persistent HMMA kernel
    recurrence_kernel<<<128, REC_THREADS, REC_SMEM>>>();

    // pos projection + log-softmax
    pos_projT_kernel<<<TT, 256>>>(pos_proj_W, pos_proj_b, out);

    // word head: wp1 (fp32) -> wmid -> bf16 -> warp-MMA big GEMM
    gemm_t_kernel<<<dim3(WORD_E / 128, NTOK / 128), 256>>>(
        woutsT + 32, NTOK, NTOKP, wp1_W, WORD_H, wp1_b,
        wmid, nullptr, WORD_E, WORD_H);
    cvt_wmid_kernel<<<(NTOK * WORD_E / 4 + 255) / 256, 256>>>();

    float* wlp = out + (size_t)NTOK * POS_V;
    head_mma_kernel<<<dim3(WORD_V / 128, NTOK / 128), 256>>>(wp2_b, wlp);
    word_softmax_kernel<<<NTOK, 256>>>(wlp);
}

// round 14
// speedup vs baseline: 3.7831x; 1.2394x over previous
#include <cuda_runtime.h>
#include <cuda_bf16.h>
#include <stdint.h>
#include <math.h>

typedef unsigned long long ull;

// ---------------------------------------------------------------------------
// Problem constants
// ---------------------------------------------------------------------------
namespace {
constexpr int TT = 128, BB = 32;
constexpr int POS_E = 64, WORD_E = 512, POS_H = 256, WORD_H = 1024;
constexpr int POS_V = 45, WORD_V = 32000;
constexpr int NTOK = TT * BB;      // 4096
constexpr int NTOKP = NTOK + 32;

// ---------------------------------------------------------------------------
// Device scratch
// ---------------------------------------------------------------------------
__device__ float g_p_embT[POS_E * NTOK];
__device__ float g_w_embT[WORD_E * NTOK];
__device__ float g_poutsT[POS_H * NTOKP];            // fp32 [H][NTOKP] (pos proj)
__device__ float g_woutsT[WORD_H * NTOKP];           // fp32 (wp1 GEMM)
__device__ float g_wmid[NTOK * WORD_E];
__device__ __align__(16) __nv_bfloat16 g_wmid_bf[NTOK * WORD_E];
__device__ __align__(16) __nv_bfloat16 g_emb_bf[WORD_V * WORD_E];
__device__ float g_preT_p[4 * POS_H * NTOK];
__device__ float g_preT_w0[4 * WORD_H * NTOK];
// h histories in B-fragment-linear layout: uint2 = (hi-pair, lo-pair) of bf16.
// per slot: (DIM/256 chunks) x 16 warps x 8 groups x 32 lanes uint2 elements.
constexpr int POS_FR_SLOT = 1 * 16 * 8 * 32;   // 4096
constexpr int W_FR_SLOT = 4 * 16 * 8 * 32;     // 16384
__device__ __align__(16) uint2 g_pofr[(TT + 1) * POS_FR_SLOT];
__device__ __align__(16) uint2 g_w0fr[(TT + 1) * W_FR_SLOT];
__device__ __align__(16) uint2 g_w1fr[(TT + 1) * W_FR_SLOT];
// fragment-linear packed bf16 hi/lo weights (uint32 = 2 bf16 along k)
constexpr int POS_U32_BLK = 5 * 16 * 2 * 32 * 4;     // 20480
constexpr int W0_U32_BLK  = 5 * 16 * 4 * 32 * 4;     // 40960
constexpr int W1_U32_BLK  = 8 * 16 * 4 * 32 * 4;     // 65536
__device__ __align__(16) unsigned g_WposP[128 * POS_U32_BLK];
__device__ __align__(16) unsigned g_Ww0P[128 * W0_U32_BLK];
__device__ __align__(16) unsigned g_Ww1P[128 * W1_U32_BLK];
__device__ float g_bpos[4 * POS_H], g_bw0[4 * WORD_H], g_bw1[4 * WORD_H];
__device__ float g_Cpos[2][POS_H * BB];
__device__ float g_Cw0[2][WORD_H * BB];
__device__ float g_Cw1[2][WORD_H * BB];
__device__ unsigned g_bar_ctr;
}  // namespace

// ---------------------------------------------------------------------------
// helpers
// ---------------------------------------------------------------------------
__device__ __forceinline__ ull pack2(float lo, float hi) {
    ull r; asm("mov.b64 %0, {%1,%2};" : "=l"(r) : "f"(lo), "f"(hi)); return r;
}
__device__ __forceinline__ ull dup2(float v) { return pack2(v, v); }
__device__ __forceinline__ void fma2(ull& d, ull a, ull b) {
    asm("fma.rn.f32x2 %0, %1, %2, %0;" : "+l"(d) : "l"(a), "l"(b));
}
__device__ __forceinline__ void unpack2(ull v, float& lo, float& hi) {
    asm("mov.b64 {%0,%1}, %2;" : "=f"(lo), "=f"(hi) : "l"(v));
}
__device__ __forceinline__ float sigm(float x) { return 1.f / (1.f + expf(-x)); }

__device__ __forceinline__ void mma_bf16(float& c0, float& c1, float& c2, float& c3,
                                         unsigned a0, unsigned a1, unsigned a2, unsigned a3,
                                         unsigned b0, unsigned b1) {
    asm volatile("mma.sync.aligned.m16n8k16.row.col.f32.bf16.bf16.f32 "
                 "{%0,%1,%2,%3}, {%4,%5,%6,%7}, {%8,%9}, {%0,%1,%2,%3};"
                 : "+f"(c0), "+f"(c1), "+f"(c2), "+f"(c3)
                 : "r"(a0), "r"(a1), "r"(a2), "r"(a3), "r"(b0), "r"(b1));
}

// gate-stage h store into fragment layout (d = dim, gb = batch)
__device__ __forceinline__ void store_hfrag(uint2* base, int d, int gb, float h2) {
    int c = d >> 8, kloc = d & 255;
    int w = kloc >> 4, koff = kloc & 15;
    int reg = koff >> 3, k8 = koff & 7;
    int tig = k8 >> 1, half = k8 & 1;
    int nt = gb >> 3, gid = gb & 7;
    int lane = gid * 4 + tig;
    int grp = nt * 2 + reg;
    unsigned short* p = (unsigned short*)(base + ((((size_t)c * 16 + w) * 8 + grp) * 32 + lane));
    __nv_bfloat16 hi = __float2bfloat16(h2);
    __nv_bfloat16 lo = __float2bfloat16(h2 - __bfloat162float(hi));
    p[half] = *(unsigned short*)&hi;
    p[2 + half] = *(unsigned short*)&lo;
}

// ---------------------------------------------------------------------------
// Init / gather / conversions
// ---------------------------------------------------------------------------
__global__ void zero_init_kernel() {
    int i = blockIdx.x * blockDim.x + threadIdx.x;
    if (i < POS_FR_SLOT) g_pofr[i] = make_uint2(0u, 0u);
    if (i < W_FR_SLOT) {
        g_w0fr[i] = make_uint2(0u, 0u);
        g_w1fr[i] = make_uint2(0u, 0u);
    }
    if (i < POS_H * BB) g_Cpos[0][i] = 0.f;
    if (i < WORD_H * BB) {
        g_Cw0[0][i] = 0.f;
        g_Cw1[0][i] = 0.f;
    }
    if (i == 0) g_bar_ctr = 0u;
}

__global__ void gather_kernel(const int* __restrict__ pos, const int* __restrict__ word,
                              const float* __restrict__ posW, const float* __restrict__ wordW) {
    int j = blockIdx.x * blockDim.x + threadIdx.x;
    if (j < WORD_E * NTOK) {
        int d = j / NTOK, tok = j - d * NTOK;
        g_w_embT[j] = wordW[(size_t)word[tok] * WORD_E + d];
    }
    if (j < POS_E * NTOK) {
        int d = j / NTOK, tok = j - d * NTOK;
        g_p_embT[j] = posW[(size_t)pos[tok] * POS_E + d];
    }
}

__global__ void cvt_emb_kernel(const float* __restrict__ src) {
    size_t i = ((size_t)blockIdx.x * blockDim.x + threadIdx.x) * 4;
    if (i < (size_t)WORD_V * WORD_E) {
        float4 v = *(const float4*)(src + i);
        *(__nv_bfloat162*)&g_emb_bf[i] = __floats2bfloat162_rn(v.x, v.y);
        *(__nv_bfloat162*)&g_emb_bf[i + 2] = __floats2bfloat162_rn(v.z, v.w);
    }
}

__global__ void cvt_wmid_kernel() {
    size_t i = ((size_t)blockIdx.x * blockDim.x + threadIdx.x) * 4;
    if (i < (size_t)NTOK * WORD_E) {
        float4 v = *(const float4*)(g_wmid + i);
        *(__nv_bfloat162*)&g_wmid_bf[i] = __floats2bfloat162_rn(v.x, v.y);
        *(__nv_bfloat162*)&g_wmid_bf[i + 2] = __floats2bfloat162_rn(v.z, v.w);
    }
}

// ---------------------------------------------------------------------------
// Repack weights into fragment-linear bf16 hi/lo (+ combined biases) — R13.
// ---------------------------------------------------------------------------
__device__ __forceinline__ unsigned pack_hl(float v0, float v1, int part) {
    __nv_bfloat16 h0 = __float2bfloat16(v0);
    __nv_bfloat16 h1 = __float2bfloat16(v1);
    unsigned short u0, u1;
    if (part == 0) {
        u0 = *(unsigned short*)&h0;
        u1 = *(unsigned short*)&h1;
    } else {
        __nv_bfloat16 l0 = __float2bfloat16(v0 - __bfloat162float(h0));
        __nv_bfloat16 l1 = __float2bfloat16(v1 - __bfloat162float(h1));
        u0 = *(unsigned short*)&l0;
        u1 = *(unsigned short*)&l1;
    }
    return (unsigned)u0 | ((unsigned)u1 << 16);
}

__global__ void repack_bf16_kernel(
    const float* __restrict__ pWih, const float* __restrict__ pWhh,
    const float* __restrict__ w0Wih, const float* __restrict__ w0Whh,
    const float* __restrict__ w1Wih, const float* __restrict__ w1Whh,
    const float* __restrict__ pbih, const float* __restrict__ pbhh,
    const float* __restrict__ w0bih, const float* __restrict__ w0bhh,
    const float* __restrict__ w1bih, const float* __restrict__ w1bhh) {
    long long i = (long long)blockIdx.x * blockDim.x + threadIdx.x;
    const long long P_TOT = 128LL * POS_U32_BLK;
    const long long W0_TOT = 128LL * W0_U32_BLK;
    const long long W1_TOT = 128LL * W1_U32_BLK;
    if (i < P_TOT) {
        int blk = (int)(i / POS_U32_BLK), e = (int)(i % POS_U32_BLK);
        int r = e & 3, lane = (e >> 2) & 31;
        int t1 = e >> 7;
        int part = t1 & 1;
        int t2 = t1 >> 1;
        int w = t2 & 15, c = t2 >> 4;
        int row_l = (lane >> 2) + (r & 1) * 8;
        int k_l = (lane & 3) * 2 + (r >> 1) * 8;
        int kg = c * 256 + w * 16 + k_l;
        float v0 = 0.f, v1 = 0.f;
        if (row_l < 8) {
            int g = row_l >> 1, hh = row_l & 1;
            int R = g * POS_H + blk * 2 + hh;
            v0 = (kg < 1024) ? pWih[(size_t)R * 1088 + 64 + kg] : pWhh[(size_t)R * 256 + kg - 1024];
            v1 = (kg + 1 < 1024) ? pWih[(size_t)R * 1088 + 64 + kg + 1]
                                 : pWhh[(size_t)R * 256 + kg + 1 - 1024];
        }
        g_WposP[i] = pack_hl(v0, v1, part);
        return;
    }
    i -= P_TOT;
    if (i < W0_TOT) {
        int blk = (int)(i / W0_U32_BLK), e = (int)(i % W0_U32_BLK);
        int r = e & 3, lane = (e >> 2) & 31;
        int t1 = e >> 7;
        int f = t1 & 3;
        int t2 = t1 >> 2;
        int w = t2 & 15, c = t2 >> 4;
        int part = f & 1, rt = f >> 1;
        int row_l = rt * 16 + (lane >> 2) + (r & 1) * 8;
        int k_l = (lane & 3) * 2 + (r >> 1) * 8;
        int kg = c * 256 + w * 16 + k_l;
        int g = row_l >> 3, hh = row_l & 7;
        int R = g * WORD_H + blk * 8 + hh;
        float v0 = (kg < 256) ? w0Wih[(size_t)R * 768 + 512 + kg]
                              : w0Whh[(size_t)R * 1024 + kg - 256];
        float v1 = (kg + 1 < 256) ? w0Wih[(size_t)R * 768 + 512 + kg + 1]
                                  : w0Whh[(size_t)R * 1024 + kg + 1 - 256];
        g_Ww0P[i] = pack_hl(v0, v1, part);
        return;
    }
    i -= W0_TOT;
    if (i < W1_TOT) {
        int blk = (int)(i / W1_U32_BLK), e = (int)(i % W1_U32_BLK);
        int r = e & 3, lane = (e >> 2) & 31;
        int t1 = e >> 7;
        int f = t1 & 3;
        int t2 = t1 >> 2;
        int w = t2 & 15, c = t2 >> 4;
        int part = f & 1, rt = f >> 1;
        int row_l = rt * 16 + (lane >> 2) + (r & 1) * 8;
        int k_l = (lane & 3) * 2 + (r >> 1) * 8;
        int kg = c * 256 + w * 16 + k_l;
        int g = row_l >> 3, hh = row_l & 7;
        int R = g * WORD_H + blk * 8 + hh;
        float v0 = (kg < 1024) ? w1Wih[(size_t)R * 1024 + kg]
                               : w1Whh[(size_t)R * 1024 + kg - 1024];
        float v1 = (kg + 1 < 1024) ? w1Wih[(size_t)R * 1024 + kg + 1]
                                   : w1Whh[(size_t)R * 1024 + kg + 1 - 1024];
        g_Ww1P[i] = pack_hl(v0, v1, part);
        return;
    }
    i -= W1_TOT;
    if (i < 4 * POS_H) { g_bpos[i] = pbih[i] + pbhh[i]; return; }
    i -= 4 * POS_H;
    if (i < 4 * WORD_H) { g_bw0[i] = w0bih[i] + w0bhh[i]; return; }
    i -= 4 * WORD_H;
    if (i < 4 * WORD_H) { g_bw1[i] = w1bih[i] + w1bhh[i]; }
}

// ---------------------------------------------------------------------------
// Persistent HMMA recurrence: 128 blocks x 512 threads.
// X operands loaded straight from fragment-layout global -> registers.
// smem: only red[16][32][34] f32 (dynamic, 69632 B).
// ---------------------------------------------------------------------------
constexpr int REC_THREADS = 512;
constexpr int REDW = 34;
constexpr int REC_SMEM = 16 * 32 * REDW * 4;  // 69632

__device__ __forceinline__ void grid_barrier(unsigned target) {
    __syncthreads();
    if (threadIdx.x == 0) {
        __threadfence();
        atomicAdd(&g_bar_ctr, 1u);
        while (*(volatile unsigned*)&g_bar_ctr < target) __nanosleep(64);
        __threadfence();
    }
    __syncthreads();
}

template <int NC, int NRT, int H, int HPB>
__device__ __forceinline__ void cell_mma(
    float* red,
    const uint4* __restrict__ W4, const float* __restrict__ bcomb,
    const float* __restrict__ preT, int tok0,
    const uint2* __restrict__ s1, int NCH1, const uint2* __restrict__ s2,
    const float* __restrict__ cin, float* __restrict__ cout,
    float* __restrict__ hcol32, uint2* __restrict__ hfrag) {
    const int tid = threadIdx.x;
    const int w = tid >> 5, lane = tid & 31;
    const int gid = lane >> 2, tig = lane & 3;

    // gate operand prefetch
    const int hh = tid >> 5, gb = tid & 31;
    const int habs = blockIdx.x * HPB + hh;
    float cin_v = 0.f, bbv[4], prg[4];
    if (tid < HPB * 32) {
        cin_v = cin[habs * 32 + gb];
#pragma unroll
        for (int g = 0; g < 4; g++) {
            bbv[g] = bcomb[g * H + habs];
            prg[g] = preT ? preT[(size_t)(g * H + habs) * NTOK + tok0 + gb] : 0.f;
        }
    }

    float acc[NRT][4][4];
#pragma unroll
    for (int rt = 0; rt < NRT; rt++)
#pragma unroll
        for (int nt = 0; nt < 4; nt++)
#pragma unroll
            for (int q = 0; q < 4; q++) acc[rt][nt][q] = 0.f;

    uint2 xr[2][8];
    uint4 wreg[2][NRT][2];

    auto xload = [&](int c, int buf) {
        const uint2* s = (c < NCH1)
            ? s1 + ((size_t)(c * 16 + w) * 8) * 32
            : s2 + ((size_t)((c - NCH1) * 16 + w) * 8) * 32;
#pragma unroll
        for (int g = 0; g < 8; g++) xr[buf][g] = s[g * 32 + lane];
    };
    auto wload = [&](int c, int buf) {
#pragma unroll
        for (int rt = 0; rt < NRT; rt++)
#pragma unroll
            for (int p = 0; p < 2; p++)
                wreg[buf][rt][p] =
                    W4[((size_t)(c * 16 + w) * (NRT * 2) + rt * 2 + p) * 32 + lane];
    };

    xload(0, 0);
    wload(0, 0);
    for (int c = 0; c < NC; c++) {
        const int cur = c & 1, nxt = cur ^ 1;
        if (c + 1 < NC) {
            xload(c + 1, nxt);
            wload(c + 1, nxt);
        }
#pragma unroll
        for (int nt = 0; nt < 4; nt++) {
            unsigned bh0 = xr[cur][nt * 2].x, bl0 = xr[cur][nt * 2].y;
            unsigned bh1 = xr[cur][nt * 2 + 1].x, bl1 = xr[cur][nt * 2 + 1].y;
#pragma unroll
            for (int rt = 0; rt < NRT; rt++) {
                uint4 Ah = wreg[cur][rt][0];
                uint4 Al = wreg[cur][rt][1];
                mma_bf16(acc[rt][nt][0], acc[rt][nt][1], acc[rt][nt][2], acc[rt][nt][3],
                         Ah.x, Ah.y, Ah.z, Ah.w, bh0, bh1);
                mma_bf16(acc[rt][nt][0], acc[rt][nt][1], acc[rt][nt][2], acc[rt][nt][3],
                         Ah.x, Ah.y, Ah.z, Ah.w, bl0, bl1);
                mma_bf16(acc[rt][nt][0], acc[rt][nt][1], acc[rt][nt][2], acc[rt][nt][3],
                         Al.x, Al.y, Al.z, Al.w, bh0, bh1);
            }
        }
    }
    // dump k-slice partials
#pragma unroll
    for (int rt = 0; rt < NRT; rt++)
#pragma unroll
        for (int nt = 0; nt < 4; nt++) {
            int row = rt * 16 + gid, col = nt * 8 + tig * 2;
            float* rp = red + (size_t)w * 32 * REDW + row * REDW + col;
            *(float2*)rp = make_float2(acc[rt][nt][0], acc[rt][nt][1]);
            *(float2*)(rp + 8 * REDW) = make_float2(acc[rt][nt][2], acc[rt][nt][3]);
        }
    __syncthreads();
    // gate stage
    if (tid < HPB * 32) {
        float gs[4];
#pragma unroll
        for (int g = 0; g < 4; g++) {
            float s = bbv[g] + prg[g];
#pragma unroll
            for (int ww = 0; ww < 16; ww++)
                s += red[(size_t)ww * 32 * REDW + (g * HPB + hh) * REDW + gb];
            gs[g] = s;
        }
        float i = sigm(gs[0]), f = sigm(gs[1]), g = tanhf(gs[2]), o = sigm(gs[3]);
        float c2 = f * cin_v + i * g;
        float h2 = o * tanhf(c2);
        cout[habs * 32 + gb] = c2;
        if (hcol32) hcol32[(size_t)habs * NTOKP + gb] = h2;
        store_hfrag(hfrag, habs, gb, h2);
    }
    __syncthreads();
}

__global__ __launch_bounds__(REC_THREADS, 1) void recurrence_kernel() {
    extern __shared__ float red[];
    unsigned ep = 0;
    const unsigned NB = gridDim.x;
    const int blk = blockIdx.x;
    const uint4* WposP = (const uint4*)g_WposP + (size_t)blk * (POS_U32_BLK / 4);
    const uint4* Ww0P = (const uint4*)g_Ww0P + (size_t)blk * (W0_U32_BLK / 4);
    const uint4* Ww1P = (const uint4*)g_Ww1P + (size_t)blk * (W1_U32_BLK / 4);
    for (int t = 0; t < TT; t++) {
        const int p = t & 1, q = p ^ 1;
        const int tok0 = t * BB;
        // pos: x = [w1_h(t-1) chunks 0..3 ; p_h(t-1) chunk 0]
        cell_mma<5, 1, POS_H, 2>(
            red, WposP, g_bpos, g_preT_p, tok0,
            g_w1fr + (size_t)t * W_FR_SLOT, 4, g_pofr + (size_t)t * POS_FR_SLOT,
            g_Cpos[p], g_Cpos[q],
            g_poutsT + (size_t)(t + 1) * 32,
            g_pofr + (size_t)(t + 1) * POS_FR_SLOT);
        grid_barrier(++ep * NB);
        // w0: x = [p_h(t) chunk 0 ; wh0(t-1) chunks 0..3]
        cell_mma<5, 2, WORD_H, 8>(
            red, Ww0P, g_bw0, g_preT_w0, tok0,
            g_pofr + (size_t)(t + 1) * POS_FR_SLOT, 1, g_w0fr + (size_t)t * W_FR_SLOT,
            g_Cw0[p], g_Cw0[q],
            nullptr,
            g_w0fr + (size_t)(t + 1) * W_FR_SLOT);
        grid_barrier(++ep * NB);
        // w1: x = [wh0(t) chunks 0..3 ; w1_h(t-1) chunks 0..3]
        cell_mma<8, 2, WORD_H, 8>(
            red, Ww1P, g_bw1, nullptr, tok0,
            g_w0fr + (size_t)(t + 1) * W_FR_SLOT, 4, g_w1fr + (size_t)t * W_FR_SLOT,
            g_Cw1[p], g_Cw1[q],
            g_woutsT + (size_t)(t + 1) * 32,
            g_w1fr + (size_t)(t + 1) * W_FR_SLOT);
        grid_barrier(++ep * NB);
    }
}

// ---------------------------------------------------------------------------
// f32x2 GEMM (R7 static-smem, proven)
// ---------------------------------------------------------------------------
__global__ __launch_bounds__(256, 2) void gemm_t_kernel(
    const float* __restrict__ AT, int M, int lda,
    const float* __restrict__ W, int ldw, const float* __restrict__ bias,
    float* __restrict__ C, float* __restrict__ CT, int N, int K) {
    __shared__ float As[32][128];
    __shared__ float Ws[32][132];
    const int tid = threadIdx.x;
    const int rt = tid & 15;
    const int ct = tid >> 4;
    const int rBase = blockIdx.y * 128, cBase = blockIdx.x * 128;

    ull acc[8][4];
#pragma unroll
    for (int jj = 0; jj < 8; jj++)
#pragma unroll
        for (int p = 0; p < 4; p++) acc[jj][p] = 0ull;

    for (int kb = 0; kb < K; kb += 32) {
#pragma unroll
        for (int it = 0; it < 4; it++) {
            int flat = tid + it * 256;
            int k = flat >> 5, m4 = flat & 31;
            float4 v = *(const float4*)&AT[(size_t)(kb + k) * lda + rBase + m4 * 4];
            *(float4*)&As[k][m4 * 4] = v;
        }
#pragma unroll
        for (int it = 0; it < 4; it++) {
            int flat = tid + it * 256;
            int n = flat >> 3, k4 = flat & 7;
            float4 v = *(const float4*)&W[(size_t)(cBase + n) * ldw + kb + k4 * 4];
            Ws[k4 * 4 + 0][n] = v.x;
            Ws[k4 * 4 + 1][n] = v.y;
            Ws[k4 * 4 + 2][n] = v.z;
            Ws[k4 * 4 + 3][n] = v.w;
        }
        __syncthreads();
#pragma unroll
        for (int k = 0; k < 32; k++) {
            ull xd[8];
#pragma unroll
            for (int jj = 0; jj < 8; jj++) xd[jj] = dup2(As[k][rt + 16 * jj]);
            const ulonglong2* wpp = (const ulonglong2*)&Ws[k][ct * 8];
            ulonglong2 wa = wpp[0];
            ulonglong2 wb = wpp[1];
#pragma unroll
            for (int jj = 0; jj < 8; jj++) {
                fma2(acc[jj][0], xd[jj], wa.x);
                fma2(acc[jj][1], xd[jj], wa.y);
                fma2(acc[jj][2], xd[jj], wb.x);
                fma2(acc[jj][3], xd[jj], wb.y);
            }
        }
        __syncthreads();
    }
    float bcol[8];
#pragma unroll
    for (int qq = 0; qq < 8; qq++) bcol[qq] = bias ? bias[cBase + ct * 8 + qq] : 0.f;
#pragma unroll
    for (int jj = 0; jj < 8; jj++) {
        int m = rBase + rt + 16 * jj;
        float v[8];
#pragma unroll
        for (int p = 0; p < 4; p++) unpack2(acc[jj][p], v[2 * p], v[2 * p + 1]);
#pragma unroll
        for (int qq = 0; qq < 8; qq++) v[qq] += bcol[qq];
        if (C) {
            float4* dst = (float4*)&C[(size_t)m * N + cBase + ct * 8];
            dst[0] = make_float4(v[0], v[1], v[2], v[3]);
            dst[1] = make_float4(v[4], v[5], v[6], v[7]);
        }
        if (CT) {
#pragma unroll
            for (int qq = 0; qq < 8; qq++)
                CT[(size_t)(cBase + ct * 8 + qq) * M + m] = v[qq];
        }
    }
}

// ---------------------------------------------------------------------------
// Warp-MMA bf16 head GEMM (R12, proven)
// ---------------------------------------------------------------------------
__global__ __launch_bounds__(256, 1) void head_mma_kernel(
    const float* __restrict__ wp2b, float* __restrict__ outp) {
    __shared__ __nv_bfloat16 As[2][128][40];
    __shared__ __nv_bfloat16 Bs[2][128][40];
    const int tid = threadIdx.x;
    const int wid = tid >> 5, lane = tid & 31;
    const int wm = wid & 3;
    const int wn = wid >> 2;
    const int rBase = blockIdx.y * 128, cBase = blockIdx.x * 128;
    const int gid = lane >> 2, tig = lane & 3;

    float acc[2][8][4];
#pragma unroll
    for (int mt = 0; mt < 2; mt++)
#pragma unroll
        for (int nt = 0; nt < 8; nt++)
#pragma unroll
            for (int q = 0; q < 4; q++) acc[mt][nt][q] = 0.f;

    const int sr0 = tid >> 2, sg = tid & 3;

    uint4 pa[2], pb[2];
#pragma unroll
    for (int it = 0; it < 2; it++) {
        int r = sr0 + it * 64;
        pa[it] = *(const uint4*)(g_wmid_bf + (size_t)(rBase + r) * WORD_E + sg * 8);
        pb[it] = *(const uint4*)(g_emb_bf + (size_t)(cBase + r) * WORD_E + sg * 8);
    }
#pragma unroll
    for (int it = 0; it < 2; it++) {
        int r = sr0 + it * 64;
        *(uint4*)&As[0][r][sg * 8] = pa[it];
        *(uint4*)&Bs[0][r][sg * 8] = pb[it];
    }
    __syncthreads();

    const int NCHUNK = WORD_E / 32;
    for (int c = 0; c < NCHUNK; c++) {
        const int cur = c & 1, nxt = cur ^ 1;
        if (c + 1 < NCHUNK) {
            int kb = (c + 1) * 32;
#pragma unroll
            for (int it = 0; it < 2; it++) {
                int r = sr0 + it * 64;
                pa[it] = *(const uint4*)(g_wmid_bf + (size_t)(rBase + r) * WORD_E + kb + sg * 8);
                pb[it] = *(const uint4*)(g_emb_bf + (size_t)(cBase + r) * WORD_E + kb + sg * 8);
            }
        }
#pragma unroll
        for (int ks = 0; ks < 32; ks += 16) {
            const int k0 = ks + tig * 2;
            unsigned b[8][2];
#pragma unroll
            for (int nt = 0; nt < 8; nt++) {
                int n0 = wn * 64 + nt * 8 + gid;
                b[nt][0] = *(const unsigned*)&Bs[cur][n0][k0];
                b[nt][1] = *(const unsigned*)&Bs[cur][n0][k0 + 8];
            }
#pragma unroll
            for (int mt = 0; mt < 2; mt++) {
                int r0 = wm * 32 + mt * 16 + gid;
                unsigned a0 = *(const unsigned*)&As[cur][r0][k0];
                unsigned a1 = *(const unsigned*)&As[cur][r0 + 8][k0];
                unsigned a2 = *(const unsigned*)&As[cur][r0][k0 + 8];
                unsigned a3 = *(const unsigned*)&As[cur][r0 + 8][k0 + 8];
#pragma unroll
                for (int nt = 0; nt < 8; nt++)
                    mma_bf16(acc[mt][nt][0], acc[mt][nt][1], acc[mt][nt][2], acc[mt][nt][3],
                             a0, a1, a2, a3, b[nt][0], b[nt][1]);
            }
        }
        if (c + 1 < NCHUNK) {
#pragma unroll
            for (int it = 0; it < 2; it++) {
                int r = sr0 + it * 64;
                *(uint4*)&As[nxt][r][sg * 8] = pa[it];
                *(uint4*)&Bs[nxt][r][sg * 8] = pb[it];
            }
        }
        __syncthreads();
    }

#pragma unroll
    for (int nt = 0; nt < 8; nt++) {
        int col = cBase + wn * 64 + nt * 8 + tig * 2;
        float2 bv = *(const float2*)(wp2b + col);
#pragma unroll
        for (int mt = 0; mt < 2; mt++) {
            int row = rBase + wm * 32 + mt * 16 + gid;
            float2 v0 = make_float2(acc[mt][nt][0] + bv.x, acc[mt][nt][1] + bv.y);
            float2 v1 = make_float2(acc[mt][nt][2] + bv.x, acc[mt][nt][3] + bv.y);
            *(float2*)(outp + (size_t)row * WORD_V + col) = v0;
            *(float2*)(outp + (size_t)(row + 8) * WORD_V + col) = v1;
        }
    }
}

// ---------------------------------------------------------------------------
// pos projection + log-softmax (one block per timestep)
// ---------------------------------------------------------------------------
__global__ void pos_projT_kernel(const float* __restrict__ Wp, const float* __restrict__ bp,
                                 float* __restrict__ out) {
    __shared__ float xs[POS_H][32];
    __shared__ float lg[POS_V][33];
    __shared__ float lsb[32];
    const int t = blockIdx.x;
    const int tok0 = t * 32;
    const int tid = threadIdx.x;
    const int b = tid & 31, vg = tid >> 5;
    for (int i = tid; i < POS_H * 32; i += 256) {
        int k = i >> 5, bb = i & 31;
        xs[k][bb] = g_poutsT[(size_t)k * NTOKP + 32 + tok0 + bb];
    }
    __syncthreads();
    for (int v = vg; v < POS_V; v += 8) {
        float s = bp[v];
        const float* wv = Wp + (size_t)v * POS_H;
        for (int k = 0; k < POS_H; k++) s = fmaf(xs[k][b], wv[k], s);
        lg[v][b] = s;
    }
    __syncthreads();
    if (tid < 32) {
        float m = -INFINITY;
        for (int v = 0; v < POS_V; v++) m = fmaxf(m, lg[v][tid]);
        float e = 0.f;
        for (int v = 0; v < POS_V; v++) e += expf(lg[v][tid] - m);
        lsb[tid] = m + logf(e);
    }
    __syncthreads();
    float ls = lsb[b];
    for (int v = vg; v < POS_V; v += 8)
        out[(size_t)(tok0 + b) * POS_V + v] = lg[v][b] - ls;
}

// ---------------------------------------------------------------------------
// word log-softmax in place (one block per row, float4)
// ---------------------------------------------------------------------------
__global__ void word_softmax_kernel(float* __restrict__ logits) {
    __shared__ float red[8];
    const int row = blockIdx.x;
    float4* p4 = (float4*)(logits + (size_t)row * WORD_V);
    const int NV4 = WORD_V / 4;
    const int tid = threadIdx.x;
    float m = -INFINITY;
    for (int i = tid; i < NV4; i += 256) {
        float4 v = p4[i];
        m = fmaxf(m, fmaxf(fmaxf(v.x, v.y), fmaxf(v.z, v.w)));
    }
#pragma unroll
    for (int o = 16; o; o >>= 1) m = fmaxf(m, __shfl_xor_sync(0xffffffffu, m, o));
    if ((tid & 31) == 0) red[tid >> 5] = m;
    __syncthreads();
    float M = red[0];
#pragma unroll
    for (int w = 1; w < 8; w++) M = fmaxf(M, red[w]);
    __syncthreads();
    float s = 0.f;
    for (int i = tid; i < NV4; i += 256) {
        float4 v = p4[i];
        s += expf(v.x - M) + expf(v.y - M) + expf(v.z - M) + expf(v.w - M);
    }
#pragma unroll
    for (int o = 16; o; o >>= 1) s += __shfl_xor_sync(0xffffffffu, s, o);
    if ((tid & 31) == 0) red[tid >> 5] = s;
    __syncthreads();
    float S = 0.f;
#pragma unroll
    for (int w = 0; w < 8; w++) S += red[w];
    float ls = M + logf(S);
    for (int i = tid; i < NV4; i += 256) {
        float4 v = p4[i];
        v.x -= ls; v.y -= ls; v.z -= ls; v.w -= ls;
        p4[i] = v;
    }
}

// ---------------------------------------------------------------------------
// Host side
// ---------------------------------------------------------------------------
extern "C" void kernel_launch(void* const* d_in, const int* in_sizes, int n_in,
                              void* d_out, int out_size) {
    (void)in_sizes; (void)n_in; (void)out_size;
    const int*   pos        = (const int*)d_in[0];
    const int*   word       = (const int*)d_in[1];
    const float* pos_emb_W  = (const float*)d_in[2];
    const float* word_emb_W = (const float*)d_in[3];
    const float* pos_Wih    = (const float*)d_in[4];
    const float* pos_Whh    = (const float*)d_in[5];
    const float* pos_bih    = (const float*)d_in[6];
    const float* pos_bhh    = (const float*)d_in[7];
    const float* w0_Wih     = (const float*)d_in[8];
    const float* w0_Whh     = (const float*)d_in[9];
    const float* w0_bih     = (const float*)d_in[10];
    const float* w0_bhh     = (const float*)d_in[11];
    const float* w1_Wih     = (const float*)d_in[12];
    const float* w1_Whh     = (const float*)d_in[13];
    const float* w1_bih     = (const float*)d_in[14];
    const float* w1_bhh     = (const float*)d_in[15];
    const float* pos_proj_W = (const float*)d_in[16];
    const float* pos_proj_b = (const float*)d_in[17];
    const float* wp1_W      = (const float*)d_in[18];
    const float* wp1_b      = (const float*)d_in[19];
    const float* wp2_b      = (const float*)d_in[20];
    float* out = (float*)d_out;

    float *p_embT, *w_embT, *woutsT, *wmid, *preT_p, *preT_w0;
    cudaGetSymbolAddress((void**)&p_embT, g_p_embT);
    cudaGetSymbolAddress((void**)&w_embT, g_w_embT);
    cudaGetSymbolAddress((void**)&woutsT, g_woutsT);
    cudaGetSymbolAddress((void**)&wmid, g_wmid);
    cudaGetSymbolAddress((void**)&preT_p, g_preT_p);
    cudaGetSymbolAddress((void**)&preT_w0, g_preT_w0);

    static bool attr_done = false;
    if (!attr_done) {
        cudaFuncSetAttribute(recurrence_kernel,
                             cudaFuncAttributeMaxDynamicSharedMemorySize, REC_SMEM);
        attr_done = true;
    }

    zero_init_kernel<<<(32 * WORD_H + 255) / 256, 256>>>();
    gather_kernel<<<(WORD_E * NTOK + 255) / 256, 256>>>(pos, word, pos_emb_W, word_emb_W);
    cvt_emb_kernel<<<(WORD_V * WORD_E / 4 + 255) / 256, 256>>>(word_emb_W);

    {
        const long long total = 128LL * POS_U32_BLK + 128LL * W0_U32_BLK +
                                128LL * W1_U32_BLK + 4 * POS_H + 2 * (4 * WORD_H);
        repack_bf16_kernel<<<(unsigned)((total + 255) / 256), 256>>>(
            pos_Wih, pos_Whh, w0_Wih, w0_Whh, w1_Wih, w1_Whh,
            pos_bih, pos_bhh, w0_bih, w0_bhh, w1_bih, w1_bhh);
    }

    // precompute emb @ Wih_emb-part for all timesteps (transposed outputs)
    gemm_t_kernel<<<dim3(4 * POS_H / 128, NTOK / 128), 256>>>(
        p_embT, NTOK, NTOK, pos_Wih, POS_E + WORD_H, nullptr,
        nullptr, preT_p, 4 * POS_H, POS_E);
    gemm_t_kernel<<<dim3(4 * WORD_H / 128, NTOK / 128), 256>>>(
        w_embT, NTOK, NTOK, w0_Wih, WORD_E + POS_H, nullptr,
        nullptr, preT_w0, 4 * WORD_H, WORD_E);

    // the whole 128-step recurrence: persistent HMMA kernel (frag-direct x)
    recurrence_kernel<<<128, REC_THREADS, REC_SMEM>>>();

    // pos projection + log-softmax
    pos_projT_kernel<<<TT, 256>>>(pos_proj_W, pos_proj_b, out);

    // word head: wp1 (fp32) -> wmid -> bf16 -> warp-MMA big GEMM
    gemm_t_kernel<<<dim3(WORD_E / 128, NTOK / 128), 256>>>(
        woutsT + 32, NTOK, NTOKP, wp1_W, WORD_H, wp1_b,
        wmid, nullptr, WORD_E, WORD_H);
    cvt_wmid_kernel<<<(NTOK * WORD_E / 4 + 255) / 256, 256>>>();

    float* wlp = out + (size_t)NTOK * POS_V;
    head_mma_kernel<<<dim3(WORD_V / 128, NTOK / 128), 256>>>(wp2_b, wlp);
    word_softmax_kernel<<<NTOK, 256>>>(wlp);
}

// round 15
// speedup vs baseline: 3.9342x; 1.0399x over previous
#include <cuda_runtime.h>
#include <cuda_bf16.h>
#include <stdint.h>
#include <math.h>

typedef unsigned long long ull;

// ---------------------------------------------------------------------------
// Problem constants
// ---------------------------------------------------------------------------
namespace {
constexpr int TT = 128, BB = 32;
constexpr int POS_E = 64, WORD_E = 512, POS_H = 256, WORD_H = 1024;
constexpr int POS_V = 45, WORD_V = 32000;
constexpr int NTOK = TT * BB;      // 4096
constexpr int NTOKP = NTOK + 32;

// ---------------------------------------------------------------------------
// Device scratch
// ---------------------------------------------------------------------------
__device__ __align__(16) __nv_bfloat16 g_p_emb_h[NTOK * POS_E];
__device__ __align__(16) __nv_bfloat16 g_p_emb_l[NTOK * POS_E];
__device__ __align__(16) __nv_bfloat16 g_w_emb_h[NTOK * WORD_E];
__device__ __align__(16) __nv_bfloat16 g_w_emb_l[NTOK * WORD_E];
__device__ float g_poutsT[POS_H * NTOKP];            // fp32 [H][NTOKP] (pos proj)
__device__ __align__(16) __nv_bfloat16 g_wouts_r_h[NTOK * WORD_H];  // row-major
__device__ __align__(16) __nv_bfloat16 g_wouts_r_l[NTOK * WORD_H];
__device__ __align__(16) __nv_bfloat16 g_wmid_bf[NTOK * WORD_E];
__device__ __align__(16) __nv_bfloat16 g_emb_bf[WORD_V * WORD_E];
__device__ float g_preT_p[4 * POS_H * NTOK];
__device__ float g_preT_w0[4 * WORD_H * NTOK];
// h histories in B-fragment-linear layout: uint2 = (hi-pair, lo-pair) of bf16.
constexpr int POS_FR_SLOT = 1 * 16 * 8 * 32;   // 4096
constexpr int W_FR_SLOT = 4 * 16 * 8 * 32;     // 16384
__device__ __align__(16) uint2 g_pofr[(TT + 1) * POS_FR_SLOT];
__device__ __align__(16) uint2 g_w0fr[(TT + 1) * W_FR_SLOT];
__device__ __align__(16) uint2 g_w1fr[(TT + 1) * W_FR_SLOT];
// fragment-linear packed bf16 hi/lo weights (uint32 = 2 bf16 along k)
constexpr int POS_U32_BLK = 5 * 16 * 2 * 32 * 4;     // 20480
constexpr int W0_U32_BLK  = 5 * 16 * 4 * 32 * 4;     // 40960
constexpr int W1_U32_BLK  = 8 * 16 * 4 * 32 * 4;     // 65536
__device__ __align__(16) unsigned g_WposP[128 * POS_U32_BLK];
__device__ __align__(16) unsigned g_Ww0P[128 * W0_U32_BLK];
__device__ __align__(16) unsigned g_Ww1P[128 * W1_U32_BLK];
__device__ float g_bpos[4 * POS_H], g_bw0[4 * WORD_H], g_bw1[4 * WORD_H];
__device__ float g_Cpos[2][POS_H * BB];
__device__ float g_Cw0[2][WORD_H * BB];
__device__ float g_Cw1[2][WORD_H * BB];
__device__ unsigned g_bar_ctr;
}  // namespace

// ---------------------------------------------------------------------------
// helpers
// ---------------------------------------------------------------------------
__device__ __forceinline__ float sigm(float x) { return 1.f / (1.f + expf(-x)); }

__device__ __forceinline__ void split_bf(float v, __nv_bfloat16& h, __nv_bfloat16& l) {
    h = __float2bfloat16(v);
    l = __float2bfloat16(v - __bfloat162float(h));
}

__device__ __forceinline__ void mma_bf16(float& c0, float& c1, float& c2, float& c3,
                                         unsigned a0, unsigned a1, unsigned a2, unsigned a3,
                                         unsigned b0, unsigned b1) {
    asm volatile("mma.sync.aligned.m16n8k16.row.col.f32.bf16.bf16.f32 "
                 "{%0,%1,%2,%3}, {%4,%5,%6,%7}, {%8,%9}, {%0,%1,%2,%3};"
                 : "+f"(c0), "+f"(c1), "+f"(c2), "+f"(c3)
                 : "r"(a0), "r"(a1), "r"(a2), "r"(a3), "r"(b0), "r"(b1));
}

// gate-stage h store into fragment layout (d = dim, gb = batch)
__device__ __forceinline__ void store_hfrag(uint2* base, int d, int gb,
                                            __nv_bfloat16 hi, __nv_bfloat16 lo) {
    int c = d >> 8, kloc = d & 255;
    int w = kloc >> 4, koff = kloc & 15;
    int reg = koff >> 3, k8 = koff & 7;
    int tig = k8 >> 1, half = k8 & 1;
    int nt = gb >> 3, gid = gb & 7;
    int lane = gid * 4 + tig;
    int grp = nt * 2 + reg;
    unsigned short* p = (unsigned short*)(base + ((((size_t)c * 16 + w) * 8 + grp) * 32 + lane));
    p[half] = *(unsigned short*)&hi;
    p[2 + half] = *(unsigned short*)&lo;
}

// ---------------------------------------------------------------------------
// Init / gather / conversions
// ---------------------------------------------------------------------------
__global__ void zero_init_kernel() {
    int i = blockIdx.x * blockDim.x + threadIdx.x;
    if (i < POS_FR_SLOT) g_pofr[i] = make_uint2(0u, 0u);
    if (i < W_FR_SLOT) {
        g_w0fr[i] = make_uint2(0u, 0u);
        g_w1fr[i] = make_uint2(0u, 0u);
    }
    if (i < POS_H * BB) g_Cpos[0][i] = 0.f;
    if (i < WORD_H * BB) {
        g_Cw0[0][i] = 0.f;
        g_Cw1[0][i] = 0.f;
    }
    if (i == 0) g_bar_ctr = 0u;
}

__global__ void gather_kernel(const int* __restrict__ pos, const int* __restrict__ word,
                              const float* __restrict__ posW, const float* __restrict__ wordW) {
    int j = blockIdx.x * blockDim.x + threadIdx.x;
    if (j < NTOK * WORD_E) {
        int tok = j / WORD_E, d = j - tok * WORD_E;
        float v = wordW[(size_t)word[tok] * WORD_E + d];
        __nv_bfloat16 h, l;
        split_bf(v, h, l);
        g_w_emb_h[j] = h;
        g_w_emb_l[j] = l;
    }
    if (j < NTOK * POS_E) {
        int tok = j / POS_E, d = j - tok * POS_E;
        float v = posW[(size_t)pos[tok] * POS_E + d];
        __nv_bfloat16 h, l;
        split_bf(v, h, l);
        g_p_emb_h[j] = h;
        g_p_emb_l[j] = l;
    }
}

__global__ void cvt_emb_kernel(const float* __restrict__ src) {
    size_t i = ((size_t)blockIdx.x * blockDim.x + threadIdx.x) * 4;
    if (i < (size_t)WORD_V * WORD_E) {
        float4 v = *(const float4*)(src + i);
        *(__nv_bfloat162*)&g_emb_bf[i] = __floats2bfloat162_rn(v.x, v.y);
        *(__nv_bfloat162*)&g_emb_bf[i + 2] = __floats2bfloat162_rn(v.z, v.w);
    }
}

// ---------------------------------------------------------------------------
// Repack weights into fragment-linear bf16 hi/lo (+ combined biases) — R13.
// ---------------------------------------------------------------------------
__device__ __forceinline__ unsigned pack_hl(float v0, float v1, int part) {
    __nv_bfloat16 h0 = __float2bfloat16(v0);
    __nv_bfloat16 h1 = __float2bfloat16(v1);
    unsigned short u0, u1;
    if (part == 0) {
        u0 = *(unsigned short*)&h0;
        u1 = *(unsigned short*)&h1;
    } else {
        __nv_bfloat16 l0 = __float2bfloat16(v0 - __bfloat162float(h0));
        __nv_bfloat16 l1 = __float2bfloat16(v1 - __bfloat162float(h1));
        u0 = *(unsigned short*)&l0;
        u1 = *(unsigned short*)&l1;
    }
    return (unsigned)u0 | ((unsigned)u1 << 16);
}

__global__ void repack_bf16_kernel(
    const float* __restrict__ pWih, const float* __restrict__ pWhh,
    const float* __restrict__ w0Wih, const float* __restrict__ w0Whh,
    const float* __restrict__ w1Wih, const float* __restrict__ w1Whh,
    const float* __restrict__ pbih, const float* __restrict__ pbhh,
    const float* __restrict__ w0bih, const float* __restrict__ w0bhh,
    const float* __restrict__ w1bih, const float* __restrict__ w1bhh) {
    long long i = (long long)blockIdx.x * blockDim.x + threadIdx.x;
    const long long P_TOT = 128LL * POS_U32_BLK;
    const long long W0_TOT = 128LL * W0_U32_BLK;
    const long long W1_TOT = 128LL * W1_U32_BLK;
    if (i < P_TOT) {
        int blk = (int)(i / POS_U32_BLK), e = (int)(i % POS_U32_BLK);
        int r = e & 3, lane = (e >> 2) & 31;
        int t1 = e >> 7;
        int part = t1 & 1;
        int t2 = t1 >> 1;
        int w = t2 & 15, c = t2 >> 4;
        int row_l = (lane >> 2) + (r & 1) * 8;
        int k_l = (lane & 3) * 2 + (r >> 1) * 8;
        int kg = c * 256 + w * 16 + k_l;
        float v0 = 0.f, v1 = 0.f;
        if (row_l < 8) {
            int g = row_l >> 1, hh = row_l & 1;
            int R = g * POS_H + blk * 2 + hh;
            v0 = (kg < 1024) ? pWih[(size_t)R * 1088 + 64 + kg] : pWhh[(size_t)R * 256 + kg - 1024];
            v1 = (kg + 1 < 1024) ? pWih[(size_t)R * 1088 + 64 + kg + 1]
                                 : pWhh[(size_t)R * 256 + kg + 1 - 1024];
        }
        g_WposP[i] = pack_hl(v0, v1, part);
        return;
    }
    i -= P_TOT;
    if (i < W0_TOT) {
        int blk = (int)(i / W0_U32_BLK), e = (int)(i % W0_U32_BLK);
        int r = e & 3, lane = (e >> 2) & 31;
        int t1 = e >> 7;
        int f = t1 & 3;
        int t2 = t1 >> 2;
        int w = t2 & 15, c = t2 >> 4;
        int part = f & 1, rt = f >> 1;
        int row_l = rt * 16 + (lane >> 2) + (r & 1) * 8;
        int k_l = (lane & 3) * 2 + (r >> 1) * 8;
        int kg = c * 256 + w * 16 + k_l;
        int g = row_l >> 3, hh = row_l & 7;
        int R = g * WORD_H + blk * 8 + hh;
        float v0 = (kg < 256) ? w0Wih[(size_t)R * 768 + 512 + kg]
                              : w0Whh[(size_t)R * 1024 + kg - 256];
        float v1 = (kg + 1 < 256) ? w0Wih[(size_t)R * 768 + 512 + kg + 1]
                                  : w0Whh[(size_t)R * 1024 + kg + 1 - 256];
        g_Ww0P[i] = pack_hl(v0, v1, part);
        return;
    }
    i -= W0_TOT;
    if (i < W1_TOT) {
        int blk = (int)(i / W1_U32_BLK), e = (int)(i % W1_U32_BLK);
        int r = e & 3, lane = (e >> 2) & 31;
        int t1 = e >> 7;
        int f = t1 & 3;
        int t2 = t1 >> 2;
        int w = t2 & 15, c = t2 >> 4;
        int part = f & 1, rt = f >> 1;
        int row_l = rt * 16 + (lane >> 2) + (r & 1) * 8;
        int k_l = (lane & 3) * 2 + (r >> 1) * 8;
        int kg = c * 256 + w * 16 + k_l;
        int g = row_l >> 3, hh = row_l & 7;
        int R = g * WORD_H + blk * 8 + hh;
        float v0 = (kg < 1024) ? w1Wih[(size_t)R * 1024 + kg]
                               : w1Whh[(size_t)R * 1024 + kg - 1024];
        float v1 = (kg + 1 < 1024) ? w1Wih[(size_t)R * 1024 + kg + 1]
                                   : w1Whh[(size_t)R * 1024 + kg + 1 - 1024];
        g_Ww1P[i] = pack_hl(v0, v1, part);
        return;
    }
    i -= W1_TOT;
    if (i < 4 * POS_H) { g_bpos[i] = pbih[i] + pbhh[i]; return; }
    i -= 4 * POS_H;
    if (i < 4 * WORD_H) { g_bw0[i] = w0bih[i] + w0bhh[i]; return; }
    i -= 4 * WORD_H;
    if (i < 4 * WORD_H) { g_bw1[i] = w1bih[i] + w1bhh[i]; }
}

// ---------------------------------------------------------------------------
// Persistent HMMA recurrence (R14, proven) + row-major bf16 wouts store.
// ---------------------------------------------------------------------------
constexpr int REC_THREADS = 512;
constexpr int REDW = 34;
constexpr int REC_SMEM = 16 * 32 * REDW * 4;  // 69632

__device__ __forceinline__ void grid_barrier(unsigned target) {
    __syncthreads();
    if (threadIdx.x == 0) {
        __threadfence();
        atomicAdd(&g_bar_ctr, 1u);
        while (*(volatile unsigned*)&g_bar_ctr < target) __nanosleep(64);
        __threadfence();
    }
    __syncthreads();
}

template <int NC, int NRT, int H, int HPB>
__device__ __forceinline__ void cell_mma(
    float* red,
    const uint4* __restrict__ W4, const float* __restrict__ bcomb,
    const float* __restrict__ preT, int tok0,
    const uint2* __restrict__ s1, int NCH1, const uint2* __restrict__ s2,
    const float* __restrict__ cin, float* __restrict__ cout,
    float* __restrict__ hcol32, uint2* __restrict__ hfrag,
    __nv_bfloat16* __restrict__ hrow_h, __nv_bfloat16* __restrict__ hrow_l) {
    const int tid = threadIdx.x;
    const int w = tid >> 5, lane = tid & 31;
    const int gid = lane >> 2, tig = lane & 3;

    const int hh = tid >> 5, gb = tid & 31;
    const int habs = blockIdx.x * HPB + hh;
    float cin_v = 0.f, bbv[4], prg[4];
    if (tid < HPB * 32) {
        cin_v = cin[habs * 32 + gb];
#pragma unroll
        for (int g = 0; g < 4; g++) {
            bbv[g] = bcomb[g * H + habs];
            prg[g] = preT ? preT[(size_t)(g * H + habs) * NTOK + tok0 + gb] : 0.f;
        }
    }

    float acc[NRT][4][4];
#pragma unroll
    for (int rt = 0; rt < NRT; rt++)
#pragma unroll
        for (int nt = 0; nt < 4; nt++)
#pragma unroll
            for (int q = 0; q < 4; q++) acc[rt][nt][q] = 0.f;

    uint2 xr[2][8];
    uint4 wreg[2][NRT][2];

    auto xload = [&](int c, int buf) {
        const uint2* s = (c < NCH1)
            ? s1 + ((size_t)(c * 16 + w) * 8) * 32
            : s2 + ((size_t)((c - NCH1) * 16 + w) * 8) * 32;
#pragma unroll
        for (int g = 0; g < 8; g++) xr[buf][g] = s[g * 32 + lane];
    };
    auto wload = [&](int c, int buf) {
#pragma unroll
        for (int rt = 0; rt < NRT; rt++)
#pragma unroll
            for (int p = 0; p < 2; p++)
                wreg[buf][rt][p] =
                    W4[((size_t)(c * 16 + w) * (NRT * 2) + rt * 2 + p) * 32 + lane];
    };

    xload(0, 0);
    wload(0, 0);
    for (int c = 0; c < NC; c++) {
        const int cur = c & 1, nxt = cur ^ 1;
        if (c + 1 < NC) {
            xload(c + 1, nxt);
            wload(c + 1, nxt);
        }
#pragma unroll
        for (int nt = 0; nt < 4; nt++) {
            unsigned bh0 = xr[cur][nt * 2].x, bl0 = xr[cur][nt * 2].y;
            unsigned bh1 = xr[cur][nt * 2 + 1].x, bl1 = xr[cur][nt * 2 + 1].y;
#pragma unroll
            for (int rt = 0; rt < NRT; rt++) {
                uint4 Ah = wreg[cur][rt][0];
                uint4 Al = wreg[cur][rt][1];
                mma_bf16(acc[rt][nt][0], acc[rt][nt][1], acc[rt][nt][2], acc[rt][nt][3],
                         Ah.x, Ah.y, Ah.z, Ah.w, bh0, bh1);
                mma_bf16(acc[rt][nt][0], acc[rt][nt][1], acc[rt][nt][2], acc[rt][nt][3],
                         Ah.x, Ah.y, Ah.z, Ah.w, bl0, bl1);
                mma_bf16(acc[rt][nt][0], acc[rt][nt][1], acc[rt][nt][2], acc[rt][nt][3],
                         Al.x, Al.y, Al.z, Al.w, bh0, bh1);
            }
        }
    }
#pragma unroll
    for (int rt = 0; rt < NRT; rt++)
#pragma unroll
        for (int nt = 0; nt < 4; nt++) {
            int row = rt * 16 + gid, col = nt * 8 + tig * 2;
            float* rp = red + (size_t)w * 32 * REDW + row * REDW + col;
            *(float2*)rp = make_float2(acc[rt][nt][0], acc[rt][nt][1]);
            *(float2*)(rp + 8 * REDW) = make_float2(acc[rt][nt][2], acc[rt][nt][3]);
        }
    __syncthreads();
    if (tid < HPB * 32) {
        float gs[4];
#pragma unroll
        for (int g = 0; g < 4; g++) {
            float s = bbv[g] + prg[g];
#pragma unroll
            for (int ww = 0; ww < 16; ww++)
                s += red[(size_t)ww * 32 * REDW + (g * HPB + hh) * REDW + gb];
            gs[g] = s;
        }
        float i = sigm(gs[0]), f = sigm(gs[1]), g = tanhf(gs[2]), o = sigm(gs[3]);
        float c2 = f * cin_v + i * g;
        float h2 = o * tanhf(c2);
        cout[habs * 32 + gb] = c2;
        if (hcol32) hcol32[(size_t)habs * NTOKP + gb] = h2;
        __nv_bfloat16 hi, lo;
        split_bf(h2, hi, lo);
        store_hfrag(hfrag, habs, gb, hi, lo);
        if (hrow_h) {
            hrow_h[(size_t)(tok0 + gb) * WORD_H + habs] = hi;
            hrow_l[(size_t)(tok0 + gb) * WORD_H + habs] = lo;
        }
    }
    __syncthreads();
}

__global__ __launch_bounds__(REC_THREADS, 1) void recurrence_kernel() {
    extern __shared__ float red[];
    unsigned ep = 0;
    const unsigned NB = gridDim.x;
    const int blk = blockIdx.x;
    const uint4* WposP = (const uint4*)g_WposP + (size_t)blk * (POS_U32_BLK / 4);
    const uint4* Ww0P = (const uint4*)g_Ww0P + (size_t)blk * (W0_U32_BLK / 4);
    const uint4* Ww1P = (const uint4*)g_Ww1P + (size_t)blk * (W1_U32_BLK / 4);
    for (int t = 0; t < TT; t++) {
        const int p = t & 1, q = p ^ 1;
        const int tok0 = t * BB;
        cell_mma<5, 1, POS_H, 2>(
            red, WposP, g_bpos, g_preT_p, tok0,
            g_w1fr + (size_t)t * W_FR_SLOT, 4, g_pofr + (size_t)t * POS_FR_SLOT,
            g_Cpos[p], g_Cpos[q],
            g_poutsT + (size_t)(t + 1) * 32,
            g_pofr + (size_t)(t + 1) * POS_FR_SLOT, nullptr, nullptr);
        grid_barrier(++ep * NB);
        cell_mma<5, 2, WORD_H, 8>(
            red, Ww0P, g_bw0, g_preT_w0, tok0,
            g_pofr + (size_t)(t + 1) * POS_FR_SLOT, 1, g_w0fr + (size_t)t * W_FR_SLOT,
            g_Cw0[p], g_Cw0[q],
            nullptr,
            g_w0fr + (size_t)(t + 1) * W_FR_SLOT, nullptr, nullptr);
        grid_barrier(++ep * NB);
        cell_mma<8, 2, WORD_H, 8>(
            red, Ww1P, g_bw1, nullptr, tok0,
            g_w0fr + (size_t)(t + 1) * W_FR_SLOT, 4, g_w1fr + (size_t)t * W_FR_SLOT,
            g_Cw1[p], g_Cw1[q],
            nullptr,
            g_w1fr + (size_t)(t + 1) * W_FR_SLOT, g_wouts_r_h, g_wouts_r_l);
        grid_barrier(++ep * NB);
    }
}

// ---------------------------------------------------------------------------
// Generic split-bf16 HMMA GEMM:
//   out[m,n] = sum_k A[m,k] * W[n,k] (+ bias[n])
//   A given as bf16 hi/lo row-major; W fp32 rows, converted during staging.
//   Outputs: CT fp32 [n][ldct] scattered, or Cbf bf16(hi) row-major [m][ldc].
//   Tile 128x128, 8 warps (4M x 2N), K chunks of 32, reg double-buffered.
// ---------------------------------------------------------------------------
constexpr int MG_SMEM = 8 * 128 * 40 * 2;  // 81920

__global__ __launch_bounds__(256, 1) void mma_gemm_kernel(
    const __nv_bfloat16* __restrict__ Ah, const __nv_bfloat16* __restrict__ Al, int lda,
    const float* __restrict__ W, int ldw, const float* __restrict__ bias,
    float* __restrict__ CT, int ldct,
    __nv_bfloat16* __restrict__ Cbf, int ldc, int K) {
    extern __shared__ __nv_bfloat16 smb[];
    __nv_bfloat16* AH = smb;
    __nv_bfloat16* AL = smb + 2 * 128 * 40;
    __nv_bfloat16* BH = smb + 4 * 128 * 40;
    __nv_bfloat16* BL = smb + 6 * 128 * 40;
    const int tid = threadIdx.x;
    const int wid = tid >> 5, lane = tid & 31;
    const int wm = wid & 3, wn = wid >> 2;
    const int rBase = blockIdx.y * 128, cBase = blockIdx.x * 128;
    const int gid = lane >> 2, tig = lane & 3;
    const int NCHUNK = K / 32;

    float acc[2][8][4];
#pragma unroll
    for (int mt = 0; mt < 2; mt++)
#pragma unroll
        for (int nt = 0; nt < 8; nt++)
#pragma unroll
            for (int q = 0; q < 4; q++) acc[mt][nt][q] = 0.f;

    const int sa_r = tid >> 2, sa_g = tid & 3;   // A staging: 2 its of 256
    const int sb_r = tid >> 1, sb_g = tid & 1;   // B staging: 4 its -> row=flat>>3

    uint4 pah[2], pal[2];
    float4 pw[4];

    auto load_regs = [&](int kb) {
#pragma unroll
        for (int it = 0; it < 2; it++) {
            int flat = tid + it * 256;
            int row = flat >> 2, sg = flat & 3;
            pah[it] = *(const uint4*)(Ah + (size_t)(rBase + row) * lda + kb + sg * 8);
            pal[it] = *(const uint4*)(Al + (size_t)(rBase + row) * lda + kb + sg * 8);
        }
#pragma unroll
        for (int it = 0; it < 4; it++) {
            int flat = tid + it * 256;
            int row = flat >> 3, k4 = flat & 7;
            pw[it] = *(const float4*)(W + (size_t)(cBase + row) * ldw + kb + k4 * 4);
        }
    };
    auto store_smem = [&](int buf) {
#pragma unroll
        for (int it = 0; it < 2; it++) {
            int flat = tid + it * 256;
            int row = flat >> 2, sg = flat & 3;
            *(uint4*)&AH[(buf * 128 + row) * 40 + sg * 8] = pah[it];
            *(uint4*)&AL[(buf * 128 + row) * 40 + sg * 8] = pal[it];
        }
#pragma unroll
        for (int it = 0; it < 4; it++) {
            int flat = tid + it * 256;
            int row = flat >> 3, k4 = flat & 7;
            __nv_bfloat16 h0, h1, h2, h3, l0, l1, l2, l3;
            split_bf(pw[it].x, h0, l0);
            split_bf(pw[it].y, h1, l1);
            split_bf(pw[it].z, h2, l2);
            split_bf(pw[it].w, h3, l3);
            __nv_bfloat16* bh = &BH[(buf * 128 + row) * 40 + k4 * 4];
            __nv_bfloat16* bl = &BL[(buf * 128 + row) * 40 + k4 * 4];
            bh[0] = h0; bh[1] = h1; bh[2] = h2; bh[3] = h3;
            bl[0] = l0; bl[1] = l1; bl[2] = l2; bl[3] = l3;
        }
    };

    load_regs(0);
    store_smem(0);
    __syncthreads();

    for (int c = 0; c < NCHUNK; c++) {
        const int cur = c & 1, nxt = cur ^ 1;
        if (c + 1 < NCHUNK) load_regs((c + 1) * 32);
#pragma unroll
        for (int ks = 0; ks < 32; ks += 16) {
            const int k0 = ks + tig * 2;
            unsigned bh[8][2], bl[8][2];
#pragma unroll
            for (int nt = 0; nt < 8; nt++) {
                int n0 = wn * 64 + nt * 8 + gid;
                bh[nt][0] = *(const unsigned*)&BH[(cur * 128 + n0) * 40 + k0];
                bh[nt][1] = *(const unsigned*)&BH[(cur * 128 + n0) * 40 + k0 + 8];
                bl[nt][0] = *(const unsigned*)&BL[(cur * 128 + n0) * 40 + k0];
                bl[nt][1] = *(const unsigned*)&BL[(cur * 128 + n0) * 40 + k0 + 8];
            }
#pragma unroll
            for (int mt = 0; mt < 2; mt++) {
                int r0 = wm * 32 + mt * 16 + gid;
                unsigned a0 = *(const unsigned*)&AH[(cur * 128 + r0) * 40 + k0];
                unsigned a1 = *(const unsigned*)&AH[(cur * 128 + r0 + 8) * 40 + k0];
                unsigned a2 = *(const unsigned*)&AH[(cur * 128 + r0) * 40 + k0 + 8];
                unsigned a3 = *(const unsigned*)&AH[(cur * 128 + r0 + 8) * 40 + k0 + 8];
                unsigned c0 = *(const unsigned*)&AL[(cur * 128 + r0) * 40 + k0];
                unsigned c1 = *(const unsigned*)&AL[(cur * 128 + r0 + 8) * 40 + k0];
                unsigned c2 = *(const unsigned*)&AL[(cur * 128 + r0) * 40 + k0 + 8];
                unsigned c3 = *(const unsigned*)&AL[(cur * 128 + r0 + 8) * 40 + k0 + 8];
#pragma unroll
                for (int nt = 0; nt < 8; nt++) {
                    mma_bf16(acc[mt][nt][0], acc[mt][nt][1], acc[mt][nt][2], acc[mt][nt][3],
                             a0, a1, a2, a3, bh[nt][0], bh[nt][1]);
                    mma_bf16(acc[mt][nt][0], acc[mt][nt][1], acc[mt][nt][2], acc[mt][nt][3],
                             a0, a1, a2, a3, bl[nt][0], bl[nt][1]);
                    mma_bf16(acc[mt][nt][0], acc[mt][nt][1], acc[mt][nt][2], acc[mt][nt][3],
                             c0, c1, c2, c3, bh[nt][0], bh[nt][1]);
                }
            }
        }
        if (c + 1 < NCHUNK) store_smem(nxt);
        __syncthreads();
    }

    if (CT) {
#pragma unroll
        for (int nt = 0; nt < 8; nt++) {
            int col = cBase + wn * 64 + nt * 8 + tig * 2;
#pragma unroll
            for (int mt = 0; mt < 2; mt++) {
                int row = rBase + wm * 32 + mt * 16 + gid;
                CT[(size_t)col * ldct + row] = acc[mt][nt][0];
                CT[(size_t)(col + 1) * ldct + row] = acc[mt][nt][1];
                CT[(size_t)col * ldct + row + 8] = acc[mt][nt][2];
                CT[(size_t)(col + 1) * ldct + row + 8] = acc[mt][nt][3];
            }
        }
    }
    if (Cbf) {
#pragma unroll
        for (int nt = 0; nt < 8; nt++) {
            int col = cBase + wn * 64 + nt * 8 + tig * 2;
            float bx = bias ? bias[col] : 0.f;
            float by = bias ? bias[col + 1] : 0.f;
#pragma unroll
            for (int mt = 0; mt < 2; mt++) {
                int row = rBase + wm * 32 + mt * 16 + gid;
                *(__nv_bfloat162*)&Cbf[(size_t)row * ldc + col] =
                    __floats2bfloat162_rn(acc[mt][nt][0] + bx, acc[mt][nt][1] + by);
                *(__nv_bfloat162*)&Cbf[(size_t)(row + 8) * ldc + col] =
                    __floats2bfloat162_rn(acc[mt][nt][2] + bx, acc[mt][nt][3] + by);
            }
        }
    }
}

// ---------------------------------------------------------------------------
// Warp-MMA bf16 head GEMM (R12, proven)
// ---------------------------------------------------------------------------
__global__ __launch_bounds__(256, 1) void head_mma_kernel(
    const float* __restrict__ wp2b, float* __restrict__ outp) {
    __shared__ __nv_bfloat16 As[2][128][40];
    __shared__ __nv_bfloat16 Bs[2][128][40];
    const int tid = threadIdx.x;
    const int wid = tid >> 5, lane = tid & 31;
    const int wm = wid & 3;
    const int wn = wid >> 2;
    const int rBase = blockIdx.y * 128, cBase = blockIdx.x * 128;
    const int gid = lane >> 2, tig = lane & 3;

    float acc[2][8][4];
#pragma unroll
    for (int mt = 0; mt < 2; mt++)
#pragma unroll
        for (int nt = 0; nt < 8; nt++)
#pragma unroll
            for (int q = 0; q < 4; q++) acc[mt][nt][q] = 0.f;

    const int sr0 = tid >> 2, sg = tid & 3;

    uint4 pa[2], pb[2];
#pragma unroll
    for (int it = 0; it < 2; it++) {
        int r = sr0 + it * 64;
        pa[it] = *(const uint4*)(g_wmid_bf + (size_t)(rBase + r) * WORD_E + sg * 8);
        pb[it] = *(const uint4*)(g_emb_bf + (size_t)(cBase + r) * WORD_E + sg * 8);
    }
#pragma unroll
    for (int it = 0; it < 2; it++) {
        int r = sr0 + it * 64;
        *(uint4*)&As[0][r][sg * 8] = pa[it];
        *(uint4*)&Bs[0][r][sg * 8] = pb[it];
    }
    __syncthreads();

    const int NCHUNK = WORD_E / 32;
    for (int c = 0; c < NCHUNK; c++) {
        const int cur = c & 1, nxt = cur ^ 1;
        if (c + 1 < NCHUNK) {
            int kb = (c + 1) * 32;
#pragma unroll
            for (int it = 0; it < 2; it++) {
                int r = sr0 + it * 64;
                pa[it] = *(const uint4*)(g_wmid_bf + (size_t)(rBase + r) * WORD_E + kb + sg * 8);
                pb[it] = *(const uint4*)(g_emb_bf + (size_t)(cBase + r) * WORD_E + kb + sg * 8);
            }
        }
#pragma unroll
        for (int ks = 0; ks < 32; ks += 16) {
            const int k0 = ks + tig * 2;
            unsigned b[8][2];
#pragma unroll
            for (int nt = 0; nt < 8; nt++) {
                int n0 = wn * 64 + nt * 8 + gid;
                b[nt][0] = *(const unsigned*)&Bs[cur][n0][k0];
                b[nt][1] = *(const unsigned*)&Bs[cur][n0][k0 + 8];
            }
#pragma unroll
            for (int mt = 0; mt < 2; mt++) {
                int r0 = wm * 32 + mt * 16 + gid;
                unsigned a0 = *(const unsigned*)&As[cur][r0][k0];
                unsigned a1 = *(const unsigned*)&As[cur][r0 + 8][k0];
                unsigned a2 = *(const unsigned*)&As[cur][r0][k0 + 8];
                unsigned a3 = *(const unsigned*)&As[cur][r0 + 8][k0 + 8];
#pragma unroll
                for (int nt = 0; nt < 8; nt++)
                    mma_bf16(acc[mt][nt][0], acc[mt][nt][1], acc[mt][nt][2], acc[mt][nt][3],
                             a0, a1, a2, a3, b[nt][0], b[nt][1]);
            }
        }
        if (c + 1 < NCHUNK) {
#pragma unroll
            for (int it = 0; it < 2; it++) {
                int r = sr0 + it * 64;
                *(uint4*)&As[nxt][r][sg * 8] = pa[it];
                *(uint4*)&Bs[nxt][r][sg * 8] = pb[it];
            }
        }
        __syncthreads();
    }

#pragma unroll
    for (int nt = 0; nt < 8; nt++) {
        int col = cBase + wn * 64 + nt * 8 + tig * 2;
        float2 bv = *(const float2*)(wp2b + col);
#pragma unroll
        for (int mt = 0; mt < 2; mt++) {
            int row = rBase + wm * 32 + mt * 16 + gid;
            float2 v0 = make_float2(acc[mt][nt][0] + bv.x, acc[mt][nt][1] + bv.y);
            float2 v1 = make_float2(acc[mt][nt][2] + bv.x, acc[mt][nt][3] + bv.y);
            *(float2*)(outp + (size_t)row * WORD_V + col) = v0;
            *(float2*)(outp + (size_t)(row + 8) * WORD_V + col) = v1;
        }
    }
}

// ---------------------------------------------------------------------------
// pos projection + log-softmax (one block per timestep)
// ---------------------------------------------------------------------------
__global__ void pos_projT_kernel(const float* __restrict__ Wp, const float* __restrict__ bp,
                                 float* __restrict__ out) {
    __shared__ float xs[POS_H][32];
    __shared__ float lg[POS_V][33];
    __shared__ float lsb[32];
    const int t = blockIdx.x;
    const int tok0 = t * 32;
    const int tid = threadIdx.x;
    const int b = tid & 31, vg = tid >> 5;
    for (int i = tid; i < POS_H * 32; i += 256) {
        int k = i >> 5, bb = i & 31;
        xs[k][bb] = g_poutsT[(size_t)k * NTOKP + 32 + tok0 + bb];
    }
    __syncthreads();
    for (int v = vg; v < POS_V; v += 8) {
        float s = bp[v];
        const float* wv = Wp + (size_t)v * POS_H;
        for (int k = 0; k < POS_H; k++) s = fmaf(xs[k][b], wv[k], s);
        lg[v][b] = s;
    }
    __syncthreads();
    if (tid < 32) {
        float m = -INFINITY;
        for (int v = 0; v < POS_V; v++) m = fmaxf(m, lg[v][tid]);
        float e = 0.f;
        for (int v = 0; v < POS_V; v++) e += expf(lg[v][tid] - m);
        lsb[tid] = m + logf(e);
    }
    __syncthreads();
    float ls = lsb[b];
    for (int v = vg; v < POS_V; v += 8)
        out[(size_t)(tok0 + b) * POS_V + v] = lg[v][b] - ls;
}

// ---------------------------------------------------------------------------
// word log-softmax in place (one block per row, float4)
// ---------------------------------------------------------------------------
__global__ void word_softmax_kernel(float* __restrict__ logits) {
    __shared__ float red[8];
    const int row = blockIdx.x;
    float4* p4 = (float4*)(logits + (size_t)row * WORD_V);
    const int NV4 = WORD_V / 4;
    const int tid = threadIdx.x;
    float m = -INFINITY;
    for (int i = tid; i < NV4; i += 256) {
        float4 v = p4[i];
        m = fmaxf(m, fmaxf(fmaxf(v.x, v.y), fmaxf(v.z, v.w)));
    }
#pragma unroll
    for (int o = 16; o; o >>= 1) m = fmaxf(m, __shfl_xor_sync(0xffffffffu, m, o));
    if ((tid & 31) == 0) red[tid >> 5] = m;
    __syncthreads();
    float M = red[0];
#pragma unroll
    for (int w = 1; w < 8; w++) M = fmaxf(M, red[w]);
    __syncthreads();
    float s = 0.f;
    for (int i = tid; i < NV4; i += 256) {
        float4 v = p4[i];
        s += expf(v.x - M) + expf(v.y - M) + expf(v.z - M) + expf(v.w - M);
    }
#pragma unroll
    for (int o = 16; o; o >>= 1) s += __shfl_xor_sync(0xffffffffu, s, o);
    if ((tid & 31) == 0) red[tid >> 5] = s;
    __syncthreads();
    float S = 0.f;
#pragma unroll
    for (int w = 0; w < 8; w++) S += red[w];
    float ls = M + logf(S);
    for (int i = tid; i < NV4; i += 256) {
        float4 v = p4[i];
        v.x -= ls; v.y -= ls; v.z -= ls; v.w -= ls;
        p4[i] = v;
    }
}

// ---------------------------------------------------------------------------
// Host side
// ---------------------------------------------------------------------------
extern "C" void kernel_launch(void* const* d_in, const int* in_sizes, int n_in,
                              void* d_out, int out_size) {
    (void)in_sizes; (void)n_in; (void)out_size;
    const int*   pos        = (const int*)d_in[0];
    const int*   word       = (const int*)d_in[1];
    const float* pos_emb_W  = (const float*)d_in[2];
    const float* word_emb_W = (const float*)d_in[3];
    const float* pos_Wih    = (const float*)d_in[4];
    const float* pos_Whh    = (const float*)d_in[5];
    const float* pos_bih    = (const float*)d_in[6];
    const float* pos_bhh    = (const float*)d_in[7];
    const float* w0_Wih     = (const float*)d_in[8];
    const float* w0_Whh     = (const float*)d_in[9];
    const float* w0_bih     = (const float*)d_in[10];
    const float* w0_bhh     = (const float*)d_in[11];
    const float* w1_Wih     = (const float*)d_in[12];
    const float* w1_Whh     = (const float*)d_in[13];
    const float* w1_bih     = (const float*)d_in[14];
    const float* w1_bhh     = (const float*)d_in[15];
    const float* pos_proj_W = (const float*)d_in[16];
    const float* pos_proj_b = (const float*)d_in[17];
    const float* wp1_W      = (const float*)d_in[18];
    const float* wp1_b      = (const float*)d_in[19];
    const float* wp2_b      = (const float*)d_in[20];
    float* out = (float*)d_out;

    float *preT_p, *preT_w0;
    __nv_bfloat16 *p_emb_h, *p_emb_l, *w_emb_h, *w_emb_l, *wouts_r_h, *wouts_r_l, *wmid_bf;
    cudaGetSymbolAddress((void**)&preT_p, g_preT_p);
    cudaGetSymbolAddress((void**)&preT_w0, g_preT_w0);
    cudaGetSymbolAddress((void**)&p_emb_h, g_p_emb_h);
    cudaGetSymbolAddress((void**)&p_emb_l, g_p_emb_l);
    cudaGetSymbolAddress((void**)&w_emb_h, g_w_emb_h);
    cudaGetSymbolAddress((void**)&w_emb_l, g_w_emb_l);
    cudaGetSymbolAddress((void**)&wouts_r_h, g_wouts_r_h);
    cudaGetSymbolAddress((void**)&wouts_r_l, g_wouts_r_l);
    cudaGetSymbolAddress((void**)&wmid_bf, g_wmid_bf);

    static bool attr_done = false;
    if (!attr_done) {
        cudaFuncSetAttribute(recurrence_kernel,
                             cudaFuncAttributeMaxDynamicSharedMemorySize, REC_SMEM);
        cudaFuncSetAttribute(mma_gemm_kernel,
                             cudaFuncAttributeMaxDynamicSharedMemorySize, MG_SMEM);
        attr_done = true;
    }

    zero_init_kernel<<<(32 * WORD_H + 255) / 256, 256>>>();
    gather_kernel<<<(NTOK * WORD_E + 255) / 256, 256>>>(pos, word, pos_emb_W, word_emb_W);
    cvt_emb_kernel<<<(WORD_V * WORD_E / 4 + 255) / 256, 256>>>(word_emb_W);

    {
        const long long total = 128LL * POS_U32_BLK + 128LL * W0_U32_BLK +
                                128LL * W1_U32_BLK + 4 * POS_H + 2 * (4 * WORD_H);
        repack_bf16_kernel<<<(unsigned)((total + 255) / 256), 256>>>(
            pos_Wih, pos_Whh, w0_Wih, w0_Whh, w1_Wih, w1_Whh,
            pos_bih, pos_bhh, w0_bih, w0_bhh, w1_bih, w1_bhh);
    }

    // precompute emb @ Wih_emb-part for all timesteps (HMMA, CT outputs)
    mma_gemm_kernel<<<dim3(4 * POS_H / 128, NTOK / 128), 256, MG_SMEM>>>(
        p_emb_h, p_emb_l, POS_E, pos_Wih, POS_E + WORD_H, nullptr,
        preT_p, NTOK, nullptr, 0, POS_E);
    mma_gemm_kernel<<<dim3(4 * WORD_H / 128, NTOK / 128), 256, MG_SMEM>>>(
        w_emb_h, w_emb_l, WORD_E, w0_Wih, WORD_E + POS_H, nullptr,
        preT_w0, NTOK, nullptr, 0, WORD_E);

    // the whole 128-step recurrence: persistent HMMA kernel (frag-direct x)
    recurrence_kernel<<<128, REC_THREADS, REC_SMEM>>>();

    // pos projection + log-softmax
    pos_projT_kernel<<<TT, 256>>>(pos_proj_W, pos_proj_b, out);

    // word head: wp1 (HMMA split-bf16 -> wmid_bf) -> big head GEMM
    mma_gemm_kernel<<<dim3(WORD_E / 128, NTOK / 128), 256, MG_SMEM>>>(
        wouts_r_h, wouts_r_l, WORD_H, wp1_W, WORD_H, wp1_b,
        nullptr, 0, wmid_bf, WORD_E, WORD_H);

    float* wlp = out + (size_t)NTOK * POS_V;
    head_mma_kernel<<<dim3(WORD_V / 128, NTOK / 128), 256>>>(wp2_b, wlp);
    word_softmax_kernel<<<NTOK, 256>>>(wlp);
}

// round 16
// speedup vs baseline: 4.5002x; 1.1439x over previous
#include <cuda_runtime.h>
#include <cuda_bf16.h>
#include <stdint.h>
#include <math.h>

typedef unsigned long long ull;

// ---------------------------------------------------------------------------
// Problem constants
// ---------------------------------------------------------------------------
namespace {
constexpr int TT = 128, BB = 32;
constexpr int POS_E = 64, WORD_E = 512, POS_H = 256, WORD_H = 1024;
constexpr int POS_V = 45, WORD_V = 32000;
constexpr int NTOK = TT * BB;      // 4096
constexpr int NTOKP = NTOK + 32;

// ---------------------------------------------------------------------------
// Device scratch
// ---------------------------------------------------------------------------
__device__ __align__(16) __nv_bfloat16 g_p_emb_h[NTOK * POS_E];
__device__ __align__(16) __nv_bfloat16 g_p_emb_l[NTOK * POS_E];
__device__ __align__(16) __nv_bfloat16 g_w_emb_h[NTOK * WORD_E];
__device__ __align__(16) __nv_bfloat16 g_w_emb_l[NTOK * WORD_E];
__device__ float g_poutsT[POS_H * NTOKP];            // fp32 [H][NTOKP] (pos proj)
__device__ __align__(16) __nv_bfloat16 g_wouts_r_h[NTOK * WORD_H];  // row-major
__device__ __align__(16) __nv_bfloat16 g_wouts_r_l[NTOK * WORD_H];
__device__ __align__(16) __nv_bfloat16 g_wmid_bf[NTOK * WORD_E];
__device__ __align__(16) __nv_bfloat16 g_emb_bf[WORD_V * WORD_E];
__device__ float g_preT_p[4 * POS_H * NTOK];
__device__ float g_preT_w0[4 * WORD_H * NTOK];
// h histories in B-fragment-linear layout: unsigned = hi bf16 pair along k.
constexpr int POS_FR_SLOT = 1 * 16 * 8 * 32;   // 4096
constexpr int W_FR_SLOT = 4 * 16 * 8 * 32;     // 16384
__device__ __align__(16) unsigned g_pofr[(TT + 1) * POS_FR_SLOT];
__device__ __align__(16) unsigned g_w0fr[(TT + 1) * W_FR_SLOT];
__device__ __align__(16) unsigned g_w1fr[(TT + 1) * W_FR_SLOT];
// fragment-linear packed bf16 hi/lo weights (uint32 = 2 bf16 along k)
constexpr int POS_U32_BLK = 5 * 16 * 2 * 32 * 4;     // 20480
constexpr int W0_U32_BLK  = 5 * 16 * 4 * 32 * 4;     // 40960
constexpr int W1_U32_BLK  = 8 * 16 * 4 * 32 * 4;     // 65536
__device__ __align__(16) unsigned g_WposP[128 * POS_U32_BLK];
__device__ __align__(16) unsigned g_Ww0P[128 * W0_U32_BLK];
__device__ __align__(16) unsigned g_Ww1P[128 * W1_U32_BLK];
__device__ float g_bpos[4 * POS_H], g_bw0[4 * WORD_H], g_bw1[4 * WORD_H];
__device__ float g_Cpos[2][POS_H * BB];
__device__ float g_Cw0[2][WORD_H * BB];
__device__ float g_Cw1[2][WORD_H * BB];
__device__ unsigned g_bar_ctr;
// online-softmax partials: 250 head blocks per row (padded 256)
__device__ float g_pmax[NTOK * 256];
__device__ float g_psum[NTOK * 256];
__device__ float g_ls[NTOK];
}  // namespace

// ---------------------------------------------------------------------------
// helpers
// ---------------------------------------------------------------------------
__device__ __forceinline__ float sigm(float x) { return 1.f / (1.f + expf(-x)); }

__device__ __forceinline__ void split_bf(float v, __nv_bfloat16& h, __nv_bfloat16& l) {
    h = __float2bfloat16(v);
    l = __float2bfloat16(v - __bfloat162float(h));
}

__device__ __forceinline__ void mma_bf16(float& c0, float& c1, float& c2, float& c3,
                                         unsigned a0, unsigned a1, unsigned a2, unsigned a3,
                                         unsigned b0, unsigned b1) {
    asm volatile("mma.sync.aligned.m16n8k16.row.col.f32.bf16.bf16.f32 "
                 "{%0,%1,%2,%3}, {%4,%5,%6,%7}, {%8,%9}, {%0,%1,%2,%3};"
                 : "+f"(c0), "+f"(c1), "+f"(c2), "+f"(c3)
                 : "r"(a0), "r"(a1), "r"(a2), "r"(a3), "r"(b0), "r"(b1));
}

// gate-stage h store into fragment layout (d = dim, gb = batch), hi only
__device__ __forceinline__ void store_hfrag(unsigned* base, int d, int gb,
                                            __nv_bfloat16 hi) {
    int c = d >> 8, kloc = d & 255;
    int w = kloc >> 4, koff = kloc & 15;
    int reg = koff >> 3, k8 = koff & 7;
    int tig = k8 >> 1, half = k8 & 1;
    int nt = gb >> 3, gid = gb & 7;
    int lane = gid * 4 + tig;
    int grp = nt * 2 + reg;
    unsigned short* p = (unsigned short*)(base + ((((size_t)c * 16 + w) * 8 + grp) * 32 + lane));
    p[half] = *(unsigned short*)&hi;
}

// ---------------------------------------------------------------------------
// Init / gather / conversions
// ---------------------------------------------------------------------------
__global__ void zero_init_kernel() {
    int i = blockIdx.x * blockDim.x + threadIdx.x;
    if (i < POS_FR_SLOT) g_pofr[i] = 0u;
    if (i < W_FR_SLOT) {
        g_w0fr[i] = 0u;
        g_w1fr[i] = 0u;
    }
    if (i < POS_H * BB) g_Cpos[0][i] = 0.f;
    if (i < WORD_H * BB) {
        g_Cw0[0][i] = 0.f;
        g_Cw1[0][i] = 0.f;
    }
    if (i == 0) g_bar_ctr = 0u;
}

__global__ void gather_kernel(const int* __restrict__ pos, const int* __restrict__ word,
                              const float* __restrict__ posW, const float* __restrict__ wordW) {
    int j = blockIdx.x * blockDim.x + threadIdx.x;
    if (j < NTOK * WORD_E) {
        int tok = j / WORD_E, d = j - tok * WORD_E;
        float v = wordW[(size_t)word[tok] * WORD_E + d];
        __nv_bfloat16 h, l;
        split_bf(v, h, l);
        g_w_emb_h[j] = h;
        g_w_emb_l[j] = l;
    }
    if (j < NTOK * POS_E) {
        int tok = j / POS_E, d = j - tok * POS_E;
        float v = posW[(size_t)pos[tok] * POS_E + d];
        __nv_bfloat16 h, l;
        split_bf(v, h, l);
        g_p_emb_h[j] = h;
        g_p_emb_l[j] = l;
    }
}

__global__ void cvt_emb_kernel(const float* __restrict__ src) {
    size_t i = ((size_t)blockIdx.x * blockDim.x + threadIdx.x) * 4;
    if (i < (size_t)WORD_V * WORD_E) {
        float4 v = *(const float4*)(src + i);
        *(__nv_bfloat162*)&g_emb_bf[i] = __floats2bfloat162_rn(v.x, v.y);
        *(__nv_bfloat162*)&g_emb_bf[i + 2] = __floats2bfloat162_rn(v.z, v.w);
    }
}

// ---------------------------------------------------------------------------
// Repack weights into fragment-linear bf16 hi/lo (+ combined biases) — R13.
// ---------------------------------------------------------------------------
__device__ __forceinline__ unsigned pack_hl(float v0, float v1, int part) {
    __nv_bfloat16 h0 = __float2bfloat16(v0);
    __nv_bfloat16 h1 = __float2bfloat16(v1);
    unsigned short u0, u1;
    if (part == 0) {
        u0 = *(unsigned short*)&h0;
        u1 = *(unsigned short*)&h1;
    } else {
        __nv_bfloat16 l0 = __float2bfloat16(v0 - __bfloat162float(h0));
        __nv_bfloat16 l1 = __float2bfloat16(v1 - __bfloat162float(h1));
        u0 = *(unsigned short*)&l0;
        u1 = *(unsigned short*)&l1;
    }
    return (unsigned)u0 | ((unsigned)u1 << 16);
}

__global__ void repack_bf16_kernel(
    const float* __restrict__ pWih, const float* __restrict__ pWhh,
    const float* __restrict__ w0Wih, const float* __restrict__ w0Whh,
    const float* __restrict__ w1Wih, const float* __restrict__ w1Whh,
    const float* __restrict__ pbih, const float* __restrict__ pbhh,
    const float* __restrict__ w0bih, const float* __restrict__ w0bhh,
    const float* __restrict__ w1bih, const float* __restrict__ w1bhh) {
    long long i = (long long)blockIdx.x * blockDim.x + threadIdx.x;
    const long long P_TOT = 128LL * POS_U32_BLK;
    const long long W0_TOT = 128LL * W0_U32_BLK;
    const long long W1_TOT = 128LL * W1_U32_BLK;
    if (i < P_TOT) {
        int blk = (int)(i / POS_U32_BLK), e = (int)(i % POS_U32_BLK);
        int r = e & 3, lane = (e >> 2) & 31;
        int t1 = e >> 7;
        int part = t1 & 1;
        int t2 = t1 >> 1;
        int w = t2 & 15, c = t2 >> 4;
        int row_l = (lane >> 2) + (r & 1) * 8;
        int k_l = (lane & 3) * 2 + (r >> 1) * 8;
        int kg = c * 256 + w * 16 + k_l;
        float v0 = 0.f, v1 = 0.f;
        if (row_l < 8) {
            int g = row_l >> 1, hh = row_l & 1;
            int R = g * POS_H + blk * 2 + hh;
            v0 = (kg < 1024) ? pWih[(size_t)R * 1088 + 64 + kg] : pWhh[(size_t)R * 256 + kg - 1024];
            v1 = (kg + 1 < 1024) ? pWih[(size_t)R * 1088 + 64 + kg + 1]
                                 : pWhh[(size_t)R * 256 + kg + 1 - 1024];
        }
        g_WposP[i] = pack_hl(v0, v1, part);
        return;
    }
    i -= P_TOT;
    if (i < W0_TOT) {
        int blk = (int)(i / W0_U32_BLK), e = (int)(i % W0_U32_BLK);
        int r = e & 3, lane = (e >> 2) & 31;
        int t1 = e >> 7;
        int f = t1 & 3;
        int t2 = t1 >> 2;
        int w = t2 & 15, c = t2 >> 4;
        int part = f & 1, rt = f >> 1;
        int row_l = rt * 16 + (lane >> 2) + (r & 1) * 8;
        int k_l = (lane & 3) * 2 + (r >> 1) * 8;
        int kg = c * 256 + w * 16 + k_l;
        int g = row_l >> 3, hh = row_l & 7;
        int R = g * WORD_H + blk * 8 + hh;
        float v0 = (kg < 256) ? w0Wih[(size_t)R * 768 + 512 + kg]
                              : w0Whh[(size_t)R * 1024 + kg - 256];
        float v1 = (kg + 1 < 256) ? w0Wih[(size_t)R * 768 + 512 + kg + 1]
                                  : w0Whh[(size_t)R * 1024 + kg + 1 - 256];
        g_Ww0P[i] = pack_hl(v0, v1, part);
        return;
    }
    i -= W0_TOT;
    if (i < W1_TOT) {
        int blk = (int)(i / W1_U32_BLK), e = (int)(i % W1_U32_BLK);
        int r = e & 3, lane = (e >> 2) & 31;
        int t1 = e >> 7;
        int f = t1 & 3;
        int t2 = t1 >> 2;
        int w = t2 & 15, c = t2 >> 4;
        int part = f & 1, rt = f >> 1;
        int row_l = rt * 16 + (lane >> 2) + (r & 1) * 8;
        int k_l = (lane & 3) * 2 + (r >> 1) * 8;
        int kg = c * 256 + w * 16 + k_l;
        int g = row_l >> 3, hh = row_l & 7;
        int R = g * WORD_H + blk * 8 + hh;
        float v0 = (kg < 1024) ? w1Wih[(size_t)R * 1024 + kg]
                               : w1Whh[(size_t)R * 1024 + kg - 1024];
        float v1 = (kg + 1 < 1024) ? w1Wih[(size_t)R * 1024 + kg + 1]
                                   : w1Whh[(size_t)R * 1024 + kg + 1 - 1024];
        g_Ww1P[i] = pack_hl(v0, v1, part);
        return;
    }
    i -= W1_TOT;
    if (i < 4 * POS_H) { g_bpos[i] = pbih[i] + pbhh[i]; return; }
    i -= 4 * POS_H;
    if (i < 4 * WORD_H) { g_bw0[i] = w0bih[i] + w0bhh[i]; return; }
    i -= 4 * WORD_H;
    if (i < 4 * WORD_H) { g_bw1[i] = w1bih[i] + w1bhh[i]; }
}

// ---------------------------------------------------------------------------
// Persistent HMMA recurrence: x hi-only fragments, weights split hi/lo.
// ---------------------------------------------------------------------------
constexpr int REC_THREADS = 512;
constexpr int REDW = 34;
constexpr int REC_SMEM = 16 * 32 * REDW * 4;  // 69632

__device__ __forceinline__ void grid_barrier(unsigned target) {
    __syncthreads();
    if (threadIdx.x == 0) {
        __threadfence();
        atomicAdd(&g_bar_ctr, 1u);
        while (*(volatile unsigned*)&g_bar_ctr < target) __nanosleep(32);
        __threadfence();
    }
    __syncthreads();
}

template <int NC, int NRT, int H, int HPB>
__device__ __forceinline__ void cell_mma(
    float* red,
    const uint4* __restrict__ W4, const float* __restrict__ bcomb,
    const float* __restrict__ preT, int tok0,
    const unsigned* __restrict__ s1, int NCH1, const unsigned* __restrict__ s2,
    const float* __restrict__ cin, float* __restrict__ cout,
    float* __restrict__ hcol32, unsigned* __restrict__ hfrag,
    __nv_bfloat16* __restrict__ hrow_h, __nv_bfloat16* __restrict__ hrow_l) {
    const int tid = threadIdx.x;
    const int w = tid >> 5, lane = tid & 31;
    const int gid = lane >> 2, tig = lane & 3;

    const int hh = tid >> 5, gb = tid & 31;
    const int habs = blockIdx.x * HPB + hh;
    float cin_v = 0.f, bbv[4], prg[4];
    if (tid < HPB * 32) {
        cin_v = cin[habs * 32 + gb];
#pragma unroll
        for (int g = 0; g < 4; g++) {
            bbv[g] = bcomb[g * H + habs];
            prg[g] = preT ? preT[(size_t)(g * H + habs) * NTOK + tok0 + gb] : 0.f;
        }
    }

    float acc[NRT][4][4];
#pragma unroll
    for (int rt = 0; rt < NRT; rt++)
#pragma unroll
        for (int nt = 0; nt < 4; nt++)
#pragma unroll
            for (int q = 0; q < 4; q++) acc[rt][nt][q] = 0.f;

    unsigned xr[2][8];
    uint4 wreg[2][NRT][2];

    auto xload = [&](int c, int buf) {
        const unsigned* s = (c < NCH1)
            ? s1 + ((size_t)(c * 16 + w) * 8) * 32
            : s2 + ((size_t)((c - NCH1) * 16 + w) * 8) * 32;
#pragma unroll
        for (int g = 0; g < 8; g++) xr[buf][g] = s[g * 32 + lane];
    };
    auto wload = [&](int c, int buf) {
#pragma unroll
        for (int rt = 0; rt < NRT; rt++)
#pragma unroll
            for (int p = 0; p < 2; p++)
                wreg[buf][rt][p] =
                    W4[((size_t)(c * 16 + w) * (NRT * 2) + rt * 2 + p) * 32 + lane];
    };

    xload(0, 0);
    wload(0, 0);
    for (int c = 0; c < NC; c++) {
        const int cur = c & 1, nxt = cur ^ 1;
        if (c + 1 < NC) {
            xload(c + 1, nxt);
            wload(c + 1, nxt);
        }
#pragma unroll
        for (int nt = 0; nt < 4; nt++) {
            unsigned bh0 = xr[cur][nt * 2];
            unsigned bh1 = xr[cur][nt * 2 + 1];
#pragma unroll
            for (int rt = 0; rt < NRT; rt++) {
                uint4 Ah = wreg[cur][rt][0];
                uint4 Al = wreg[cur][rt][1];
                mma_bf16(acc[rt][nt][0], acc[rt][nt][1], acc[rt][nt][2], acc[rt][nt][3],
                         Ah.x, Ah.y, Ah.z, Ah.w, bh0, bh1);
                mma_bf16(acc[rt][nt][0], acc[rt][nt][1], acc[rt][nt][2], acc[rt][nt][3],
                         Al.x, Al.y, Al.z, Al.w, bh0, bh1);
            }
        }
    }
#pragma unroll
    for (int rt = 0; rt < NRT; rt++)
#pragma unroll
        for (int nt = 0; nt < 4; nt++) {
            int row = rt * 16 + gid, col = nt * 8 + tig * 2;
            float* rp = red + (size_t)w * 32 * REDW + row * REDW + col;
            *(float2*)rp = make_float2(acc[rt][nt][0], acc[rt][nt][1]);
            *(float2*)(rp + 8 * REDW) = make_float2(acc[rt][nt][2], acc[rt][nt][3]);
        }
    __syncthreads();
    if (tid < HPB * 32) {
        float gs[4];
#pragma unroll
        for (int g = 0; g < 4; g++) {
            float s = bbv[g] + prg[g];
#pragma unroll
            for (int ww = 0; ww < 16; ww++)
                s += red[(size_t)ww * 32 * REDW + (g * HPB + hh) * REDW + gb];
            gs[g] = s;
        }
        float i = sigm(gs[0]), f = sigm(gs[1]), g = tanhf(gs[2]), o = sigm(gs[3]);
        float c2 = f * cin_v + i * g;
        float h2 = o * tanhf(c2);
        cout[habs * 32 + gb] = c2;
        if (hcol32) hcol32[(size_t)habs * NTOKP + gb] = h2;
        __nv_bfloat16 hi, lo;
        split_bf(h2, hi, lo);
        store_hfrag(hfrag, habs, gb, hi);
        if (hrow_h) {
            hrow_h[(size_t)(tok0 + gb) * WORD_H + habs] = hi;
            hrow_l[(size_t)(tok0 + gb) * WORD_H + habs] = lo;
        }
    }
    __syncthreads();
}

__global__ __launch_bounds__(REC_THREADS, 1) void recurrence_kernel() {
    extern __shared__ float red[];
    unsigned ep = 0;
    const unsigned NB = gridDim.x;
    const int blk = blockIdx.x;
    const uint4* WposP = (const uint4*)g_WposP + (size_t)blk * (POS_U32_BLK / 4);
    const uint4* Ww0P = (const uint4*)g_Ww0P + (size_t)blk * (W0_U32_BLK / 4);
    const uint4* Ww1P = (const uint4*)g_Ww1P + (size_t)blk * (W1_U32_BLK / 4);
    for (int t = 0; t < TT; t++) {
        const int p = t & 1, q = p ^ 1;
        const int tok0 = t * BB;
        cell_mma<5, 1, POS_H, 2>(
            red, WposP, g_bpos, g_preT_p, tok0,
            g_w1fr + (size_t)t * W_FR_SLOT, 4, g_pofr + (size_t)t * POS_FR_SLOT,
            g_Cpos[p], g_Cpos[q],
            g_poutsT + (size_t)(t + 1) * 32,
            g_pofr + (size_t)(t + 1) * POS_FR_SLOT, nullptr, nullptr);
        grid_barrier(++ep * NB);
        cell_mma<5, 2, WORD_H, 8>(
            red, Ww0P, g_bw0, g_preT_w0, tok0,
            g_pofr + (size_t)(t + 1) * POS_FR_SLOT, 1, g_w0fr + (size_t)t * W_FR_SLOT,
            g_Cw0[p], g_Cw0[q],
            nullptr,
            g_w0fr + (size_t)(t + 1) * W_FR_SLOT, nullptr, nullptr);
        grid_barrier(++ep * NB);
        cell_mma<8, 2, WORD_H, 8>(
            red, Ww1P, g_bw1, nullptr, tok0,
            g_w0fr + (size_t)(t + 1) * W_FR_SLOT, 4, g_w1fr + (size_t)t * W_FR_SLOT,
            g_Cw1[p], g_Cw1[q],
            nullptr,
            g_w1fr + (size_t)(t + 1) * W_FR_SLOT, g_wouts_r_h, g_wouts_r_l);
        grid_barrier(++ep * NB);
    }
}

// ---------------------------------------------------------------------------
// Generic split-bf16 HMMA GEMM (R15, proven)
// ---------------------------------------------------------------------------
constexpr int MG_SMEM = 8 * 128 * 40 * 2;  // 81920

__global__ __launch_bounds__(256, 1) void mma_gemm_kernel(
    const __nv_bfloat16* __restrict__ Ah, const __nv_bfloat16* __restrict__ Al, int lda,
    const float* __restrict__ W, int ldw, const float* __restrict__ bias,
    float* __restrict__ CT, int ldct,
    __nv_bfloat16* __restrict__ Cbf, int ldc, int K) {
    extern __shared__ __nv_bfloat16 smb[];
    __nv_bfloat16* AH = smb;
    __nv_bfloat16* AL = smb + 2 * 128 * 40;
    __nv_bfloat16* BH = smb + 4 * 128 * 40;
    __nv_bfloat16* BL = smb + 6 * 128 * 40;
    const int tid = threadIdx.x;
    const int wid = tid >> 5, lane = tid & 31;
    const int wm = wid & 3, wn = wid >> 2;
    const int rBase = blockIdx.y * 128, cBase = blockIdx.x * 128;
    const int gid = lane >> 2, tig = lane & 3;
    const int NCHUNK = K / 32;

    float acc[2][8][4];
#pragma unroll
    for (int mt = 0; mt < 2; mt++)
#pragma unroll
        for (int nt = 0; nt < 8; nt++)
#pragma unroll
            for (int q = 0; q < 4; q++) acc[mt][nt][q] = 0.f;

    uint4 pah[2], pal[2];
    float4 pw[4];

    auto load_regs = [&](int kb) {
#pragma unroll
        for (int it = 0; it < 2; it++) {
            int flat = tid + it * 256;
            int row = flat >> 2, sg = flat & 3;
            pah[it] = *(const uint4*)(Ah + (size_t)(rBase + row) * lda + kb + sg * 8);
            pal[it] = *(const uint4*)(Al + (size_t)(rBase + row) * lda + kb + sg * 8);
        }
#pragma unroll
        for (int it = 0; it < 4; it++) {
            int flat = tid + it * 256;
            int row = flat >> 3, k4 = flat & 7;
            pw[it] = *(const float4*)(W + (size_t)(cBase + row) * ldw + kb + k4 * 4);
        }
    };
    auto store_smem = [&](int buf) {
#pragma unroll
        for (int it = 0; it < 2; it++) {
            int flat = tid + it * 256;
            int row = flat >> 2, sg = flat & 3;
            *(uint4*)&AH[(buf * 128 + row) * 40 + sg * 8] = pah[it];
            *(uint4*)&AL[(buf * 128 + row) * 40 + sg * 8] = pal[it];
        }
#pragma unroll
        for (int it = 0; it < 4; it++) {
            int flat = tid + it * 256;
            int row = flat >> 3, k4 = flat & 7;
            __nv_bfloat16 h0, h1, h2, h3, l0, l1, l2, l3;
            split_bf(pw[it].x, h0, l0);
            split_bf(pw[it].y, h1, l1);
            split_bf(pw[it].z, h2, l2);
            split_bf(pw[it].w, h3, l3);
            __nv_bfloat16* bh = &BH[(buf * 128 + row) * 40 + k4 * 4];
            __nv_bfloat16* bl = &BL[(buf * 128 + row) * 40 + k4 * 4];
            bh[0] = h0; bh[1] = h1; bh[2] = h2; bh[3] = h3;
            bl[0] = l0; bl[1] = l1; bl[2] = l2; bl[3] = l3;
        }
    };

    load_regs(0);
    store_smem(0);
    __syncthreads();

    for (int c = 0; c < NCHUNK; c++) {
        const int cur = c & 1, nxt = cur ^ 1;
        if (c + 1 < NCHUNK) load_regs((c + 1) * 32);
#pragma unroll
        for (int ks = 0; ks < 32; ks += 16) {
            const int k0 = ks + tig * 2;
            unsigned bh[8][2], bl[8][2];
#pragma unroll
            for (int nt = 0; nt < 8; nt++) {
                int n0 = wn * 64 + nt * 8 + gid;
                bh[nt][0] = *(const unsigned*)&BH[(cur * 128 + n0) * 40 + k0];
                bh[nt][1] = *(const unsigned*)&BH[(cur * 128 + n0) * 40 + k0 + 8];
                bl[nt][0] = *(const unsigned*)&BL[(cur * 128 + n0) * 40 + k0];
                bl[nt][1] = *(const unsigned*)&BL[(cur * 128 + n0) * 40 + k0 + 8];
            }
#pragma unroll
            for (int mt = 0; mt < 2; mt++) {
                int r0 = wm * 32 + mt * 16 + gid;
                unsigned a0 = *(const unsigned*)&AH[(cur * 128 + r0) * 40 + k0];
                unsigned a1 = *(const unsigned*)&AH[(cur * 128 + r0 + 8) * 40 + k0];
                unsigned a2 = *(const unsigned*)&AH[(cur * 128 + r0) * 40 + k0 + 8];
                unsigned a3 = *(const unsigned*)&AH[(cur * 128 + r0 + 8) * 40 + k0 + 8];
                unsigned c0 = *(const unsigned*)&AL[(cur * 128 + r0) * 40 + k0];
                unsigned c1 = *(const unsigned*)&AL[(cur * 128 + r0 + 8) * 40 + k0];
                unsigned c2 = *(const unsigned*)&AL[(cur * 128 + r0) * 40 + k0 + 8];
                unsigned c3 = *(const unsigned*)&AL[(cur * 128 + r0 + 8) * 40 + k0 + 8];
#pragma unroll
                for (int nt = 0; nt < 8; nt++) {
                    mma_bf16(acc[mt][nt][0], acc[mt][nt][1], acc[mt][nt][2], acc[mt][nt][3],
                             a0, a1, a2, a3, bh[nt][0], bh[nt][1]);
                    mma_bf16(acc[mt][nt][0], acc[mt][nt][1], acc[mt][nt][2], acc[mt][nt][3],
                             a0, a1, a2, a3, bl[nt][0], bl[nt][1]);
                    mma_bf16(acc[mt][nt][0], acc[mt][nt][1], acc[mt][nt][2], acc[mt][nt][3],
                             c0, c1, c2, c3, bh[nt][0], bh[nt][1]);
                }
            }
        }
        if (c + 1 < NCHUNK) store_smem(nxt);
        __syncthreads();
    }

    if (CT) {
#pragma unroll
        for (int nt = 0; nt < 8; nt++) {
            int col = cBase + wn * 64 + nt * 8 + tig * 2;
#pragma unroll
            for (int mt = 0; mt < 2; mt++) {
                int row = rBase + wm * 32 + mt * 16 + gid;
                CT[(size_t)col * ldct + row] = acc[mt][nt][0];
                CT[(size_t)(col + 1) * ldct + row] = acc[mt][nt][1];
                CT[(size_t)col * ldct + row + 8] = acc[mt][nt][2];
                CT[(size_t)(col + 1) * ldct + row + 8] = acc[mt][nt][3];
            }
        }
    }
    if (Cbf) {
#pragma unroll
        for (int nt = 0; nt < 8; nt++) {
            int col = cBase + wn * 64 + nt * 8 + tig * 2;
            float bx = bias ? bias[col] : 0.f;
            float by = bias ? bias[col + 1] : 0.f;
#pragma unroll
            for (int mt = 0; mt < 2; mt++) {
                int row = rBase + wm * 32 + mt * 16 + gid;
                *(__nv_bfloat162*)&Cbf[(size_t)row * ldc + col] =
                    __floats2bfloat162_rn(acc[mt][nt][0] + bx, acc[mt][nt][1] + by);
                *(__nv_bfloat162*)&Cbf[(size_t)(row + 8) * ldc + col] =
                    __floats2bfloat162_rn(acc[mt][nt][2] + bx, acc[mt][nt][3] + by);
            }
        }
    }
}

// ---------------------------------------------------------------------------
// Warp-MMA bf16 head GEMM with fused online-softmax partials.
// ---------------------------------------------------------------------------
__global__ __launch_bounds__(256, 1) void head_mma_kernel(
    const float* __restrict__ wp2b, float* __restrict__ outp) {
    __shared__ __nv_bfloat16 As[2][128][40];
    __shared__ __nv_bfloat16 Bs[2][128][40];
    __shared__ float2 sm_ms[128][2];
    const int tid = threadIdx.x;
    const int wid = tid >> 5, lane = tid & 31;
    const int wm = wid & 3;
    const int wn = wid >> 2;
    const int rBase = blockIdx.y * 128, cBase = blockIdx.x * 128;
    const int gid = lane >> 2, tig = lane & 3;

    float acc[2][8][4];
#pragma unroll
    for (int mt = 0; mt < 2; mt++)
#pragma unroll
        for (int nt = 0; nt < 8; nt++)
#pragma unroll
            for (int q = 0; q < 4; q++) acc[mt][nt][q] = 0.f;

    const int sr0 = tid >> 2, sg = tid & 3;

    uint4 pa[2], pb[2];
#pragma unroll
    for (int it = 0; it < 2; it++) {
        int r = sr0 + it * 64;
        pa[it] = *(const uint4*)(g_wmid_bf + (size_t)(rBase + r) * WORD_E + sg * 8);
        pb[it] = *(const uint4*)(g_emb_bf + (size_t)(cBase + r) * WORD_E + sg * 8);
    }
#pragma unroll
    for (int it = 0; it < 2; it++) {
        int r = sr0 + it * 64;
        *(uint4*)&As[0][r][sg * 8] = pa[it];
        *(uint4*)&Bs[0][r][sg * 8] = pb[it];
    }
    __syncthreads();

    const int NCHUNK = WORD_E / 32;
    for (int c = 0; c < NCHUNK; c++) {
        const int cur = c & 1, nxt = cur ^ 1;
        if (c + 1 < NCHUNK) {
            int kb = (c + 1) * 32;
#pragma unroll
            for (int it = 0; it < 2; it++) {
                int r = sr0 + it * 64;
                pa[it] = *(const uint4*)(g_wmid_bf + (size_t)(rBase + r) * WORD_E + kb + sg * 8);
                pb[it] = *(const uint4*)(g_emb_bf + (size_t)(cBase + r) * WORD_E + kb + sg * 8);
            }
        }
#pragma unroll
        for (int ks = 0; ks < 32; ks += 16) {
            const int k0 = ks + tig * 2;
            unsigned b[8][2];
#pragma unroll
            for (int nt = 0; nt < 8; nt++) {
                int n0 = wn * 64 + nt * 8 + gid;
                b[nt][0] = *(const unsigned*)&Bs[cur][n0][k0];
                b[nt][1] = *(const unsigned*)&Bs[cur][n0][k0 + 8];
            }
#pragma unroll
            for (int mt = 0; mt < 2; mt++) {
                int r0 = wm * 32 + mt * 16 + gid;
                unsigned a0 = *(const unsigned*)&As[cur][r0][k0];
                unsigned a1 = *(const unsigned*)&As[cur][r0 + 8][k0];
                unsigned a2 = *(const unsigned*)&As[cur][r0][k0 + 8];
                unsigned a3 = *(const unsigned*)&As[cur][r0 + 8][k0 + 8];
#pragma unroll
                for (int nt = 0; nt < 8; nt++)
                    mma_bf16(acc[mt][nt][0], acc[mt][nt][1], acc[mt][nt][2], acc[mt][nt][3],
                             a0, a1, a2, a3, b[nt][0], b[nt][1]);
            }
        }
        if (c + 1 < NCHUNK) {
#pragma unroll
            for (int it = 0; it < 2; it++) {
                int r = sr0 + it * 64;
                *(uint4*)&As[nxt][r][sg * 8] = pa[it];
                *(uint4*)&Bs[nxt][r][sg * 8] = pb[it];
            }
        }
        __syncthreads();
    }

    // epilogue: bias + store logits; track per-row (max, sumexp) partials.
    float rm[4] = {-1e30f, -1e30f, -1e30f, -1e30f};   // idx = mt*2 + half
#pragma unroll
    for (int nt = 0; nt < 8; nt++) {
        int col = cBase + wn * 64 + nt * 8 + tig * 2;
        float2 bv = *(const float2*)(wp2b + col);
#pragma unroll
        for (int mt = 0; mt < 2; mt++) {
            int row = rBase + wm * 32 + mt * 16 + gid;
            float v0 = acc[mt][nt][0] + bv.x, v1 = acc[mt][nt][1] + bv.y;
            float v2 = acc[mt][nt][2] + bv.x, v3 = acc[mt][nt][3] + bv.y;
            *(float2*)(outp + (size_t)row * WORD_V + col) = make_float2(v0, v1);
            *(float2*)(outp + (size_t)(row + 8) * WORD_V + col) = make_float2(v2, v3);
            rm[mt * 2] = fmaxf(rm[mt * 2], fmaxf(v0, v1));
            rm[mt * 2 + 1] = fmaxf(rm[mt * 2 + 1], fmaxf(v2, v3));
        }
    }
    float rs[4] = {0.f, 0.f, 0.f, 0.f};
#pragma unroll
    for (int nt = 0; nt < 8; nt++) {
        int col = cBase + wn * 64 + nt * 8 + tig * 2;
        float2 bv = *(const float2*)(wp2b + col);
#pragma unroll
        for (int mt = 0; mt < 2; mt++) {
            rs[mt * 2] += expf(acc[mt][nt][0] + bv.x - rm[mt * 2]) +
                          expf(acc[mt][nt][1] + bv.y - rm[mt * 2]);
            rs[mt * 2 + 1] += expf(acc[mt][nt][2] + bv.x - rm[mt * 2 + 1]) +
                              expf(acc[mt][nt][3] + bv.y - rm[mt * 2 + 1]);
        }
    }
    // reduce over tig (4-lane groups, same row set)
#pragma unroll
    for (int off = 1; off <= 2; off <<= 1) {
#pragma unroll
        for (int i = 0; i < 4; i++) {
            float om = __shfl_xor_sync(0xffffffffu, rm[i], off);
            float os = __shfl_xor_sync(0xffffffffu, rs[i], off);
            float M = fmaxf(rm[i], om);
            rs[i] = rs[i] * expf(rm[i] - M) + os * expf(om - M);
            rm[i] = M;
        }
    }
    if (tig == 0) {
#pragma unroll
        for (int i = 0; i < 4; i++) {
            int rowl = wm * 32 + (i >> 1) * 16 + (i & 1) * 8 + gid;
            sm_ms[rowl][wn] = make_float2(rm[i], rs[i]);
        }
    }
    __syncthreads();
    if (tid < 128) {
        float2 a = sm_ms[tid][0], b2 = sm_ms[tid][1];
        float M = fmaxf(a.x, b2.x);
        float S = a.y * expf(a.x - M) + b2.y * expf(b2.x - M);
        g_pmax[(size_t)(rBase + tid) * 256 + blockIdx.x] = M;
        g_psum[(size_t)(rBase + tid) * 256 + blockIdx.x] = S;
    }
}

// combine 250 partials per row -> logsumexp
__global__ void reduce_ls_kernel() {
    __shared__ float sred[8];
    const int row = blockIdx.x;
    const int tid = threadIdx.x;  // 256
    float m = -1e30f;
    for (int i = tid; i < 250; i += 256) m = fmaxf(m, g_pmax[(size_t)row * 256 + i]);
#pragma unroll
    for (int o = 16; o; o >>= 1) m = fmaxf(m, __shfl_xor_sync(0xffffffffu, m, o));
    if ((tid & 31) == 0) sred[tid >> 5] = m;
    __syncthreads();
    float M = sred[0];
#pragma unroll
    for (int w = 1; w < 8; w++) M = fmaxf(M, sred[w]);
    __syncthreads();
    float s = 0.f;
    for (int i = tid; i < 250; i += 256)
        s += g_psum[(size_t)row * 256 + i] * expf(g_pmax[(size_t)row * 256 + i] - M);
#pragma unroll
    for (int o = 16; o; o >>= 1) s += __shfl_xor_sync(0xffffffffu, s, o);
    if ((tid & 31) == 0) sred[tid >> 5] = s;
    __syncthreads();
    if (tid == 0) {
        float S = 0.f;
#pragma unroll
        for (int w = 0; w < 8; w++) S += sred[w];
        g_ls[row] = M + logf(S);
    }
}

__global__ void normalize_kernel(float* __restrict__ logits) {
    const int row = blockIdx.x;
    const float ls = g_ls[row];
    float4* p4 = (float4*)(logits + (size_t)row * WORD_V);
    for (int i = threadIdx.x; i < WORD_V / 4; i += 256) {
        float4 v = p4[i];
        v.x -= ls; v.y -= ls; v.z -= ls; v.w -= ls;
        p4[i] = v;
    }
}

// ---------------------------------------------------------------------------
// pos projection + log-softmax (one block per timestep)
// ---------------------------------------------------------------------------
__global__ void pos_projT_kernel(const float* __restrict__ Wp, const float* __restrict__ bp,
                                 float* __restrict__ out) {
    __shared__ float xs[POS_H][32];
    __shared__ float lg[POS_V][33];
    __shared__ float lsb[32];
    const int t = blockIdx.x;
    const int tok0 = t * 32;
    const int tid = threadIdx.x;
    const int b = tid & 31, vg = tid >> 5;
    for (int i = tid; i < POS_H * 32; i += 256) {
        int k = i >> 5, bb = i & 31;
        xs[k][bb] = g_poutsT[(size_t)k * NTOKP + 32 + tok0 + bb];
    }
    __syncthreads();
    for (int v = vg; v < POS_V; v += 8) {
        float s = bp[v];
        const float* wv = Wp + (size_t)v * POS_H;
        for (int k = 0; k < POS_H; k++) s = fmaf(xs[k][b], wv[k], s);
        lg[v][b] = s;
    }
    __syncthreads();
    if (tid < 32) {
        float m = -INFINITY;
        for (int v = 0; v < POS_V; v++) m = fmaxf(m, lg[v][tid]);
        float e = 0.f;
        for (int v = 0; v < POS_V; v++) e += expf(lg[v][tid] - m);
        lsb[tid] = m + logf(e);
    }
    __syncthreads();
    float ls = lsb[b];
    for (int v = vg; v < POS_V; v += 8)
        out[(size_t)(tok0 + b) * POS_V + v] = lg[v][b] - ls;
}

// ---------------------------------------------------------------------------
// Host side
// ---------------------------------------------------------------------------
extern "C" void kernel_launch(void* const* d_in, const int* in_sizes, int n_in,
                              void* d_out, int out_size) {
    (void)in_sizes; (void)n_in; (void)out_size;
    const int*   pos        = (const int*)d_in[0];
    const int*   word       = (const int*)d_in[1];
    const float* pos_emb_W  = (const float*)d_in[2];
    const float* word_emb_W = (const float*)d_in[3];
    const float* pos_Wih    = (const float*)d_in[4];
    const float* pos_Whh    = (const float*)d_in[5];
    const float* pos_bih    = (const float*)d_in[6];
    const float* pos_bhh    = (const float*)d_in[7];
    const float* w0_Wih     = (const float*)d_in[8];
    const float* w0_Whh     = (const float*)d_in[9];
    const float* w0_bih     = (const float*)d_in[10];
    const float* w0_bhh     = (const float*)d_in[11];
    const float* w1_Wih     = (const float*)d_in[12];
    const float* w1_Whh     = (const float*)d_in[13];
    const float* w1_bih     = (const float*)d_in[14];
    const float* w1_bhh     = (const float*)d_in[15];
    const float* pos_proj_W = (const float*)d_in[16];
    const float* pos_proj_b = (const float*)d_in[17];
    const float* wp1_W      = (const float*)d_in[18];
    const float* wp1_b      = (const float*)d_in[19];
    const float* wp2_b      = (const float*)d_in[20];
    float* out = (float*)d_out;

    float *preT_p, *preT_w0;
    __nv_bfloat16 *p_emb_h, *p_emb_l, *w_emb_h, *w_emb_l, *wouts_r_h, *wouts_r_l, *wmid_bf;
    cudaGetSymbolAddress((void**)&preT_p, g_preT_p);
    cudaGetSymbolAddress((void**)&preT_w0, g_preT_w0);
    cudaGetSymbolAddress((void**)&p_emb_h, g_p_emb_h);
    cudaGetSymbolAddress((void**)&p_emb_l, g_p_emb_l);
    cudaGetSymbolAddress((void**)&w_emb_h, g_w_emb_h);
    cudaGetSymbolAddress((void**)&w_emb_l, g_w_emb_l);
    cudaGetSymbolAddress((void**)&wouts_r_h, g_wouts_r_h);
    cudaGetSymbolAddress((void**)&wouts_r_l, g_wouts_r_l);
    cudaGetSymbolAddress((void**)&wmid_bf, g_wmid_bf);

    static bool attr_done = false;
    if (!attr_done) {
        cudaFuncSetAttribute(recurrence_kernel,
                             cudaFuncAttributeMaxDynamicSharedMemorySize, REC_SMEM);
        cudaFuncSetAttribute(mma_gemm_kernel,
                             cudaFuncAttributeMaxDynamicSharedMemorySize, MG_SMEM);
        attr_done = true;
    }

    zero_init_kernel<<<(32 * WORD_H + 255) / 256, 256>>>();
    gather_kernel<<<(NTOK * WORD_E + 255) / 256, 256>>>(pos, word, pos_emb_W, word_emb_W);
    cvt_emb_kernel<<<(WORD_V * WORD_E / 4 + 255) / 256, 256>>>(word_emb_W);

    {
        const long long total = 128LL * POS_U32_BLK + 128LL * W0_U32_BLK +
                                128LL * W1_U32_BLK + 4 * POS_H + 2 * (4 * WORD_H);
        repack_bf16_kernel<<<(unsigned)((total + 255) / 256), 256>>>(
            pos_Wih, pos_Whh, w0_Wih, w0_Whh, w1_Wih, w1_Whh,
            pos_bih, pos_bhh, w0_bih, w0_bhh, w1_bih, w1_bhh);
    }

    // precompute emb @ Wih_emb-part for all timesteps (HMMA, CT outputs)
    mma_gemm_kernel<<<dim3(4 * POS_H / 128, NTOK / 128), 256, MG_SMEM>>>(
        p_emb_h, p_emb_l, POS_E, pos_Wih, POS_E + WORD_H, nullptr,
        preT_p, NTOK, nullptr, 0, POS_E);
    mma_gemm_kernel<<<dim3(4 * WORD_H / 128, NTOK / 128), 256, MG_SMEM>>>(
        w_emb_h, w_emb_l, WORD_E, w0_Wih, WORD_E + POS_H, nullptr,
        preT_w0, NTOK, nullptr, 0, WORD_E);

    // the whole 128-step recurrence: persistent HMMA kernel (frag-direct x)
    recurrence_kernel<<<128, REC_THREADS, REC_SMEM>>>();

    // pos projection + log-softmax
    pos_projT_kernel<<<TT, 256>>>(pos_proj_W, pos_proj_b, out);

    // word head: wp1 (HMMA split-bf16 -> wmid_bf) -> big head GEMM
    mma_gemm_kernel<<<dim3(WORD_E / 128, NTOK / 128), 256, MG_SMEM>>>(
        wouts_r_h, wouts_r_l, WORD_H, wp1_W, WORD_H, wp1_b,
        nullptr, 0, wmid_bf, WORD_E, WORD_H);

    float* wlp = out + (size_t)NTOK * POS_V;
    head_mma_kernel<<<dim3(WORD_V / 128, NTOK / 128), 256>>>(wp2_b, wlp);
    reduce_ls_kernel<<<NTOK, 256>>>();
    normalize_kernel<<<NTOK, 256>>>(wlp);
}